// round 8
// baseline (speedup 1.0000x reference)
#include <cuda_runtime.h>
#include <math.h>

#define FEAT 128
#define HID  64
#define NMAX 50048
#define EMAX 1048576

// ---------------- scratch (static __device__, zero-initialized at load) ----------------
__device__ float g_h[NMAX * FEAT];      // post-GEMM features h
__device__ float g_y[NMAX * HID];       // post-epilogue features
__device__ float g_agg[NMAX * FEAT];    // edge-aggregated output (invariant: zero at entry)
__device__ float g_as[NMAX];            // alpha_src per node
__device__ float g_ad[NMAX];            // alpha_dst per node
__device__ float g_s[NMAX];             // segment sum
__device__ float g_e[EMAX];             // per-edge exp(e)
__device__ int2  g_sd[EMAX];            // packed (src, dst)
__device__ float g_colsum[4 * FEAT];    // per-layer BN stat slots
__device__ float g_colsq[4 * FEAT];
__device__ int   g_is64;

// ---------------- startup: zero BN stat slots + detect index dtype ----------------
__global__ void start_kernel(const void* ei) {
    int t = threadIdx.x;
    if (t < 4 * FEAT) { g_colsum[t] = 0.f; g_colsq[t] = 0.f; }
    if (t < 32) {
        const long long* p = (const long long*)ei;
        int bad = 0;
        for (int i = t; i < 64; i += 32) {
            long long v = p[i];
            if (v < 0 || v >= (1LL << 31)) bad = 1;
        }
        bad = __any_sync(0xffffffffu, bad);
        if (t == 0) g_is64 = bad ? 0 : 1;
    }
}

__global__ void convert_kernel(const void* ei, int E, int ET) {
    int i = blockIdx.x * blockDim.x + threadIdx.x;
    if (i >= ET) return;
    if (i < E) {
        if (g_is64) {
            const long long* p = (const long long*)ei;
            g_sd[i] = make_int2((int)p[i], (int)p[E + i]);
        } else {
            const int* p = (const int*)ei;
            g_sd[i] = make_int2(p[i], p[E + i]);
        }
    } else {
        g_sd[i] = make_int2(i - E, i - E);
    }
}

// ---------------- GEMM: h = affine(x) @ W^T ----------------
// Round-4 structure (4x8 thread tile, M=8192/OUT, KC=32), NATURAL register count
// (no launch_bounds — capping causes K-loop spills, rounds 6/7 regressions).
// Fused: BN-finalize prologue, alpha_s/alpha_d epilogue, g_s zeroing.
template <int IN, int OUT>
__global__ void gemm_kernel(const float* __restrict__ x, const float* __restrict__ W,
                            const float* __restrict__ gamma, const float* __restrict__ beta,
                            const float* __restrict__ colsum, const float* __restrict__ colsq,
                            float invn, int useAffine,
                            const float* __restrict__ avs, const float* __restrict__ avd,
                            float* __restrict__ h, int n) {
    const int M = 8192 / OUT;          // 128 (OUT=64) or 64 (OUT=128)
    const int OC = OUT / 8;            // col groups: 8 or 16
    const int KC = 32;
    const int SXS = M + 4;
    const int SWS = OUT + 4;

    __shared__ __align__(16) float sSc[IN];
    __shared__ __align__(16) float sSh[IN];
    __shared__ __align__(16) float sX[KC * SXS];
    __shared__ __align__(16) float sW[KC * SWS];

    int tid = threadIdx.x;
    int og = tid % OC;
    int rg = tid / OC;
    int r0 = blockIdx.x * M;

    if (useAffine) {
        for (int o = tid; o < IN; o += 256) {
            float mu = colsum[o] * invn;
            float var = colsq[o] * invn - mu * mu;
            float sc = gamma[o] * rsqrtf(var + 1e-5f);
            sSc[o] = sc;
            sSh[o] = beta[o] - mu * sc;
        }
        __syncthreads();
    }

    float acc[4][8];
#pragma unroll
    for (int i = 0; i < 4; i++)
#pragma unroll
        for (int j = 0; j < 8; j++) acc[i][j] = 0.f;

    for (int kc = 0; kc < IN; kc += KC) {
        // x tile [M x KC] -> sX[k][r] (transposed), optional affine
        for (int idx = tid; idx < M * (KC / 4); idx += 256) {
            int r = idx >> 3, q = idx & 7;
            int k = q * 4;
            int row = r0 + r;
            float4 v = (row < n) ? *(const float4*)&x[row * IN + kc + k]
                                 : make_float4(0.f, 0.f, 0.f, 0.f);
            if (useAffine) {
                v.x = v.x * sSc[kc + k] + sSh[kc + k];
                v.y = v.y * sSc[kc + k + 1] + sSh[kc + k + 1];
                v.z = v.z * sSc[kc + k + 2] + sSh[kc + k + 2];
                v.w = v.w * sSc[kc + k + 3] + sSh[kc + k + 3];
            }
            sX[(k + 0) * SXS + r] = v.x;
            sX[(k + 1) * SXS + r] = v.y;
            sX[(k + 2) * SXS + r] = v.z;
            sX[(k + 3) * SXS + r] = v.w;
        }
        // W tile [OUT x KC] -> sW[k][o] (transposed)
        for (int idx = tid; idx < OUT * (KC / 4); idx += 256) {
            int o = idx >> 3, q = idx & 7;
            int k = q * 4;
            float4 w = *(const float4*)&W[o * IN + kc + k];
            sW[(k + 0) * SWS + o] = w.x;
            sW[(k + 1) * SWS + o] = w.y;
            sW[(k + 2) * SWS + o] = w.z;
            sW[(k + 3) * SWS + o] = w.w;
        }
        __syncthreads();

#pragma unroll
        for (int k = 0; k < KC; k++) {
            float4 a  = *(const float4*)&sX[k * SXS + rg * 4];
            float4 b0 = *(const float4*)&sW[k * SWS + og * 8];
            float4 b1 = *(const float4*)&sW[k * SWS + og * 8 + 4];
            float av[4] = {a.x, a.y, a.z, a.w};
            float bv[8] = {b0.x, b0.y, b0.z, b0.w, b1.x, b1.y, b1.z, b1.w};
#pragma unroll
            for (int i = 0; i < 4; i++)
#pragma unroll
                for (int j = 0; j < 8; j++)
                    acc[i][j] += av[i] * bv[j];
        }
        __syncthreads();
    }

    float avsr[8], avdr[8];
#pragma unroll
    for (int j = 0; j < 8; j++) {
        avsr[j] = __ldg(&avs[og * 8 + j]);
        avdr[j] = __ldg(&avd[og * 8 + j]);
    }

    float* sP = sX;                    // overlay: [M * OC] = 1024 floats
    float* sQ = sX + M * OC;
#pragma unroll
    for (int i = 0; i < 4; i++) {
        int rl = rg * 4 + i;
        int row = r0 + rl;
        float ps = 0.f, pd = 0.f;
#pragma unroll
        for (int j = 0; j < 8; j++) {
            ps += acc[i][j] * avsr[j];
            pd += acc[i][j] * avdr[j];
        }
        sP[rl * OC + og] = ps;
        sQ[rl * OC + og] = pd;
        if (row < n) {
            float4 v0 = make_float4(acc[i][0], acc[i][1], acc[i][2], acc[i][3]);
            float4 v1 = make_float4(acc[i][4], acc[i][5], acc[i][6], acc[i][7]);
            *(float4*)&h[row * OUT + og * 8] = v0;
            *(float4*)&h[row * OUT + og * 8 + 4] = v1;
        }
    }
    __syncthreads();
    if (tid < M) {
        int row = r0 + tid;
        if (row < n) {
            float as = 0.f, ad = 0.f;
#pragma unroll
            for (int t = 0; t < OC; t++) {
                as += sP[tid * OC + t];
                ad += sQ[tid * OC + t];
            }
            g_as[row] = as;
            g_ad[row] = ad;
            g_s[row] = 0.f;
        }
    }
}

// ---------------- fused edge pass: t = exp(leaky_relu(as+ad)); segment sum ----------------
__global__ void edge12_kernel(int ET) {
    int i = blockIdx.x * blockDim.x + threadIdx.x;
    if (i >= ET) return;
    int2 sd = g_sd[i];
    float e = g_as[sd.x] + g_ad[sd.y];
    e = (e >= 0.f) ? e : 0.2f * e;
    float t = __expf(e);
    g_e[i] = t;
    atomicAdd(&g_s[sd.y], t);
}

// ---------------- edge pass 3: agg[dst] += alpha * h[src]  (vector red) ----------------
template <int OUT>
__global__ void edge3_kernel(const float* __restrict__ h, int ET) {
    const int G = OUT / 4;
    int gtid = blockIdx.x * blockDim.x + threadIdx.x;
    int i = gtid / G;
    int j = gtid % G;
    if (i >= ET) return;
    int2 sd = g_sd[i];
    float alpha = __fdividef(g_e[i], g_s[sd.y] + 1e-16f);
    const float4 hv = *(const float4*)&h[sd.x * OUT + j * 4];
    float vx = alpha * hv.x, vy = alpha * hv.y, vz = alpha * hv.z, vw = alpha * hv.w;
    float* p = &g_agg[sd.y * OUT + j * 4];
    asm volatile("red.global.add.v4.f32 [%0], {%1, %2, %3, %4};"
                 :: "l"(p), "f"(vx), "f"(vy), "f"(vz), "f"(vw) : "memory");
}

// ---------------- epilogue: y = relu(agg + b), BN stats, re-zero agg ----------------
template <int OUT>
__global__ void epi_bn_kernel(const float* __restrict__ b, float* __restrict__ y,
                              float* __restrict__ colsum, float* __restrict__ colsq, int n) {
    const int T = 256;
    const int RT = T / OUT;
    const int RPB = 64;
    int o = threadIdx.x % OUT;
    int rsub = threadIdx.x / OUT;
    int r0 = blockIdx.x * RPB;
    float bo = b[o];
    float sum = 0.f, sq = 0.f;
    for (int r = rsub; r < RPB; r += RT) {
        int row = r0 + r;
        if (row >= n) break;
        float v = g_agg[row * OUT + o] + bo;
        g_agg[row * OUT + o] = 0.f;                 // restore zero invariant (line is L2-hot)
        v = (v > 0.f) ? v : 0.f;
        y[row * OUT + o] = v;
        sum += v; sq += v * v;
    }
    __shared__ float ssum[T], ssq[T];
    ssum[threadIdx.x] = sum; ssq[threadIdx.x] = sq;
    __syncthreads();
    if (rsub == 0) {
#pragma unroll
        for (int t = 1; t < RT; t++) { sum += ssum[t * OUT + o]; sq += ssq[t * OUT + o]; }
        atomicAdd(&colsum[o], sum);
        atomicAdd(&colsq[o], sq);
    }
}

// ---------------- final: x_hat = relu(agg + b4); out = [|x-x_hat|, x_hat]; re-zero agg ----
__global__ void final_kernel(const float* __restrict__ x, const float* __restrict__ b4,
                             float* __restrict__ out, int n, int out_size) {
    int i = blockIdx.x * blockDim.x + threadIdx.x;
    int total = n * FEAT;
    if (i >= total) return;
    float v = g_agg[i] + b4[i & (FEAT - 1)];
    g_agg[i] = 0.f;                                  // restore zero invariant
    v = (v > 0.f) ? v : 0.f;
    out[i] = fabsf(x[i] - v);
    if (out_size >= 2 * total) out[total + i] = v;
}

extern "C" void kernel_launch(void* const* d_in, const int* in_sizes, int n_in,
                              void* d_out, int out_size) {
    const float* x   = (const float*)d_in[0];
    const void*  ei  = d_in[1];
    const float* W1  = (const float*)d_in[2];
    const float* a1s = (const float*)d_in[3];
    const float* a1d = (const float*)d_in[4];
    const float* b1  = (const float*)d_in[5];
    const float* g1  = (const float*)d_in[6];
    const float* be1 = (const float*)d_in[7];
    const float* W2  = (const float*)d_in[8];
    const float* a2s = (const float*)d_in[9];
    const float* a2d = (const float*)d_in[10];
    const float* b2  = (const float*)d_in[11];
    const float* g2  = (const float*)d_in[12];
    const float* be2 = (const float*)d_in[13];
    const float* W3  = (const float*)d_in[14];
    const float* a3s = (const float*)d_in[15];
    const float* a3d = (const float*)d_in[16];
    const float* b3  = (const float*)d_in[17];
    const float* g3  = (const float*)d_in[18];
    const float* be3 = (const float*)d_in[19];
    const float* W4  = (const float*)d_in[20];
    const float* a4s = (const float*)d_in[21];
    const float* a4d = (const float*)d_in[22];
    const float* b4  = (const float*)d_in[23];

    int n  = in_sizes[0] / FEAT;     // 50000
    int E  = in_sizes[1] / 2;        // 800000
    int ET = E + n;

    float *hbuf, *ybuf, *csum, *csq;
    cudaGetSymbolAddress((void**)&hbuf, g_h);
    cudaGetSymbolAddress((void**)&ybuf, g_y);
    cudaGetSymbolAddress((void**)&csum, g_colsum);
    cudaGetSymbolAddress((void**)&csq,  g_colsq);

    float invn = 1.0f / (float)n;

    start_kernel<<<1, 512>>>(ei);
    convert_kernel<<<(ET + 255) / 256, 256>>>(ei, E, ET);

    // ---- Layer 1: 128 -> 64 ----
    gemm_kernel<FEAT, HID><<<(n + 127) / 128, 256>>>(
        x, W1, nullptr, nullptr, nullptr, nullptr, invn, 0, a1s, a1d, hbuf, n);
    edge12_kernel<<<(ET + 255) / 256, 256>>>(ET);
    edge3_kernel<HID><<<(unsigned)(((long long)ET * (HID / 4) + 255) / 256), 256>>>(hbuf, ET);
    epi_bn_kernel<HID><<<(n + 63) / 64, 256>>>(b1, ybuf, csum + 0 * FEAT, csq + 0 * FEAT, n);

    // ---- Layer 2: 64 -> 64 (BN1 finalize folded into GEMM prologue) ----
    gemm_kernel<HID, HID><<<(n + 127) / 128, 256>>>(
        ybuf, W2, g1, be1, csum + 0 * FEAT, csq + 0 * FEAT, invn, 1, a2s, a2d, hbuf, n);
    edge12_kernel<<<(ET + 255) / 256, 256>>>(ET);
    edge3_kernel<HID><<<(unsigned)(((long long)ET * (HID / 4) + 255) / 256), 256>>>(hbuf, ET);
    epi_bn_kernel<HID><<<(n + 63) / 64, 256>>>(b2, ybuf, csum + 1 * FEAT, csq + 1 * FEAT, n);

    // ---- Layer 3: 64 -> 64 ----
    gemm_kernel<HID, HID><<<(n + 127) / 128, 256>>>(
        ybuf, W3, g2, be2, csum + 1 * FEAT, csq + 1 * FEAT, invn, 1, a3s, a3d, hbuf, n);
    edge12_kernel<<<(ET + 255) / 256, 256>>>(ET);
    edge3_kernel<HID><<<(unsigned)(((long long)ET * (HID / 4) + 255) / 256), 256>>>(hbuf, ET);
    epi_bn_kernel<HID><<<(n + 63) / 64, 256>>>(b3, ybuf, csum + 2 * FEAT, csq + 2 * FEAT, n);

    // ---- Layer 4: 64 -> 128 (no BN after) ----
    gemm_kernel<HID, FEAT><<<(n + 63) / 64, 256>>>(
        ybuf, W4, g3, be3, csum + 2 * FEAT, csq + 2 * FEAT, invn, 1, a4s, a4d, hbuf, n);
    edge12_kernel<<<(ET + 255) / 256, 256>>>(ET);
    edge3_kernel<FEAT><<<(unsigned)(((long long)ET * (FEAT / 4) + 255) / 256), 256>>>(hbuf, ET);
    final_kernel<<<(n * FEAT + 255) / 256, 256>>>(x, b4, (float*)d_out, n, out_size);
}

// round 9
// speedup vs baseline: 1.5943x; 1.5943x over previous
#include <cuda_runtime.h>
#include <math.h>

#define FEAT 128
#define HID  64
#define NMAX 50048
#define EMAX 1048576

// ---------------- scratch (static __device__) ----------------
__device__ float g_h[NMAX * FEAT];      // post-GEMM features h
__device__ float g_y[NMAX * HID];       // post-aggregation features
__device__ float g_as[NMAX];            // alpha_src per node
__device__ float g_ad[NMAX];            // alpha_dst per node
__device__ int2  g_sd[EMAX];            // packed (src, dst), original order
__device__ int   g_csrc[EMAX];          // CSR: src indices grouped by dst
__device__ int   g_cnt[NMAX];           // in-degree histogram
__device__ int   g_rowptr[NMAX + 1];    // CSR row pointers
__device__ int   g_cursor[NMAX];        // scatter cursors
__device__ float g_colsum[FEAT];        // BN stats (current layer)
__device__ float g_colsq[FEAT];
__device__ float g_scale[FEAT];         // BN affine for next GEMM
__device__ float g_shift[FEAT];
__device__ int   g_is64;

// ---------------- startup: zero histogram + stats, detect index dtype ----------------
__global__ void start_kernel(const void* ei, int n) {
    int i = blockIdx.x * blockDim.x + threadIdx.x;
    if (i < n) g_cnt[i] = 0;
    if (i < FEAT) { g_colsum[i] = 0.f; g_colsq[i] = 0.f; }
    if (blockIdx.x == 0 && threadIdx.x < 32) {
        const long long* p = (const long long*)ei;
        int bad = 0;
        for (int k = threadIdx.x; k < 64; k += 32) {
            long long v = p[k];
            if (v < 0 || v >= (1LL << 31)) bad = 1;
        }
        bad = __any_sync(0xffffffffu, bad);
        if (threadIdx.x == 0) g_is64 = bad ? 0 : 1;
    }
}

// ---------------- convert + degree histogram ----------------
__global__ void convert_kernel(const void* ei, int E, int ET) {
    int i = blockIdx.x * blockDim.x + threadIdx.x;
    if (i >= ET) return;
    int s, d;
    if (i < E) {
        if (g_is64) {
            const long long* p = (const long long*)ei;
            s = (int)p[i]; d = (int)p[E + i];
        } else {
            const int* p = (const int*)ei;
            s = p[i]; d = p[E + i];
        }
    } else {
        s = i - E; d = i - E;
    }
    g_sd[i] = make_int2(s, d);
    atomicAdd(&g_cnt[d], 1);
}

// ---------------- exclusive scan of degrees -> rowptr + cursors (1 block) ----------------
__global__ void scan_kernel(int n) {
    __shared__ int sp[1024];
    int tid = threadIdx.x;
    int chunk = (n + 1023) / 1024;
    int b = tid * chunk;
    int e = min(b + chunk, n);
    int s = 0;
    for (int i = b; i < e; i++) s += g_cnt[i];
    sp[tid] = s;
    __syncthreads();
    for (int off = 1; off < 1024; off <<= 1) {
        int v = (tid >= off) ? sp[tid - off] : 0;
        __syncthreads();
        sp[tid] += v;
        __syncthreads();
    }
    int pre = (tid > 0) ? sp[tid - 1] : 0;
    for (int i = b; i < e; i++) {
        g_rowptr[i] = pre;
        g_cursor[i] = pre;
        pre += g_cnt[i];
    }
    if (tid == 0) g_rowptr[n] = sp[1023];
}

// ---------------- scatter edges into CSR ----------------
__global__ void scatter_kernel(int ET) {
    int i = blockIdx.x * blockDim.x + threadIdx.x;
    if (i >= ET) return;
    int2 sd = g_sd[i];
    int pos = atomicAdd(&g_cursor[sd.y], 1);
    g_csrc[pos] = sd.x;
}

// ---------------- GEMM: h = affine(x) @ W^T  (round-4 exact structure) ----------------
// 256 threads; block tile M x OUT, M = 8192/OUT; thread tile 4x8; natural regs.
// Fused alpha_s/alpha_d epilogue.
template <int IN, int OUT>
__global__ void gemm_kernel(const float* __restrict__ x, const float* __restrict__ W,
                            int useAffine,
                            const float* __restrict__ avs, const float* __restrict__ avd,
                            float* __restrict__ h, int n) {
    const int M = 8192 / OUT;          // 128 (OUT=64) or 64 (OUT=128)
    const int OC = OUT / 8;            // col groups: 8 or 16
    const int KC = 32;
    const int SXS = M + 4;
    const int SWS = OUT + 4;

    __shared__ __align__(16) float sSc[IN];
    __shared__ __align__(16) float sSh[IN];
    __shared__ __align__(16) float sX[KC * SXS];
    __shared__ __align__(16) float sW[KC * SWS];

    int tid = threadIdx.x;
    int og = tid % OC;
    int rg = tid / OC;
    int r0 = blockIdx.x * M;

    if (useAffine) {
        for (int o = tid; o < IN; o += 256) { sSc[o] = g_scale[o]; sSh[o] = g_shift[o]; }
        __syncthreads();
    }

    float acc[4][8];
#pragma unroll
    for (int i = 0; i < 4; i++)
#pragma unroll
        for (int j = 0; j < 8; j++) acc[i][j] = 0.f;

    for (int kc = 0; kc < IN; kc += KC) {
        for (int idx = tid; idx < M * (KC / 4); idx += 256) {
            int r = idx >> 3, q = idx & 7;
            int k = q * 4;
            int row = r0 + r;
            float4 v = (row < n) ? *(const float4*)&x[row * IN + kc + k]
                                 : make_float4(0.f, 0.f, 0.f, 0.f);
            if (useAffine) {
                v.x = v.x * sSc[kc + k] + sSh[kc + k];
                v.y = v.y * sSc[kc + k + 1] + sSh[kc + k + 1];
                v.z = v.z * sSc[kc + k + 2] + sSh[kc + k + 2];
                v.w = v.w * sSc[kc + k + 3] + sSh[kc + k + 3];
            }
            sX[(k + 0) * SXS + r] = v.x;
            sX[(k + 1) * SXS + r] = v.y;
            sX[(k + 2) * SXS + r] = v.z;
            sX[(k + 3) * SXS + r] = v.w;
        }
        for (int idx = tid; idx < OUT * (KC / 4); idx += 256) {
            int o = idx >> 3, q = idx & 7;
            int k = q * 4;
            float4 w = *(const float4*)&W[o * IN + kc + k];
            sW[(k + 0) * SWS + o] = w.x;
            sW[(k + 1) * SWS + o] = w.y;
            sW[(k + 2) * SWS + o] = w.z;
            sW[(k + 3) * SWS + o] = w.w;
        }
        __syncthreads();

#pragma unroll
        for (int k = 0; k < KC; k++) {
            float4 a  = *(const float4*)&sX[k * SXS + rg * 4];
            float4 b0 = *(const float4*)&sW[k * SWS + og * 8];
            float4 b1 = *(const float4*)&sW[k * SWS + og * 8 + 4];
            float av[4] = {a.x, a.y, a.z, a.w};
            float bv[8] = {b0.x, b0.y, b0.z, b0.w, b1.x, b1.y, b1.z, b1.w};
#pragma unroll
            for (int i = 0; i < 4; i++)
#pragma unroll
                for (int j = 0; j < 8; j++)
                    acc[i][j] += av[i] * bv[j];
        }
        __syncthreads();
    }

    float avsr[8], avdr[8];
#pragma unroll
    for (int j = 0; j < 8; j++) {
        avsr[j] = __ldg(&avs[og * 8 + j]);
        avdr[j] = __ldg(&avd[og * 8 + j]);
    }

    float* sP = sX;                    // overlay: [M * OC] = 1024 floats
    float* sQ = sX + M * OC;
#pragma unroll
    for (int i = 0; i < 4; i++) {
        int rl = rg * 4 + i;
        int row = r0 + rl;
        float ps = 0.f, pd = 0.f;
#pragma unroll
        for (int j = 0; j < 8; j++) {
            ps += acc[i][j] * avsr[j];
            pd += acc[i][j] * avdr[j];
        }
        sP[rl * OC + og] = ps;
        sQ[rl * OC + og] = pd;
        if (row < n) {
            float4 v0 = make_float4(acc[i][0], acc[i][1], acc[i][2], acc[i][3]);
            float4 v1 = make_float4(acc[i][4], acc[i][5], acc[i][6], acc[i][7]);
            *(float4*)&h[row * OUT + og * 8] = v0;
            *(float4*)&h[row * OUT + og * 8 + 4] = v1;
        }
    }
    __syncthreads();
    if (tid < M) {
        int row = r0 + tid;
        if (row < n) {
            float as = 0.f, ad = 0.f;
#pragma unroll
            for (int t = 0; t < OC; t++) {
                as += sP[tid * OC + t];
                ad += sQ[tid * OC + t];
            }
            g_as[row] = as;
            g_ad[row] = ad;
        }
    }
}

// ---------------- fused CSR aggregation (thread-parallel gather) ----------------
// Thread = (node, 4-col group). Single loop over in-edges: t = exp(leakyrelu(as+ad))
// computed inline (broadcast loads), acc += t * h[src][cols], lsum += t.
// y = relu(acc/lsum + bias). MODE 0: +BN stats. MODE 1: final |x - xhat| output.
template <int OUT, int MODE>
__global__ void agg_kernel(const float* __restrict__ h, const float* __restrict__ b,
                           const float* __restrict__ x, float* __restrict__ yout,
                           int n, int out_size) {
    const int TPN = OUT / 4;            // threads per node: 16 or 32
    const int NPB = 256 / TPN;          // nodes per block: 16 or 8
    int c4 = threadIdx.x % TPN;
    int nl = threadIdx.x / TPN;

    float4 bias = *(const float4*)&b[c4 * 4];

    float st_s[4] = {0.f, 0.f, 0.f, 0.f};
    float st_q[4] = {0.f, 0.f, 0.f, 0.f};

    for (int node = blockIdx.x * NPB + nl; node < n; node += gridDim.x * NPB) {
        int p   = g_rowptr[node];
        int end = g_rowptr[node + 1];
        float adn = g_ad[node];

        float a0 = 0.f, a1 = 0.f, a2 = 0.f, a3 = 0.f;
        float lsum = 0.f;
        for (; p < end; p++) {
            int s = g_csrc[p];                       // broadcast across TPN lanes
            float e = g_as[s] + adn;                 // broadcast
            e = (e >= 0.f) ? e : 0.2f * e;
            float t = __expf(e);
            lsum += t;
            float4 hv = *(const float4*)&h[s * OUT + c4 * 4];
            a0 += t * hv.x; a1 += t * hv.y; a2 += t * hv.z; a3 += t * hv.w;
        }
        float inv = __fdividef(1.f, lsum + 1e-16f);
        float v0 = a0 * inv + bias.x; v0 = (v0 > 0.f) ? v0 : 0.f;
        float v1 = a1 * inv + bias.y; v1 = (v1 > 0.f) ? v1 : 0.f;
        float v2 = a2 * inv + bias.z; v2 = (v2 > 0.f) ? v2 : 0.f;
        float v3 = a3 * inv + bias.w; v3 = (v3 > 0.f) ? v3 : 0.f;

        if (MODE == 0) {
            *(float4*)&yout[node * OUT + c4 * 4] = make_float4(v0, v1, v2, v3);
            st_s[0] += v0; st_q[0] += v0 * v0;
            st_s[1] += v1; st_q[1] += v1 * v1;
            st_s[2] += v2; st_q[2] += v2 * v2;
            st_s[3] += v3; st_q[3] += v3 * v3;
        } else {
            float4 xv = *(const float4*)&x[node * OUT + c4 * 4];
            *(float4*)&yout[node * OUT + c4 * 4] =
                make_float4(fabsf(xv.x - v0), fabsf(xv.y - v1),
                            fabsf(xv.z - v2), fabsf(xv.w - v3));
            int total = n * OUT;
            if (out_size >= 2 * total)
                *(float4*)&yout[total + node * OUT + c4 * 4] =
                    make_float4(v0, v1, v2, v3);
        }
    }

    if (MODE == 0) {
        // block-level reduction over the NPB node-lanes sharing each column group
        __shared__ float sS[256 * 4];
        __shared__ float sQ[256 * 4];
#pragma unroll
        for (int c = 0; c < 4; c++) {
            sS[threadIdx.x * 4 + c] = st_s[c];
            sQ[threadIdx.x * 4 + c] = st_q[c];
        }
        __syncthreads();
        if (nl == 0) {                      // threads 0..TPN-1
#pragma unroll 4
            for (int t = 1; t < NPB; t++) {
#pragma unroll
                for (int c = 0; c < 4; c++) {
                    st_s[c] += sS[(t * TPN + c4) * 4 + c];
                    st_q[c] += sQ[(t * TPN + c4) * 4 + c];
                }
            }
#pragma unroll
            for (int c = 0; c < 4; c++) {
                atomicAdd(&g_colsum[c4 * 4 + c], st_s[c]);
                atomicAdd(&g_colsq[c4 * 4 + c], st_q[c]);
            }
        }
    }
}

// ---------------- BN finalize: scale/shift for next GEMM, reset stats ----------------
__global__ void bnfin_kernel(const float* __restrict__ g, const float* __restrict__ be,
                             int OUT, float invn) {
    int o = threadIdx.x;
    if (o >= OUT) return;
    float mu = g_colsum[o] * invn;
    float var = g_colsq[o] * invn - mu * mu;
    float sc = g[o] * rsqrtf(var + 1e-5f);
    g_scale[o] = sc;
    g_shift[o] = be[o] - mu * sc;
    g_colsum[o] = 0.f;                  // ready for next layer's stats
    g_colsq[o] = 0.f;
}

extern "C" void kernel_launch(void* const* d_in, const int* in_sizes, int n_in,
                              void* d_out, int out_size) {
    const float* x   = (const float*)d_in[0];
    const void*  ei  = d_in[1];
    const float* W1  = (const float*)d_in[2];
    const float* a1s = (const float*)d_in[3];
    const float* a1d = (const float*)d_in[4];
    const float* b1  = (const float*)d_in[5];
    const float* g1  = (const float*)d_in[6];
    const float* be1 = (const float*)d_in[7];
    const float* W2  = (const float*)d_in[8];
    const float* a2s = (const float*)d_in[9];
    const float* a2d = (const float*)d_in[10];
    const float* b2  = (const float*)d_in[11];
    const float* g2  = (const float*)d_in[12];
    const float* be2 = (const float*)d_in[13];
    const float* W3  = (const float*)d_in[14];
    const float* a3s = (const float*)d_in[15];
    const float* a3d = (const float*)d_in[16];
    const float* b3  = (const float*)d_in[17];
    const float* g3  = (const float*)d_in[18];
    const float* be3 = (const float*)d_in[19];
    const float* W4  = (const float*)d_in[20];
    const float* a4s = (const float*)d_in[21];
    const float* a4d = (const float*)d_in[22];
    const float* b4  = (const float*)d_in[23];

    int n  = in_sizes[0] / FEAT;     // 50000
    int E  = in_sizes[1] / 2;        // 800000
    int ET = E + n;

    float *hbuf, *ybuf;
    cudaGetSymbolAddress((void**)&hbuf, g_h);
    cudaGetSymbolAddress((void**)&ybuf, g_y);

    float invn = 1.0f / (float)n;
    const int AGG_BLOCKS = 1184;        // 8 blocks/SM, grid-stride over nodes

    // ---- CSR build (per replay; edges are replay-static but buffers are ours) ----
    start_kernel<<<(n + 255) / 256, 256>>>(ei, n);
    convert_kernel<<<(ET + 255) / 256, 256>>>(ei, E, ET);
    scan_kernel<<<1, 1024>>>(n);
    scatter_kernel<<<(ET + 255) / 256, 256>>>(ET);

    // ---- Layer 1: 128 -> 64 ----
    gemm_kernel<FEAT, HID><<<(n + 127) / 128, 256>>>(x, W1, 0, a1s, a1d, hbuf, n);
    agg_kernel<HID, 0><<<AGG_BLOCKS, 256>>>(hbuf, b1, nullptr, ybuf, n, 0);
    bnfin_kernel<<<1, HID>>>(g1, be1, HID, invn);

    // ---- Layer 2: 64 -> 64 ----
    gemm_kernel<HID, HID><<<(n + 127) / 128, 256>>>(ybuf, W2, 1, a2s, a2d, hbuf, n);
    agg_kernel<HID, 0><<<AGG_BLOCKS, 256>>>(hbuf, b2, nullptr, ybuf, n, 0);
    bnfin_kernel<<<1, HID>>>(g2, be2, HID, invn);

    // ---- Layer 3: 64 -> 64 ----
    gemm_kernel<HID, HID><<<(n + 127) / 128, 256>>>(ybuf, W3, 1, a3s, a3d, hbuf, n);
    agg_kernel<HID, 0><<<AGG_BLOCKS, 256>>>(hbuf, b3, nullptr, ybuf, n, 0);
    bnfin_kernel<<<1, HID>>>(g3, be3, HID, invn);

    // ---- Layer 4: 64 -> 128, fused final output ----
    gemm_kernel<HID, FEAT><<<(n + 63) / 64, 256>>>(ybuf, W4, 1, a4s, a4d, hbuf, n);
    agg_kernel<FEAT, 1><<<AGG_BLOCKS, 256>>>(hbuf, b4, x, (float*)d_out, n, out_size);
}

// round 10
// speedup vs baseline: 1.6097x; 1.0097x over previous
#include <cuda_runtime.h>
#include <math.h>

#define FEAT 128
#define HID  64
#define NMAX 50048
#define EMAX 1048576

// ---------------- scratch (static __device__) ----------------
__device__ float g_h[NMAX * FEAT];      // post-GEMM features h
__device__ float g_y[NMAX * HID];       // post-aggregation features
__device__ float g_as[NMAX];            // alpha_src per node
__device__ float g_ad[NMAX];            // alpha_dst per node
__device__ int   g_csrc[EMAX];          // CSR: src indices grouped by dst
__device__ int   g_cnt[NMAX];           // in-degree histogram
__device__ int   g_rowptr[NMAX + 1];    // CSR row pointers
__device__ int   g_cursor[NMAX];        // scatter cursors
__device__ float g_colsum[FEAT];        // BN stats (current layer)
__device__ float g_colsq[FEAT];
__device__ float g_scale[FEAT];         // BN affine for next GEMM
__device__ float g_shift[FEAT];
__device__ int   g_is64;

// ---------------- startup: zero histogram + stats, detect index dtype ----------------
__global__ void start_kernel(const void* ei, int n) {
    int i = blockIdx.x * blockDim.x + threadIdx.x;
    if (i < n) g_cnt[i] = 0;
    if (i < FEAT) { g_colsum[i] = 0.f; g_colsq[i] = 0.f; }
    if (blockIdx.x == 0 && threadIdx.x < 32) {
        const long long* p = (const long long*)ei;
        int bad = 0;
        for (int k = threadIdx.x; k < 64; k += 32) {
            long long v = p[k];
            if (v < 0 || v >= (1LL << 31)) bad = 1;
        }
        bad = __any_sync(0xffffffffu, bad);
        if (threadIdx.x == 0) g_is64 = bad ? 0 : 1;
    }
}

// ---------------- degree histogram (reads ei directly) ----------------
__global__ void convert_kernel(const void* ei, int E, int ET) {
    int i = blockIdx.x * blockDim.x + threadIdx.x;
    if (i >= ET) return;
    int d;
    if (i < E) {
        d = g_is64 ? (int)((const long long*)ei)[E + i] : ((const int*)ei)[E + i];
    } else {
        d = i - E;
    }
    atomicAdd(&g_cnt[d], 1);
}

// ---------------- exclusive scan of degrees -> rowptr + cursors (1 block) ----------------
__global__ void scan_kernel(int n) {
    __shared__ int sp[1024];
    int tid = threadIdx.x;
    int chunk = (n + 1023) / 1024;
    int b = tid * chunk;
    int e = min(b + chunk, n);
    int s = 0;
    for (int i = b; i < e; i++) s += g_cnt[i];
    sp[tid] = s;
    __syncthreads();
    for (int off = 1; off < 1024; off <<= 1) {
        int v = (tid >= off) ? sp[tid - off] : 0;
        __syncthreads();
        sp[tid] += v;
        __syncthreads();
    }
    int pre = (tid > 0) ? sp[tid - 1] : 0;
    for (int i = b; i < e; i++) {
        g_rowptr[i] = pre;
        g_cursor[i] = pre;
        pre += g_cnt[i];
    }
    if (tid == 0) g_rowptr[n] = sp[1023];
}

// ---------------- scatter edges into CSR (reads ei directly) ----------------
__global__ void scatter_kernel(const void* ei, int E, int ET) {
    int i = blockIdx.x * blockDim.x + threadIdx.x;
    if (i >= ET) return;
    int s, d;
    if (i < E) {
        if (g_is64) {
            const long long* p = (const long long*)ei;
            s = (int)p[i]; d = (int)p[E + i];
        } else {
            const int* p = (const int*)ei;
            s = p[i]; d = p[E + i];
        }
    } else {
        s = i - E; d = i - E;
    }
    int pos = atomicAdd(&g_cursor[d], 1);
    g_csrc[pos] = s;
}

// ---------------- GEMM: h = affine(x) @ W^T  (round-4 structure, untouched) ----------
template <int IN, int OUT>
__global__ void gemm_kernel(const float* __restrict__ x, const float* __restrict__ W,
                            int useAffine,
                            const float* __restrict__ avs, const float* __restrict__ avd,
                            float* __restrict__ h, int n) {
    const int M = 8192 / OUT;          // 128 (OUT=64) or 64 (OUT=128)
    const int OC = OUT / 8;            // col groups: 8 or 16
    const int KC = 32;
    const int SXS = M + 4;
    const int SWS = OUT + 4;

    __shared__ __align__(16) float sSc[IN];
    __shared__ __align__(16) float sSh[IN];
    __shared__ __align__(16) float sX[KC * SXS];
    __shared__ __align__(16) float sW[KC * SWS];

    int tid = threadIdx.x;
    int og = tid % OC;
    int rg = tid / OC;
    int r0 = blockIdx.x * M;

    if (useAffine) {
        for (int o = tid; o < IN; o += 256) { sSc[o] = g_scale[o]; sSh[o] = g_shift[o]; }
        __syncthreads();
    }

    float acc[4][8];
#pragma unroll
    for (int i = 0; i < 4; i++)
#pragma unroll
        for (int j = 0; j < 8; j++) acc[i][j] = 0.f;

    for (int kc = 0; kc < IN; kc += KC) {
        for (int idx = tid; idx < M * (KC / 4); idx += 256) {
            int r = idx >> 3, q = idx & 7;
            int k = q * 4;
            int row = r0 + r;
            float4 v = (row < n) ? *(const float4*)&x[row * IN + kc + k]
                                 : make_float4(0.f, 0.f, 0.f, 0.f);
            if (useAffine) {
                v.x = v.x * sSc[kc + k] + sSh[kc + k];
                v.y = v.y * sSc[kc + k + 1] + sSh[kc + k + 1];
                v.z = v.z * sSc[kc + k + 2] + sSh[kc + k + 2];
                v.w = v.w * sSc[kc + k + 3] + sSh[kc + k + 3];
            }
            sX[(k + 0) * SXS + r] = v.x;
            sX[(k + 1) * SXS + r] = v.y;
            sX[(k + 2) * SXS + r] = v.z;
            sX[(k + 3) * SXS + r] = v.w;
        }
        for (int idx = tid; idx < OUT * (KC / 4); idx += 256) {
            int o = idx >> 3, q = idx & 7;
            int k = q * 4;
            float4 w = *(const float4*)&W[o * IN + kc + k];
            sW[(k + 0) * SWS + o] = w.x;
            sW[(k + 1) * SWS + o] = w.y;
            sW[(k + 2) * SWS + o] = w.z;
            sW[(k + 3) * SWS + o] = w.w;
        }
        __syncthreads();

#pragma unroll
        for (int k = 0; k < KC; k++) {
            float4 a  = *(const float4*)&sX[k * SXS + rg * 4];
            float4 b0 = *(const float4*)&sW[k * SWS + og * 8];
            float4 b1 = *(const float4*)&sW[k * SWS + og * 8 + 4];
            float av[4] = {a.x, a.y, a.z, a.w};
            float bv[8] = {b0.x, b0.y, b0.z, b0.w, b1.x, b1.y, b1.z, b1.w};
#pragma unroll
            for (int i = 0; i < 4; i++)
#pragma unroll
                for (int j = 0; j < 8; j++)
                    acc[i][j] += av[i] * bv[j];
        }
        __syncthreads();
    }

    float avsr[8], avdr[8];
#pragma unroll
    for (int j = 0; j < 8; j++) {
        avsr[j] = __ldg(&avs[og * 8 + j]);
        avdr[j] = __ldg(&avd[og * 8 + j]);
    }

    float* sP = sX;                    // overlay: [M * OC] = 1024 floats
    float* sQ = sX + M * OC;
#pragma unroll
    for (int i = 0; i < 4; i++) {
        int rl = rg * 4 + i;
        int row = r0 + rl;
        float ps = 0.f, pd = 0.f;
#pragma unroll
        for (int j = 0; j < 8; j++) {
            ps += acc[i][j] * avsr[j];
            pd += acc[i][j] * avdr[j];
        }
        sP[rl * OC + og] = ps;
        sQ[rl * OC + og] = pd;
        if (row < n) {
            float4 v0 = make_float4(acc[i][0], acc[i][1], acc[i][2], acc[i][3]);
            float4 v1 = make_float4(acc[i][4], acc[i][5], acc[i][6], acc[i][7]);
            *(float4*)&h[row * OUT + og * 8] = v0;
            *(float4*)&h[row * OUT + og * 8 + 4] = v1;
        }
    }
    __syncthreads();
    if (tid < M) {
        int row = r0 + tid;
        if (row < n) {
            float as = 0.f, ad = 0.f;
#pragma unroll
            for (int t = 0; t < OC; t++) {
                as += sP[tid * OC + t];
                ad += sQ[tid * OC + t];
            }
            g_as[row] = as;
            g_ad[row] = ad;
        }
    }
}

// ---------------- fused CSR aggregation (thread-parallel gather, x2 unrolled) -------
// Thread = (node, 4-col group). Edge loop unrolled x2 with independent loads to
// double MLP into L2 (dependent-chain latency was the binding constraint).
template <int OUT, int MODE>
__global__ void agg_kernel(const float* __restrict__ h, const float* __restrict__ b,
                           const float* __restrict__ x, float* __restrict__ yout,
                           int n, int out_size) {
    const int TPN = OUT / 4;            // threads per node: 16 or 32
    const int NPB = 256 / TPN;          // nodes per block: 16 or 8
    int c4 = threadIdx.x % TPN;
    int nl = threadIdx.x / TPN;

    float4 bias = *(const float4*)&b[c4 * 4];

    float st_s[4] = {0.f, 0.f, 0.f, 0.f};
    float st_q[4] = {0.f, 0.f, 0.f, 0.f};

    for (int node = blockIdx.x * NPB + nl; node < n; node += gridDim.x * NPB) {
        int p   = g_rowptr[node];
        int end = g_rowptr[node + 1];
        float adn = g_ad[node];

        float a0 = 0.f, a1 = 0.f, a2 = 0.f, a3 = 0.f;
        float b0 = 0.f, b1_ = 0.f, b2 = 0.f, b3 = 0.f;
        float lsum = 0.f;

        // x2 unrolled: two independent edge chains per iteration
        for (; p + 2 <= end; p += 2) {
            int s0 = g_csrc[p];
            int s1 = g_csrc[p + 1];
            float e0 = g_as[s0] + adn;
            float e1 = g_as[s1] + adn;
            float4 h0 = *(const float4*)&h[s0 * OUT + c4 * 4];
            float4 h1 = *(const float4*)&h[s1 * OUT + c4 * 4];
            e0 = (e0 >= 0.f) ? e0 : 0.2f * e0;
            e1 = (e1 >= 0.f) ? e1 : 0.2f * e1;
            float t0 = __expf(e0);
            float t1 = __expf(e1);
            lsum += t0 + t1;
            a0 += t0 * h0.x; a1 += t0 * h0.y; a2 += t0 * h0.z; a3 += t0 * h0.w;
            b0 += t1 * h1.x; b1_ += t1 * h1.y; b2 += t1 * h1.z; b3 += t1 * h1.w;
        }
        if (p < end) {
            int s = g_csrc[p];
            float e = g_as[s] + adn;
            e = (e >= 0.f) ? e : 0.2f * e;
            float t = __expf(e);
            lsum += t;
            float4 hv = *(const float4*)&h[s * OUT + c4 * 4];
            a0 += t * hv.x; a1 += t * hv.y; a2 += t * hv.z; a3 += t * hv.w;
        }
        a0 += b0; a1 += b1_; a2 += b2; a3 += b3;

        float inv = __fdividef(1.f, lsum + 1e-16f);
        float v0 = a0 * inv + bias.x; v0 = (v0 > 0.f) ? v0 : 0.f;
        float v1 = a1 * inv + bias.y; v1 = (v1 > 0.f) ? v1 : 0.f;
        float v2 = a2 * inv + bias.z; v2 = (v2 > 0.f) ? v2 : 0.f;
        float v3 = a3 * inv + bias.w; v3 = (v3 > 0.f) ? v3 : 0.f;

        if (MODE == 0) {
            *(float4*)&yout[node * OUT + c4 * 4] = make_float4(v0, v1, v2, v3);
            st_s[0] += v0; st_q[0] += v0 * v0;
            st_s[1] += v1; st_q[1] += v1 * v1;
            st_s[2] += v2; st_q[2] += v2 * v2;
            st_s[3] += v3; st_q[3] += v3 * v3;
        } else {
            float4 xv = *(const float4*)&x[node * OUT + c4 * 4];
            *(float4*)&yout[node * OUT + c4 * 4] =
                make_float4(fabsf(xv.x - v0), fabsf(xv.y - v1),
                            fabsf(xv.z - v2), fabsf(xv.w - v3));
            int total = n * OUT;
            if (out_size >= 2 * total)
                *(float4*)&yout[total + node * OUT + c4 * 4] =
                    make_float4(v0, v1, v2, v3);
        }
    }

    if (MODE == 0) {
        __shared__ float sS[256 * 4];
        __shared__ float sQ[256 * 4];
#pragma unroll
        for (int c = 0; c < 4; c++) {
            sS[threadIdx.x * 4 + c] = st_s[c];
            sQ[threadIdx.x * 4 + c] = st_q[c];
        }
        __syncthreads();
        if (nl == 0) {
#pragma unroll 4
            for (int t = 1; t < NPB; t++) {
#pragma unroll
                for (int c = 0; c < 4; c++) {
                    st_s[c] += sS[(t * TPN + c4) * 4 + c];
                    st_q[c] += sQ[(t * TPN + c4) * 4 + c];
                }
            }
#pragma unroll
            for (int c = 0; c < 4; c++) {
                atomicAdd(&g_colsum[c4 * 4 + c], st_s[c]);
                atomicAdd(&g_colsq[c4 * 4 + c], st_q[c]);
            }
        }
    }
}

// ---------------- BN finalize: scale/shift for next GEMM, reset stats ----------------
__global__ void bnfin_kernel(const float* __restrict__ g, const float* __restrict__ be,
                             int OUT, float invn) {
    int o = threadIdx.x;
    if (o >= OUT) return;
    float mu = g_colsum[o] * invn;
    float var = g_colsq[o] * invn - mu * mu;
    float sc = g[o] * rsqrtf(var + 1e-5f);
    g_scale[o] = sc;
    g_shift[o] = be[o] - mu * sc;
    g_colsum[o] = 0.f;
    g_colsq[o] = 0.f;
}

extern "C" void kernel_launch(void* const* d_in, const int* in_sizes, int n_in,
                              void* d_out, int out_size) {
    const float* x   = (const float*)d_in[0];
    const void*  ei  = d_in[1];
    const float* W1  = (const float*)d_in[2];
    const float* a1s = (const float*)d_in[3];
    const float* a1d = (const float*)d_in[4];
    const float* b1  = (const float*)d_in[5];
    const float* g1  = (const float*)d_in[6];
    const float* be1 = (const float*)d_in[7];
    const float* W2  = (const float*)d_in[8];
    const float* a2s = (const float*)d_in[9];
    const float* a2d = (const float*)d_in[10];
    const float* b2  = (const float*)d_in[11];
    const float* g2  = (const float*)d_in[12];
    const float* be2 = (const float*)d_in[13];
    const float* W3  = (const float*)d_in[14];
    const float* a3s = (const float*)d_in[15];
    const float* a3d = (const float*)d_in[16];
    const float* b3  = (const float*)d_in[17];
    const float* g3  = (const float*)d_in[18];
    const float* be3 = (const float*)d_in[19];
    const float* W4  = (const float*)d_in[20];
    const float* a4s = (const float*)d_in[21];
    const float* a4d = (const float*)d_in[22];
    const float* b4  = (const float*)d_in[23];

    int n  = in_sizes[0] / FEAT;     // 50000
    int E  = in_sizes[1] / 2;        // 800000
    int ET = E + n;

    float *hbuf, *ybuf;
    cudaGetSymbolAddress((void**)&hbuf, g_h);
    cudaGetSymbolAddress((void**)&ybuf, g_y);

    float invn = 1.0f / (float)n;
    const int AGG_BLOCKS = 1184;        // grid-stride over nodes

    // ---- CSR build ----
    start_kernel<<<(n + 255) / 256, 256>>>(ei, n);
    convert_kernel<<<(ET + 255) / 256, 256>>>(ei, E, ET);
    scan_kernel<<<1, 1024>>>(n);
    scatter_kernel<<<(ET + 255) / 256, 256>>>(ei, E, ET);

    // ---- Layer 1: 128 -> 64 ----
    gemm_kernel<FEAT, HID><<<(n + 127) / 128, 256>>>(x, W1, 0, a1s, a1d, hbuf, n);
    agg_kernel<HID, 0><<<AGG_BLOCKS, 256>>>(hbuf, b1, nullptr, ybuf, n, 0);
    bnfin_kernel<<<1, HID>>>(g1, be1, HID, invn);

    // ---- Layer 2: 64 -> 64 ----
    gemm_kernel<HID, HID><<<(n + 127) / 128, 256>>>(ybuf, W2, 1, a2s, a2d, hbuf, n);
    agg_kernel<HID, 0><<<AGG_BLOCKS, 256>>>(hbuf, b2, nullptr, ybuf, n, 0);
    bnfin_kernel<<<1, HID>>>(g2, be2, HID, invn);

    // ---- Layer 3: 64 -> 64 ----
    gemm_kernel<HID, HID><<<(n + 127) / 128, 256>>>(ybuf, W3, 1, a3s, a3d, hbuf, n);
    agg_kernel<HID, 0><<<AGG_BLOCKS, 256>>>(hbuf, b3, nullptr, ybuf, n, 0);
    bnfin_kernel<<<1, HID>>>(g3, be3, HID, invn);

    // ---- Layer 4: 64 -> 128, fused final output ----
    gemm_kernel<HID, FEAT><<<(n + 63) / 64, 256>>>(ybuf, W4, 1, a4s, a4d, hbuf, n);
    agg_kernel<FEAT, 1><<<AGG_BLOCKS, 256>>>(hbuf, b4, x, (float*)d_out, n, out_size);
}

// round 11
// speedup vs baseline: 1.6357x; 1.0161x over previous
#include <cuda_runtime.h>
#include <math.h>

#define FEAT 128
#define HID  64
#define NMAX 50048
#define EMAX 1048576

// ---------------- scratch (static __device__) ----------------
__device__ float g_h[NMAX * HID];       // post-GEMM features h (layers 1-3) / aggregated u (layer 4)
__device__ float g_y[NMAX * HID];       // post-aggregation features
__device__ float g_as[NMAX];            // alpha_src per node
__device__ float g_ad[NMAX];            // alpha_dst per node
__device__ int   g_csrc[EMAX];          // CSR: src indices grouped by dst
__device__ int   g_cnt[NMAX];           // in-degree histogram
__device__ int   g_rowptr[NMAX + 1];    // CSR row pointers
__device__ int   g_cursor[NMAX];        // scatter cursors
__device__ float g_colsum[FEAT];        // BN stats (current layer)
__device__ float g_colsq[FEAT];
__device__ float g_scale[FEAT];         // BN affine for next GEMM
__device__ float g_shift[FEAT];
__device__ float g_w4s[HID];            // W4^T @ a4s
__device__ float g_w4d[HID];            // W4^T @ a4d
__device__ int   g_is64;

// ---------------- startup: zero histogram + stats, detect index dtype ----------------
__global__ void start_kernel(const void* ei, int n) {
    int i = blockIdx.x * blockDim.x + threadIdx.x;
    if (i < n) g_cnt[i] = 0;
    if (i < FEAT) { g_colsum[i] = 0.f; g_colsq[i] = 0.f; }
    if (blockIdx.x == 0 && threadIdx.x < 32) {
        const long long* p = (const long long*)ei;
        int bad = 0;
        for (int k = threadIdx.x; k < 64; k += 32) {
            long long v = p[k];
            if (v < 0 || v >= (1LL << 31)) bad = 1;
        }
        bad = __any_sync(0xffffffffu, bad);
        if (threadIdx.x == 0) g_is64 = bad ? 0 : 1;
    }
}

// ---------------- w4 = W4^T @ a4s / a4d  (64-dim vectors for layer-4 alpha) ----------
__global__ void w4_kernel(const float* __restrict__ W4, const float* __restrict__ a4s,
                          const float* __restrict__ a4d) {
    int k = threadIdx.x;                 // 0..63
    float s = 0.f, d = 0.f;
#pragma unroll 8
    for (int o = 0; o < FEAT; o++) {
        float w = W4[o * HID + k];
        s += w * a4s[o];
        d += w * a4d[o];
    }
    g_w4s[k] = s;
    g_w4d[k] = d;
}

// ---------------- degree histogram (reads ei directly) ----------------
__global__ void convert_kernel(const void* ei, int E, int ET) {
    int i = blockIdx.x * blockDim.x + threadIdx.x;
    if (i >= ET) return;
    int d;
    if (i < E) {
        d = g_is64 ? (int)((const long long*)ei)[E + i] : ((const int*)ei)[E + i];
    } else {
        d = i - E;
    }
    atomicAdd(&g_cnt[d], 1);
}

// ---------------- exclusive scan of degrees -> rowptr + cursors (1 block) ----------------
__global__ void scan_kernel(int n) {
    __shared__ int sp[1024];
    int tid = threadIdx.x;
    int chunk = (n + 1023) / 1024;
    int b = tid * chunk;
    int e = min(b + chunk, n);
    int s = 0;
    for (int i = b; i < e; i++) s += g_cnt[i];
    sp[tid] = s;
    __syncthreads();
    for (int off = 1; off < 1024; off <<= 1) {
        int v = (tid >= off) ? sp[tid - off] : 0;
        __syncthreads();
        sp[tid] += v;
        __syncthreads();
    }
    int pre = (tid > 0) ? sp[tid - 1] : 0;
    for (int i = b; i < e; i++) {
        g_rowptr[i] = pre;
        g_cursor[i] = pre;
        pre += g_cnt[i];
    }
    if (tid == 0) g_rowptr[n] = sp[1023];
}

// ---------------- scatter edges into CSR (reads ei directly) ----------------
__global__ void scatter_kernel(const void* ei, int E, int ET) {
    int i = blockIdx.x * blockDim.x + threadIdx.x;
    if (i >= ET) return;
    int s, d;
    if (i < E) {
        if (g_is64) {
            const long long* p = (const long long*)ei;
            s = (int)p[i]; d = (int)p[E + i];
        } else {
            const int* p = (const int*)ei;
            s = p[i]; d = p[E + i];
        }
    } else {
        s = i - E; d = i - E;
    }
    int pos = atomicAdd(&g_cursor[d], 1);
    g_csrc[pos] = s;
}

// ---------------- GEMM: h = affine(x) @ W^T  (layers 1-3, untouched structure) -------
template <int IN, int OUT>
__global__ void gemm_kernel(const float* __restrict__ x, const float* __restrict__ W,
                            int useAffine,
                            const float* __restrict__ avs, const float* __restrict__ avd,
                            float* __restrict__ h, int n) {
    const int M = 8192 / OUT;
    const int OC = OUT / 8;
    const int KC = 32;
    const int SXS = M + 4;
    const int SWS = OUT + 4;

    __shared__ __align__(16) float sSc[IN];
    __shared__ __align__(16) float sSh[IN];
    __shared__ __align__(16) float sX[KC * SXS];
    __shared__ __align__(16) float sW[KC * SWS];

    int tid = threadIdx.x;
    int og = tid % OC;
    int rg = tid / OC;
    int r0 = blockIdx.x * M;

    if (useAffine) {
        for (int o = tid; o < IN; o += 256) { sSc[o] = g_scale[o]; sSh[o] = g_shift[o]; }
        __syncthreads();
    }

    float acc[4][8];
#pragma unroll
    for (int i = 0; i < 4; i++)
#pragma unroll
        for (int j = 0; j < 8; j++) acc[i][j] = 0.f;

    for (int kc = 0; kc < IN; kc += KC) {
        for (int idx = tid; idx < M * (KC / 4); idx += 256) {
            int r = idx >> 3, q = idx & 7;
            int k = q * 4;
            int row = r0 + r;
            float4 v = (row < n) ? *(const float4*)&x[row * IN + kc + k]
                                 : make_float4(0.f, 0.f, 0.f, 0.f);
            if (useAffine) {
                v.x = v.x * sSc[kc + k] + sSh[kc + k];
                v.y = v.y * sSc[kc + k + 1] + sSh[kc + k + 1];
                v.z = v.z * sSc[kc + k + 2] + sSh[kc + k + 2];
                v.w = v.w * sSc[kc + k + 3] + sSh[kc + k + 3];
            }
            sX[(k + 0) * SXS + r] = v.x;
            sX[(k + 1) * SXS + r] = v.y;
            sX[(k + 2) * SXS + r] = v.z;
            sX[(k + 3) * SXS + r] = v.w;
        }
        for (int idx = tid; idx < OUT * (KC / 4); idx += 256) {
            int o = idx >> 3, q = idx & 7;
            int k = q * 4;
            float4 w = *(const float4*)&W[o * IN + kc + k];
            sW[(k + 0) * SWS + o] = w.x;
            sW[(k + 1) * SWS + o] = w.y;
            sW[(k + 2) * SWS + o] = w.z;
            sW[(k + 3) * SWS + o] = w.w;
        }
        __syncthreads();

#pragma unroll
        for (int k = 0; k < KC; k++) {
            float4 a  = *(const float4*)&sX[k * SXS + rg * 4];
            float4 b0 = *(const float4*)&sW[k * SWS + og * 8];
            float4 b1 = *(const float4*)&sW[k * SWS + og * 8 + 4];
            float av[4] = {a.x, a.y, a.z, a.w};
            float bv[8] = {b0.x, b0.y, b0.z, b0.w, b1.x, b1.y, b1.z, b1.w};
#pragma unroll
            for (int i = 0; i < 4; i++)
#pragma unroll
                for (int j = 0; j < 8; j++)
                    acc[i][j] += av[i] * bv[j];
        }
        __syncthreads();
    }

    float avsr[8], avdr[8];
#pragma unroll
    for (int j = 0; j < 8; j++) {
        avsr[j] = __ldg(&avs[og * 8 + j]);
        avdr[j] = __ldg(&avd[og * 8 + j]);
    }

    float* sP = sX;
    float* sQ = sX + M * OC;
#pragma unroll
    for (int i = 0; i < 4; i++) {
        int rl = rg * 4 + i;
        int row = r0 + rl;
        float ps = 0.f, pd = 0.f;
#pragma unroll
        for (int j = 0; j < 8; j++) {
            ps += acc[i][j] * avsr[j];
            pd += acc[i][j] * avdr[j];
        }
        sP[rl * OC + og] = ps;
        sQ[rl * OC + og] = pd;
        if (row < n) {
            float4 v0 = make_float4(acc[i][0], acc[i][1], acc[i][2], acc[i][3]);
            float4 v1 = make_float4(acc[i][4], acc[i][5], acc[i][6], acc[i][7]);
            *(float4*)&h[row * OUT + og * 8] = v0;
            *(float4*)&h[row * OUT + og * 8 + 4] = v1;
        }
    }
    __syncthreads();
    if (tid < M) {
        int row = r0 + tid;
        if (row < n) {
            float as = 0.f, ad = 0.f;
#pragma unroll
            for (int t = 0; t < OC; t++) {
                as += sP[tid * OC + t];
                ad += sQ[tid * OC + t];
            }
            g_as[row] = as;
            g_ad[row] = ad;
        }
    }
}

// ---------------- final GEMM: x_hat = relu(affine(u) @ W4^T + b4); out = |x-xhat|,xhat --
__global__ void gemm_final_kernel(const float* __restrict__ u, const float* __restrict__ W,
                                  const float* __restrict__ b4, const float* __restrict__ x,
                                  float* __restrict__ out, int n, int out_size) {
    const int IN = HID, OUT = FEAT;
    const int M = 8192 / OUT;          // 64
    const int OC = OUT / 8;            // 16
    const int KC = 32;
    const int SXS = M + 4;
    const int SWS = OUT + 4;

    __shared__ __align__(16) float sSc[IN];
    __shared__ __align__(16) float sSh[IN];
    __shared__ __align__(16) float sX[KC * SXS];
    __shared__ __align__(16) float sW[KC * SWS];

    int tid = threadIdx.x;
    int og = tid % OC;
    int rg = tid / OC;
    int r0 = blockIdx.x * M;

    for (int o = tid; o < IN; o += 256) { sSc[o] = g_scale[o]; sSh[o] = g_shift[o]; }
    __syncthreads();

    float acc[4][8];
#pragma unroll
    for (int i = 0; i < 4; i++)
#pragma unroll
        for (int j = 0; j < 8; j++) acc[i][j] = 0.f;

    for (int kc = 0; kc < IN; kc += KC) {
        for (int idx = tid; idx < M * (KC / 4); idx += 256) {
            int r = idx >> 3, q = idx & 7;
            int k = q * 4;
            int row = r0 + r;
            float4 v = (row < n) ? *(const float4*)&u[row * IN + kc + k]
                                 : make_float4(0.f, 0.f, 0.f, 0.f);
            v.x = v.x * sSc[kc + k] + sSh[kc + k];
            v.y = v.y * sSc[kc + k + 1] + sSh[kc + k + 1];
            v.z = v.z * sSc[kc + k + 2] + sSh[kc + k + 2];
            v.w = v.w * sSc[kc + k + 3] + sSh[kc + k + 3];
            sX[(k + 0) * SXS + r] = v.x;
            sX[(k + 1) * SXS + r] = v.y;
            sX[(k + 2) * SXS + r] = v.z;
            sX[(k + 3) * SXS + r] = v.w;
        }
        for (int idx = tid; idx < OUT * (KC / 4); idx += 256) {
            int o = idx >> 3, q = idx & 7;
            int k = q * 4;
            float4 w = *(const float4*)&W[o * IN + kc + k];
            sW[(k + 0) * SWS + o] = w.x;
            sW[(k + 1) * SWS + o] = w.y;
            sW[(k + 2) * SWS + o] = w.z;
            sW[(k + 3) * SWS + o] = w.w;
        }
        __syncthreads();

#pragma unroll
        for (int k = 0; k < KC; k++) {
            float4 a  = *(const float4*)&sX[k * SXS + rg * 4];
            float4 b0 = *(const float4*)&sW[k * SWS + og * 8];
            float4 b1 = *(const float4*)&sW[k * SWS + og * 8 + 4];
            float av[4] = {a.x, a.y, a.z, a.w};
            float bv[8] = {b0.x, b0.y, b0.z, b0.w, b1.x, b1.y, b1.z, b1.w};
#pragma unroll
            for (int i = 0; i < 4; i++)
#pragma unroll
                for (int j = 0; j < 8; j++)
                    acc[i][j] += av[i] * bv[j];
        }
        __syncthreads();
    }

    float4 ba = *(const float4*)&b4[og * 8];
    float4 bb = *(const float4*)&b4[og * 8 + 4];
    float bias[8] = {ba.x, ba.y, ba.z, ba.w, bb.x, bb.y, bb.z, bb.w};
    int total = n * OUT;
    int full = (out_size >= 2 * total);

#pragma unroll
    for (int i = 0; i < 4; i++) {
        int row = r0 + rg * 4 + i;
        if (row < n) {
            float v[8];
#pragma unroll
            for (int j = 0; j < 8; j++) {
                v[j] = acc[i][j] + bias[j];
                v[j] = (v[j] > 0.f) ? v[j] : 0.f;
            }
            float4 x0 = *(const float4*)&x[row * OUT + og * 8];
            float4 x1 = *(const float4*)&x[row * OUT + og * 8 + 4];
            *(float4*)&out[row * OUT + og * 8] =
                make_float4(fabsf(x0.x - v[0]), fabsf(x0.y - v[1]),
                            fabsf(x0.z - v[2]), fabsf(x0.w - v[3]));
            *(float4*)&out[row * OUT + og * 8 + 4] =
                make_float4(fabsf(x1.x - v[4]), fabsf(x1.y - v[5]),
                            fabsf(x1.z - v[6]), fabsf(x1.w - v[7]));
            if (full) {
                *(float4*)&out[total + row * OUT + og * 8] =
                    make_float4(v[0], v[1], v[2], v[3]);
                *(float4*)&out[total + row * OUT + og * 8 + 4] =
                    make_float4(v[4], v[5], v[6], v[7]);
            }
        }
    }
}

// ---------------- alpha for layer 4: as/ad = BN3(y) . w4s/w4d  (warp per node) -------
__global__ void alpha4_kernel(const float* __restrict__ y, int n) {
    int warp = (blockIdx.x * blockDim.x + threadIdx.x) >> 5;
    int lane = threadIdx.x & 31;
    if (warp >= n) return;
    float as = 0.f, ad = 0.f;
#pragma unroll
    for (int j = 0; j < 2; j++) {
        int k = j * 32 + lane;
        float v = y[warp * HID + k] * g_scale[k] + g_shift[k];
        as += v * g_w4s[k];
        ad += v * g_w4d[k];
    }
#pragma unroll
    for (int off = 16; off; off >>= 1) {
        as += __shfl_down_sync(0xffffffffu, as, off);
        ad += __shfl_down_sync(0xffffffffu, ad, off);
    }
    if (lane == 0) { g_as[warp] = as; g_ad[warp] = ad; }
}

// ---------------- fused CSR aggregation (thread-parallel gather, x2 unrolled) -------
// MODE 0: y = relu(agg + b) + BN stats.  MODE 3: raw aggregate u (no bias/relu/stats).
template <int OUT, int MODE>
__global__ void agg_kernel(const float* __restrict__ h, const float* __restrict__ b,
                           float* __restrict__ yout, int n) {
    const int TPN = OUT / 4;
    const int NPB = 256 / TPN;
    int c4 = threadIdx.x % TPN;
    int nl = threadIdx.x / TPN;

    float4 bias = (MODE == 0) ? *(const float4*)&b[c4 * 4] : make_float4(0.f, 0.f, 0.f, 0.f);

    float st_s[4] = {0.f, 0.f, 0.f, 0.f};
    float st_q[4] = {0.f, 0.f, 0.f, 0.f};

    for (int node = blockIdx.x * NPB + nl; node < n; node += gridDim.x * NPB) {
        int p   = g_rowptr[node];
        int end = g_rowptr[node + 1];
        float adn = g_ad[node];

        float a0 = 0.f, a1 = 0.f, a2 = 0.f, a3 = 0.f;
        float b0 = 0.f, b1_ = 0.f, b2 = 0.f, b3 = 0.f;
        float lsum = 0.f;

        for (; p + 2 <= end; p += 2) {
            int s0 = g_csrc[p];
            int s1 = g_csrc[p + 1];
            float e0 = g_as[s0] + adn;
            float e1 = g_as[s1] + adn;
            float4 h0 = *(const float4*)&h[s0 * OUT + c4 * 4];
            float4 h1 = *(const float4*)&h[s1 * OUT + c4 * 4];
            e0 = (e0 >= 0.f) ? e0 : 0.2f * e0;
            e1 = (e1 >= 0.f) ? e1 : 0.2f * e1;
            float t0 = __expf(e0);
            float t1 = __expf(e1);
            lsum += t0 + t1;
            a0 += t0 * h0.x; a1 += t0 * h0.y; a2 += t0 * h0.z; a3 += t0 * h0.w;
            b0 += t1 * h1.x; b1_ += t1 * h1.y; b2 += t1 * h1.z; b3 += t1 * h1.w;
        }
        if (p < end) {
            int s = g_csrc[p];
            float e = g_as[s] + adn;
            e = (e >= 0.f) ? e : 0.2f * e;
            float t = __expf(e);
            lsum += t;
            float4 hv = *(const float4*)&h[s * OUT + c4 * 4];
            a0 += t * hv.x; a1 += t * hv.y; a2 += t * hv.z; a3 += t * hv.w;
        }
        a0 += b0; a1 += b1_; a2 += b2; a3 += b3;

        float inv = __fdividef(1.f, lsum + 1e-16f);

        if (MODE == 0) {
            float v0 = a0 * inv + bias.x; v0 = (v0 > 0.f) ? v0 : 0.f;
            float v1 = a1 * inv + bias.y; v1 = (v1 > 0.f) ? v1 : 0.f;
            float v2 = a2 * inv + bias.z; v2 = (v2 > 0.f) ? v2 : 0.f;
            float v3 = a3 * inv + bias.w; v3 = (v3 > 0.f) ? v3 : 0.f;
            *(float4*)&yout[node * OUT + c4 * 4] = make_float4(v0, v1, v2, v3);
            st_s[0] += v0; st_q[0] += v0 * v0;
            st_s[1] += v1; st_q[1] += v1 * v1;
            st_s[2] += v2; st_q[2] += v2 * v2;
            st_s[3] += v3; st_q[3] += v3 * v3;
        } else {
            *(float4*)&yout[node * OUT + c4 * 4] =
                make_float4(a0 * inv, a1 * inv, a2 * inv, a3 * inv);
        }
    }

    if (MODE == 0) {
        __shared__ float sS[256 * 4];
        __shared__ float sQ[256 * 4];
#pragma unroll
        for (int c = 0; c < 4; c++) {
            sS[threadIdx.x * 4 + c] = st_s[c];
            sQ[threadIdx.x * 4 + c] = st_q[c];
        }
        __syncthreads();
        if (nl == 0) {
#pragma unroll 4
            for (int t = 1; t < NPB; t++) {
#pragma unroll
                for (int c = 0; c < 4; c++) {
                    st_s[c] += sS[(t * TPN + c4) * 4 + c];
                    st_q[c] += sQ[(t * TPN + c4) * 4 + c];
                }
            }
#pragma unroll
            for (int c = 0; c < 4; c++) {
                atomicAdd(&g_colsum[c4 * 4 + c], st_s[c]);
                atomicAdd(&g_colsq[c4 * 4 + c], st_q[c]);
            }
        }
    }
}

// ---------------- BN finalize: scale/shift for next GEMM, reset stats ----------------
__global__ void bnfin_kernel(const float* __restrict__ g, const float* __restrict__ be,
                             int OUT, float invn) {
    int o = threadIdx.x;
    if (o >= OUT) return;
    float mu = g_colsum[o] * invn;
    float var = g_colsq[o] * invn - mu * mu;
    float sc = g[o] * rsqrtf(var + 1e-5f);
    g_scale[o] = sc;
    g_shift[o] = be[o] - mu * sc;
    g_colsum[o] = 0.f;
    g_colsq[o] = 0.f;
}

extern "C" void kernel_launch(void* const* d_in, const int* in_sizes, int n_in,
                              void* d_out, int out_size) {
    const float* x   = (const float*)d_in[0];
    const void*  ei  = d_in[1];
    const float* W1  = (const float*)d_in[2];
    const float* a1s = (const float*)d_in[3];
    const float* a1d = (const float*)d_in[4];
    const float* b1  = (const float*)d_in[5];
    const float* g1  = (const float*)d_in[6];
    const float* be1 = (const float*)d_in[7];
    const float* W2  = (const float*)d_in[8];
    const float* a2s = (const float*)d_in[9];
    const float* a2d = (const float*)d_in[10];
    const float* b2  = (const float*)d_in[11];
    const float* g2  = (const float*)d_in[12];
    const float* be2 = (const float*)d_in[13];
    const float* W3  = (const float*)d_in[14];
    const float* a3s = (const float*)d_in[15];
    const float* a3d = (const float*)d_in[16];
    const float* b3  = (const float*)d_in[17];
    const float* g3  = (const float*)d_in[18];
    const float* be3 = (const float*)d_in[19];
    const float* W4  = (const float*)d_in[20];
    const float* a4s = (const float*)d_in[21];
    const float* a4d = (const float*)d_in[22];
    const float* b4  = (const float*)d_in[23];

    int n  = in_sizes[0] / FEAT;     // 50000
    int E  = in_sizes[1] / 2;        // 800000
    int ET = E + n;

    float *hbuf, *ybuf;
    cudaGetSymbolAddress((void**)&hbuf, g_h);
    cudaGetSymbolAddress((void**)&ybuf, g_y);

    float invn = 1.0f / (float)n;
    const int AGG_BLOCKS = 1184;

    // ---- CSR build + w4 precompute ----
    start_kernel<<<(n + 255) / 256, 256>>>(ei, n);
    w4_kernel<<<1, HID>>>(W4, a4s, a4d);
    convert_kernel<<<(ET + 255) / 256, 256>>>(ei, E, ET);
    scan_kernel<<<1, 1024>>>(n);
    scatter_kernel<<<(ET + 255) / 256, 256>>>(ei, E, ET);

    // ---- Layer 1: 128 -> 64 ----
    gemm_kernel<FEAT, HID><<<(n + 127) / 128, 256>>>(x, W1, 0, a1s, a1d, hbuf, n);
    agg_kernel<HID, 0><<<AGG_BLOCKS, 256>>>(hbuf, b1, ybuf, n);
    bnfin_kernel<<<1, HID>>>(g1, be1, HID, invn);

    // ---- Layer 2: 64 -> 64 ----
    gemm_kernel<HID, HID><<<(n + 127) / 128, 256>>>(ybuf, W2, 1, a2s, a2d, hbuf, n);
    agg_kernel<HID, 0><<<AGG_BLOCKS, 256>>>(hbuf, b2, ybuf, n);
    bnfin_kernel<<<1, HID>>>(g2, be2, HID, invn);

    // ---- Layer 3: 64 -> 64 ----
    gemm_kernel<HID, HID><<<(n + 127) / 128, 256>>>(ybuf, W3, 1, a3s, a3d, hbuf, n);
    agg_kernel<HID, 0><<<AGG_BLOCKS, 256>>>(hbuf, b3, ybuf, n);
    bnfin_kernel<<<1, HID>>>(g3, be3, HID, invn);

    // ---- Layer 4 (commuted): alpha from BN3(y).w4, aggregate y, then GEMM+final ----
    alpha4_kernel<<<(n * 32 + 255) / 256, 256>>>(ybuf, n);
    agg_kernel<HID, 3><<<AGG_BLOCKS, 256>>>(ybuf, nullptr, hbuf, n);
    gemm_final_kernel<<<(n + 63) / 64, 256>>>(hbuf, W4, b4, x, (float*)d_out, n, out_size);
}

// round 12
// speedup vs baseline: 1.9825x; 1.2121x over previous
#include <cuda_runtime.h>
#include <math.h>

#define FEAT 128
#define HID  64
#define NMAX 50048
#define EMAX 1048576
#define SCH  512                        // scan chunk (elements per block)

// ---------------- scratch (static __device__) ----------------
__device__ float g_h[NMAX * HID];       // post-GEMM features h (L1-3) / aggregated u (L4)
__device__ float g_y[NMAX * HID];       // post-aggregation features
__device__ float g_as[NMAX];            // alpha_src per node
__device__ float g_ad[NMAX];            // alpha_dst per node
__device__ int   g_csrc[EMAX];          // CSR: src indices grouped by dst
__device__ int   g_cnt[NMAX];           // in-degree histogram
__device__ int   g_rowptr[NMAX + 1];    // CSR row pointers
__device__ int   g_cursor[NMAX];        // scatter cursors
__device__ int   g_bsum[256];           // scan block sums
__device__ float g_colsum[FEAT];        // BN stats (current layer)
__device__ float g_colsq[FEAT];
__device__ float g_scale[FEAT];         // BN affine for next GEMM
__device__ float g_shift[FEAT];
__device__ float g_w4s[HID];            // W4^T @ a4s
__device__ float g_w4d[HID];            // W4^T @ a4d
__device__ int   g_is64;

// ---------------- startup: zero histogram + stats, detect index dtype ----------------
__global__ void start_kernel(const void* ei, int n) {
    int i = blockIdx.x * blockDim.x + threadIdx.x;
    if (i < n) g_cnt[i] = 0;
    if (i < FEAT) { g_colsum[i] = 0.f; g_colsq[i] = 0.f; }
    if (blockIdx.x == 0 && threadIdx.x < 32) {
        const long long* p = (const long long*)ei;
        int bad = 0;
        for (int k = threadIdx.x; k < 64; k += 32) {
            long long v = p[k];
            if (v < 0 || v >= (1LL << 31)) bad = 1;
        }
        bad = __any_sync(0xffffffffu, bad);
        if (threadIdx.x == 0) g_is64 = bad ? 0 : 1;
    }
}

// ---------------- w4 = W4^T @ a4s / a4d ----------------
__global__ void w4_kernel(const float* __restrict__ W4, const float* __restrict__ a4s,
                          const float* __restrict__ a4d) {
    int k = threadIdx.x;                 // 0..63
    float s = 0.f, d = 0.f;
#pragma unroll 8
    for (int o = 0; o < FEAT; o++) {
        float w = W4[o * HID + k];
        s += w * a4s[o];
        d += w * a4d[o];
    }
    g_w4s[k] = s;
    g_w4d[k] = d;
}

// ---------------- degree histogram ----------------
__global__ void convert_kernel(const void* ei, int E, int ET) {
    int i = blockIdx.x * blockDim.x + threadIdx.x;
    if (i >= ET) return;
    int d;
    if (i < E) {
        d = g_is64 ? (int)((const long long*)ei)[E + i] : ((const int*)ei)[E + i];
    } else {
        d = i - E;
    }
    atomicAdd(&g_cnt[d], 1);
}

// ---------------- 3-phase parallel scan ----------------
// phase 1: per-block reduce of SCH counts
__global__ void scan1_kernel(int n) {
    __shared__ int s[SCH];
    int t = threadIdx.x;
    int i = blockIdx.x * SCH + t;
    s[t] = (i < n) ? g_cnt[i] : 0;
    __syncthreads();
#pragma unroll
    for (int off = SCH / 2; off; off >>= 1) {
        if (t < off) s[t] += s[t + off];
        __syncthreads();
    }
    if (t == 0) g_bsum[blockIdx.x] = s[0];
}

// phase 2: exclusive scan of block sums (1 block, nb <= 256); writes rowptr[n]
__global__ void scan2_kernel(int nb, int n) {
    __shared__ int s[256];
    int t = threadIdx.x;
    int v = (t < nb) ? g_bsum[t] : 0;
    s[t] = v;
    __syncthreads();
#pragma unroll
    for (int off = 1; off < 256; off <<= 1) {
        int u = (t >= off) ? s[t - off] : 0;
        __syncthreads();
        s[t] += u;
        __syncthreads();
    }
    if (t < nb) g_bsum[t] = s[t] - v;          // exclusive
    if (t == 0) g_rowptr[n] = s[255];          // total (zeros beyond nb)
}

// phase 3: intra-block exclusive scan + block offset -> rowptr/cursor
__global__ void scan3_kernel(int n) {
    __shared__ int s[SCH];
    int t = threadIdx.x;
    int i = blockIdx.x * SCH + t;
    int v = (i < n) ? g_cnt[i] : 0;
    s[t] = v;
    __syncthreads();
#pragma unroll
    for (int off = 1; off < SCH; off <<= 1) {
        int u = (t >= off) ? s[t - off] : 0;
        __syncthreads();
        s[t] += u;
        __syncthreads();
    }
    if (i < n) {
        int ex = g_bsum[blockIdx.x] + s[t] - v;
        g_rowptr[i] = ex;
        g_cursor[i] = ex;
    }
}

// ---------------- scatter edges into CSR ----------------
__global__ void scatter_kernel(const void* ei, int E, int ET) {
    int i = blockIdx.x * blockDim.x + threadIdx.x;
    if (i >= ET) return;
    int s, d;
    if (i < E) {
        if (g_is64) {
            const long long* p = (const long long*)ei;
            s = (int)p[i]; d = (int)p[E + i];
        } else {
            const int* p = (const int*)ei;
            s = p[i]; d = p[E + i];
        }
    } else {
        s = i - E; d = i - E;
    }
    int pos = atomicAdd(&g_cursor[d], 1);
    g_csrc[pos] = s;
}

// ---------------- GEMM: h = affine(x) @ W^T  (layers 1-3, untouched) ----------------
template <int IN, int OUT>
__global__ void gemm_kernel(const float* __restrict__ x, const float* __restrict__ W,
                            int useAffine,
                            const float* __restrict__ avs, const float* __restrict__ avd,
                            float* __restrict__ h, int n) {
    const int M = 8192 / OUT;
    const int OC = OUT / 8;
    const int KC = 32;
    const int SXS = M + 4;
    const int SWS = OUT + 4;

    __shared__ __align__(16) float sSc[IN];
    __shared__ __align__(16) float sSh[IN];
    __shared__ __align__(16) float sX[KC * SXS];
    __shared__ __align__(16) float sW[KC * SWS];

    int tid = threadIdx.x;
    int og = tid % OC;
    int rg = tid / OC;
    int r0 = blockIdx.x * M;

    if (useAffine) {
        for (int o = tid; o < IN; o += 256) { sSc[o] = g_scale[o]; sSh[o] = g_shift[o]; }
        __syncthreads();
    }

    float acc[4][8];
#pragma unroll
    for (int i = 0; i < 4; i++)
#pragma unroll
        for (int j = 0; j < 8; j++) acc[i][j] = 0.f;

    for (int kc = 0; kc < IN; kc += KC) {
        for (int idx = tid; idx < M * (KC / 4); idx += 256) {
            int r = idx >> 3, q = idx & 7;
            int k = q * 4;
            int row = r0 + r;
            float4 v = (row < n) ? *(const float4*)&x[row * IN + kc + k]
                                 : make_float4(0.f, 0.f, 0.f, 0.f);
            if (useAffine) {
                v.x = v.x * sSc[kc + k] + sSh[kc + k];
                v.y = v.y * sSc[kc + k + 1] + sSh[kc + k + 1];
                v.z = v.z * sSc[kc + k + 2] + sSh[kc + k + 2];
                v.w = v.w * sSc[kc + k + 3] + sSh[kc + k + 3];
            }
            sX[(k + 0) * SXS + r] = v.x;
            sX[(k + 1) * SXS + r] = v.y;
            sX[(k + 2) * SXS + r] = v.z;
            sX[(k + 3) * SXS + r] = v.w;
        }
        for (int idx = tid; idx < OUT * (KC / 4); idx += 256) {
            int o = idx >> 3, q = idx & 7;
            int k = q * 4;
            float4 w = *(const float4*)&W[o * IN + kc + k];
            sW[(k + 0) * SWS + o] = w.x;
            sW[(k + 1) * SWS + o] = w.y;
            sW[(k + 2) * SWS + o] = w.z;
            sW[(k + 3) * SWS + o] = w.w;
        }
        __syncthreads();

#pragma unroll
        for (int k = 0; k < KC; k++) {
            float4 a  = *(const float4*)&sX[k * SXS + rg * 4];
            float4 b0 = *(const float4*)&sW[k * SWS + og * 8];
            float4 b1 = *(const float4*)&sW[k * SWS + og * 8 + 4];
            float av[4] = {a.x, a.y, a.z, a.w};
            float bv[8] = {b0.x, b0.y, b0.z, b0.w, b1.x, b1.y, b1.z, b1.w};
#pragma unroll
            for (int i = 0; i < 4; i++)
#pragma unroll
                for (int j = 0; j < 8; j++)
                    acc[i][j] += av[i] * bv[j];
        }
        __syncthreads();
    }

    float avsr[8], avdr[8];
#pragma unroll
    for (int j = 0; j < 8; j++) {
        avsr[j] = __ldg(&avs[og * 8 + j]);
        avdr[j] = __ldg(&avd[og * 8 + j]);
    }

    float* sP = sX;
    float* sQ = sX + M * OC;
#pragma unroll
    for (int i = 0; i < 4; i++) {
        int rl = rg * 4 + i;
        int row = r0 + rl;
        float ps = 0.f, pd = 0.f;
#pragma unroll
        for (int j = 0; j < 8; j++) {
            ps += acc[i][j] * avsr[j];
            pd += acc[i][j] * avdr[j];
        }
        sP[rl * OC + og] = ps;
        sQ[rl * OC + og] = pd;
        if (row < n) {
            float4 v0 = make_float4(acc[i][0], acc[i][1], acc[i][2], acc[i][3]);
            float4 v1 = make_float4(acc[i][4], acc[i][5], acc[i][6], acc[i][7]);
            *(float4*)&h[row * OUT + og * 8] = v0;
            *(float4*)&h[row * OUT + og * 8 + 4] = v1;
        }
    }
    __syncthreads();
    if (tid < M) {
        int row = r0 + tid;
        if (row < n) {
            float as = 0.f, ad = 0.f;
#pragma unroll
            for (int t = 0; t < OC; t++) {
                as += sP[tid * OC + t];
                ad += sQ[tid * OC + t];
            }
            g_as[row] = as;
            g_ad[row] = ad;
        }
    }
}

// ---------------- final GEMM: x_hat = relu(affine(u) @ W4^T + b4); fused output ------
__global__ void gemm_final_kernel(const float* __restrict__ u, const float* __restrict__ W,
                                  const float* __restrict__ b4, const float* __restrict__ x,
                                  float* __restrict__ out, int n, int out_size) {
    const int IN = HID, OUT = FEAT;
    const int M = 8192 / OUT;          // 64
    const int OC = OUT / 8;            // 16
    const int KC = 32;
    const int SXS = M + 4;
    const int SWS = OUT + 4;

    __shared__ __align__(16) float sSc[IN];
    __shared__ __align__(16) float sSh[IN];
    __shared__ __align__(16) float sX[KC * SXS];
    __shared__ __align__(16) float sW[KC * SWS];

    int tid = threadIdx.x;
    int og = tid % OC;
    int rg = tid / OC;
    int r0 = blockIdx.x * M;

    for (int o = tid; o < IN; o += 256) { sSc[o] = g_scale[o]; sSh[o] = g_shift[o]; }
    __syncthreads();

    float acc[4][8];
#pragma unroll
    for (int i = 0; i < 4; i++)
#pragma unroll
        for (int j = 0; j < 8; j++) acc[i][j] = 0.f;

    for (int kc = 0; kc < IN; kc += KC) {
        for (int idx = tid; idx < M * (KC / 4); idx += 256) {
            int r = idx >> 3, q = idx & 7;
            int k = q * 4;
            int row = r0 + r;
            float4 v = (row < n) ? *(const float4*)&u[row * IN + kc + k]
                                 : make_float4(0.f, 0.f, 0.f, 0.f);
            v.x = v.x * sSc[kc + k] + sSh[kc + k];
            v.y = v.y * sSc[kc + k + 1] + sSh[kc + k + 1];
            v.z = v.z * sSc[kc + k + 2] + sSh[kc + k + 2];
            v.w = v.w * sSc[kc + k + 3] + sSh[kc + k + 3];
            sX[(k + 0) * SXS + r] = v.x;
            sX[(k + 1) * SXS + r] = v.y;
            sX[(k + 2) * SXS + r] = v.z;
            sX[(k + 3) * SXS + r] = v.w;
        }
        for (int idx = tid; idx < OUT * (KC / 4); idx += 256) {
            int o = idx >> 3, q = idx & 7;
            int k = q * 4;
            float4 w = *(const float4*)&W[o * IN + kc + k];
            sW[(k + 0) * SWS + o] = w.x;
            sW[(k + 1) * SWS + o] = w.y;
            sW[(k + 2) * SWS + o] = w.z;
            sW[(k + 3) * SWS + o] = w.w;
        }
        __syncthreads();

#pragma unroll
        for (int k = 0; k < KC; k++) {
            float4 a  = *(const float4*)&sX[k * SXS + rg * 4];
            float4 b0 = *(const float4*)&sW[k * SWS + og * 8];
            float4 b1 = *(const float4*)&sW[k * SWS + og * 8 + 4];
            float av[4] = {a.x, a.y, a.z, a.w};
            float bv[8] = {b0.x, b0.y, b0.z, b0.w, b1.x, b1.y, b1.z, b1.w};
#pragma unroll
            for (int i = 0; i < 4; i++)
#pragma unroll
                for (int j = 0; j < 8; j++)
                    acc[i][j] += av[i] * bv[j];
        }
        __syncthreads();
    }

    float4 ba = *(const float4*)&b4[og * 8];
    float4 bb = *(const float4*)&b4[og * 8 + 4];
    float bias[8] = {ba.x, ba.y, ba.z, ba.w, bb.x, bb.y, bb.z, bb.w};
    int total = n * OUT;
    int full = (out_size >= 2 * total);

#pragma unroll
    for (int i = 0; i < 4; i++) {
        int row = r0 + rg * 4 + i;
        if (row < n) {
            float v[8];
#pragma unroll
            for (int j = 0; j < 8; j++) {
                v[j] = acc[i][j] + bias[j];
                v[j] = (v[j] > 0.f) ? v[j] : 0.f;
            }
            float4 x0 = *(const float4*)&x[row * OUT + og * 8];
            float4 x1 = *(const float4*)&x[row * OUT + og * 8 + 4];
            *(float4*)&out[row * OUT + og * 8] =
                make_float4(fabsf(x0.x - v[0]), fabsf(x0.y - v[1]),
                            fabsf(x0.z - v[2]), fabsf(x0.w - v[3]));
            *(float4*)&out[row * OUT + og * 8 + 4] =
                make_float4(fabsf(x1.x - v[4]), fabsf(x1.y - v[5]),
                            fabsf(x1.z - v[6]), fabsf(x1.w - v[7]));
            if (full) {
                *(float4*)&out[total + row * OUT + og * 8] =
                    make_float4(v[0], v[1], v[2], v[3]);
                *(float4*)&out[total + row * OUT + og * 8 + 4] =
                    make_float4(v[4], v[5], v[6], v[7]);
            }
        }
    }
}

// ---------------- alpha for layer 4 (warp per node) ----------------
__global__ void alpha4_kernel(const float* __restrict__ y, int n) {
    int warp = (blockIdx.x * blockDim.x + threadIdx.x) >> 5;
    int lane = threadIdx.x & 31;
    if (warp >= n) return;
    float as = 0.f, ad = 0.f;
#pragma unroll
    for (int j = 0; j < 2; j++) {
        int k = j * 32 + lane;
        float v = y[warp * HID + k] * g_scale[k] + g_shift[k];
        as += v * g_w4s[k];
        ad += v * g_w4d[k];
    }
#pragma unroll
    for (int off = 16; off; off >>= 1) {
        as += __shfl_down_sync(0xffffffffu, as, off);
        ad += __shfl_down_sync(0xffffffffu, ad, off);
    }
    if (lane == 0) { g_as[warp] = as; g_ad[warp] = ad; }
}

// ---------------- fused CSR aggregation ----------------
// MODE 0: y = relu(agg + b) + BN stats.  MODE 3: raw aggregate u.
template <int OUT, int MODE>
__global__ void agg_kernel(const float* __restrict__ h, const float* __restrict__ b,
                           float* __restrict__ yout, int n) {
    const int TPN = OUT / 4;
    const int NPB = 256 / TPN;
    int c4 = threadIdx.x % TPN;
    int nl = threadIdx.x / TPN;

    float4 bias = (MODE == 0) ? *(const float4*)&b[c4 * 4] : make_float4(0.f, 0.f, 0.f, 0.f);

    float st_s[4] = {0.f, 0.f, 0.f, 0.f};
    float st_q[4] = {0.f, 0.f, 0.f, 0.f};

    for (int node = blockIdx.x * NPB + nl; node < n; node += gridDim.x * NPB) {
        int p   = g_rowptr[node];
        int end = g_rowptr[node + 1];
        float adn = g_ad[node];

        float a0 = 0.f, a1 = 0.f, a2 = 0.f, a3 = 0.f;
        float b0 = 0.f, b1_ = 0.f, b2 = 0.f, b3 = 0.f;
        float lsum = 0.f;

        for (; p + 2 <= end; p += 2) {
            int s0 = g_csrc[p];
            int s1 = g_csrc[p + 1];
            float e0 = g_as[s0] + adn;
            float e1 = g_as[s1] + adn;
            float4 h0 = *(const float4*)&h[s0 * OUT + c4 * 4];
            float4 h1 = *(const float4*)&h[s1 * OUT + c4 * 4];
            e0 = (e0 >= 0.f) ? e0 : 0.2f * e0;
            e1 = (e1 >= 0.f) ? e1 : 0.2f * e1;
            float t0 = __expf(e0);
            float t1 = __expf(e1);
            lsum += t0 + t1;
            a0 += t0 * h0.x; a1 += t0 * h0.y; a2 += t0 * h0.z; a3 += t0 * h0.w;
            b0 += t1 * h1.x; b1_ += t1 * h1.y; b2 += t1 * h1.z; b3 += t1 * h1.w;
        }
        if (p < end) {
            int s = g_csrc[p];
            float e = g_as[s] + adn;
            e = (e >= 0.f) ? e : 0.2f * e;
            float t = __expf(e);
            lsum += t;
            float4 hv = *(const float4*)&h[s * OUT + c4 * 4];
            a0 += t * hv.x; a1 += t * hv.y; a2 += t * hv.z; a3 += t * hv.w;
        }
        a0 += b0; a1 += b1_; a2 += b2; a3 += b3;

        float inv = __fdividef(1.f, lsum + 1e-16f);

        if (MODE == 0) {
            float v0 = a0 * inv + bias.x; v0 = (v0 > 0.f) ? v0 : 0.f;
            float v1 = a1 * inv + bias.y; v1 = (v1 > 0.f) ? v1 : 0.f;
            float v2 = a2 * inv + bias.z; v2 = (v2 > 0.f) ? v2 : 0.f;
            float v3 = a3 * inv + bias.w; v3 = (v3 > 0.f) ? v3 : 0.f;
            *(float4*)&yout[node * OUT + c4 * 4] = make_float4(v0, v1, v2, v3);
            st_s[0] += v0; st_q[0] += v0 * v0;
            st_s[1] += v1; st_q[1] += v1 * v1;
            st_s[2] += v2; st_q[2] += v2 * v2;
            st_s[3] += v3; st_q[3] += v3 * v3;
        } else {
            *(float4*)&yout[node * OUT + c4 * 4] =
                make_float4(a0 * inv, a1 * inv, a2 * inv, a3 * inv);
        }
    }

    if (MODE == 0) {
        __shared__ float sS[256 * 4];
        __shared__ float sQ[256 * 4];
#pragma unroll
        for (int c = 0; c < 4; c++) {
            sS[threadIdx.x * 4 + c] = st_s[c];
            sQ[threadIdx.x * 4 + c] = st_q[c];
        }
        __syncthreads();
        if (nl == 0) {
#pragma unroll 4
            for (int t = 1; t < NPB; t++) {
#pragma unroll
                for (int c = 0; c < 4; c++) {
                    st_s[c] += sS[(t * TPN + c4) * 4 + c];
                    st_q[c] += sQ[(t * TPN + c4) * 4 + c];
                }
            }
#pragma unroll
            for (int c = 0; c < 4; c++) {
                atomicAdd(&g_colsum[c4 * 4 + c], st_s[c]);
                atomicAdd(&g_colsq[c4 * 4 + c], st_q[c]);
            }
        }
    }
}

// ---------------- BN finalize ----------------
__global__ void bnfin_kernel(const float* __restrict__ g, const float* __restrict__ be,
                             int OUT, float invn) {
    int o = threadIdx.x;
    if (o >= OUT) return;
    float mu = g_colsum[o] * invn;
    float var = g_colsq[o] * invn - mu * mu;
    float sc = g[o] * rsqrtf(var + 1e-5f);
    g_scale[o] = sc;
    g_shift[o] = be[o] - mu * sc;
    g_colsum[o] = 0.f;
    g_colsq[o] = 0.f;
}

extern "C" void kernel_launch(void* const* d_in, const int* in_sizes, int n_in,
                              void* d_out, int out_size) {
    const float* x   = (const float*)d_in[0];
    const void*  ei  = d_in[1];
    const float* W1  = (const float*)d_in[2];
    const float* a1s = (const float*)d_in[3];
    const float* a1d = (const float*)d_in[4];
    const float* b1  = (const float*)d_in[5];
    const float* g1  = (const float*)d_in[6];
    const float* be1 = (const float*)d_in[7];
    const float* W2  = (const float*)d_in[8];
    const float* a2s = (const float*)d_in[9];
    const float* a2d = (const float*)d_in[10];
    const float* b2  = (const float*)d_in[11];
    const float* g2  = (const float*)d_in[12];
    const float* be2 = (const float*)d_in[13];
    const float* W3  = (const float*)d_in[14];
    const float* a3s = (const float*)d_in[15];
    const float* a3d = (const float*)d_in[16];
    const float* b3  = (const float*)d_in[17];
    const float* g3  = (const float*)d_in[18];
    const float* be3 = (const float*)d_in[19];
    const float* W4  = (const float*)d_in[20];
    const float* a4s = (const float*)d_in[21];
    const float* a4d = (const float*)d_in[22];
    const float* b4  = (const float*)d_in[23];

    int n  = in_sizes[0] / FEAT;     // 50000
    int E  = in_sizes[1] / 2;        // 800000
    int ET = E + n;
    int nb = (n + SCH - 1) / SCH;    // scan blocks (98)

    float *hbuf, *ybuf;
    cudaGetSymbolAddress((void**)&hbuf, g_h);
    cudaGetSymbolAddress((void**)&ybuf, g_y);

    float invn = 1.0f / (float)n;
    const int AGG_BLOCKS = 1184;

    // ---- CSR build + w4 precompute ----
    start_kernel<<<(n + 255) / 256, 256>>>(ei, n);
    w4_kernel<<<1, HID>>>(W4, a4s, a4d);
    convert_kernel<<<(ET + 255) / 256, 256>>>(ei, E, ET);
    scan1_kernel<<<nb, SCH>>>(n);
    scan2_kernel<<<1, 256>>>(nb, n);
    scan3_kernel<<<nb, SCH>>>(n);
    scatter_kernel<<<(ET + 255) / 256, 256>>>(ei, E, ET);

    // ---- Layer 1: 128 -> 64 ----
    gemm_kernel<FEAT, HID><<<(n + 127) / 128, 256>>>(x, W1, 0, a1s, a1d, hbuf, n);
    agg_kernel<HID, 0><<<AGG_BLOCKS, 256>>>(hbuf, b1, ybuf, n);
    bnfin_kernel<<<1, HID>>>(g1, be1, HID, invn);

    // ---- Layer 2: 64 -> 64 ----
    gemm_kernel<HID, HID><<<(n + 127) / 128, 256>>>(ybuf, W2, 1, a2s, a2d, hbuf, n);
    agg_kernel<HID, 0><<<AGG_BLOCKS, 256>>>(hbuf, b2, ybuf, n);
    bnfin_kernel<<<1, HID>>>(g2, be2, HID, invn);

    // ---- Layer 3: 64 -> 64 ----
    gemm_kernel<HID, HID><<<(n + 127) / 128, 256>>>(ybuf, W3, 1, a3s, a3d, hbuf, n);
    agg_kernel<HID, 0><<<AGG_BLOCKS, 256>>>(hbuf, b3, ybuf, n);
    bnfin_kernel<<<1, HID>>>(g3, be3, HID, invn);

    // ---- Layer 4 (commuted): alpha, aggregate, GEMM+final ----
    alpha4_kernel<<<(n * 32 + 255) / 256, 256>>>(ybuf, n);
    agg_kernel<HID, 3><<<AGG_BLOCKS, 256>>>(ybuf, nullptr, hbuf, n);
    gemm_final_kernel<<<(n + 63) / 64, 256>>>(hbuf, W4, b4, x, (float*)d_out, n, out_size);
}

// round 14
// speedup vs baseline: 1.9861x; 1.0018x over previous
#include <cuda_runtime.h>
#include <math.h>

#define FEAT 128
#define HID  64
#define NMAX 50048
#define EMAX 1048576
#define SCH  512                        // scan chunk (elements per block)

// ---------------- scratch (static __device__) ----------------
__device__ float g_h[NMAX * HID];       // post-GEMM features h (L1-3) / unused L4
__device__ float g_u[NMAX * HID];       // layer-4 aggregated u
__device__ float g_y[NMAX * HID];       // post-aggregation features
__device__ float g_as[NMAX];            // alpha_src per node
__device__ float g_ad[NMAX];            // alpha_dst per node
__device__ int   g_csrc[EMAX];          // CSR: src indices grouped by dst
__device__ int   g_cnt[NMAX];           // in-degree histogram (invariant: zero at entry)
__device__ int   g_rowptr[NMAX + 1];    // CSR row pointers
__device__ int   g_cursor[NMAX];        // scatter cursors
__device__ int   g_bsum[256];           // scan block sums
__device__ float g_colsum[FEAT];        // BN stats (invariant: zero at entry; reset by fused bnfin)
__device__ float g_colsq[FEAT];
__device__ float g_scale[FEAT];         // BN affine for next GEMM
__device__ float g_shift[FEAT];
__device__ float g_w4s[HID];            // W4^T @ a4s
__device__ float g_w4d[HID];            // W4^T @ a4d
__device__ int   g_done;                // last-block counter (invariant: zero at entry)
__device__ int   g_is64;

// ---------------- startup: dtype probe (warp 0) + w4 matvec (all 64 threads) --------
__global__ void start_kernel(const void* ei, const float* __restrict__ W4,
                             const float* __restrict__ a4s, const float* __restrict__ a4d) {
    int t = threadIdx.x;
    if (t < 32) {
        const long long* p = (const long long*)ei;
        int bad = 0;
        for (int k = t; k < 64; k += 32) {
            long long v = p[k];
            if (v < 0 || v >= (1LL << 31)) bad = 1;
        }
        bad = __any_sync(0xffffffffu, bad);
        if (t == 0) g_is64 = bad ? 0 : 1;
    }
    // w4 = W4^T @ a4s / a4d
    float s = 0.f, d = 0.f;
#pragma unroll 8
    for (int o = 0; o < FEAT; o++) {
        float w = W4[o * HID + t];
        s += w * a4s[o];
        d += w * a4d[o];
    }
    g_w4s[t] = s;
    g_w4d[t] = d;
}

// ---------------- degree histogram ----------------
__global__ void convert_kernel(const void* ei, int E, int ET) {
    int i = blockIdx.x * blockDim.x + threadIdx.x;
    if (i >= ET) return;
    int d;
    if (i < E) {
        d = g_is64 ? (int)((const long long*)ei)[E + i] : ((const int*)ei)[E + i];
    } else {
        d = i - E;
    }
    atomicAdd(&g_cnt[d], 1);
}

// ---------------- 3-phase parallel scan ----------------
__global__ void scan1_kernel(int n) {
    __shared__ int s[SCH];
    int t = threadIdx.x;
    int i = blockIdx.x * SCH + t;
    s[t] = (i < n) ? g_cnt[i] : 0;
    __syncthreads();
#pragma unroll
    for (int off = SCH / 2; off; off >>= 1) {
        if (t < off) s[t] += s[t + off];
        __syncthreads();
    }
    if (t == 0) g_bsum[blockIdx.x] = s[0];
}

__global__ void scan2_kernel(int nb, int n) {
    __shared__ int s[256];
    int t = threadIdx.x;
    int v = (t < nb) ? g_bsum[t] : 0;
    s[t] = v;
    __syncthreads();
#pragma unroll
    for (int off = 1; off < 256; off <<= 1) {
        int u = (t >= off) ? s[t - off] : 0;
        __syncthreads();
        s[t] += u;
        __syncthreads();
    }
    if (t < nb) g_bsum[t] = s[t] - v;          // exclusive
    if (t == 0) g_rowptr[n] = s[255];
}

// phase 3: intra-block exclusive scan + block offset; re-zeroes g_cnt (replay invariant)
__global__ void scan3_kernel(int n) {
    __shared__ int s[SCH];
    int t = threadIdx.x;
    int i = blockIdx.x * SCH + t;
    int v = (i < n) ? g_cnt[i] : 0;
    s[t] = v;
    __syncthreads();
#pragma unroll
    for (int off = 1; off < SCH; off <<= 1) {
        int u = (t >= off) ? s[t - off] : 0;
        __syncthreads();
        s[t] += u;
        __syncthreads();
    }
    if (i < n) {
        int ex = g_bsum[blockIdx.x] + s[t] - v;
        g_rowptr[i] = ex;
        g_cursor[i] = ex;
        g_cnt[i] = 0;                          // ready for next replay
    }
}

// ---------------- scatter edges into CSR ----------------
__global__ void scatter_kernel(const void* ei, int E, int ET) {
    int i = blockIdx.x * blockDim.x + threadIdx.x;
    if (i >= ET) return;
    int s, d;
    if (i < E) {
        if (g_is64) {
            const long long* p = (const long long*)ei;
            s = (int)p[i]; d = (int)p[E + i];
        } else {
            const int* p = (const int*)ei;
            s = p[i]; d = p[E + i];
        }
    } else {
        s = i - E; d = i - E;
    }
    int pos = atomicAdd(&g_cursor[d], 1);
    g_csrc[pos] = s;
}

// ---------------- GEMM: h = affine(x) @ W^T  (layers 1-3, round-4 structure) --------
template <int IN, int OUT>
__global__ void gemm_kernel(const float* __restrict__ x, const float* __restrict__ W,
                            int useAffine,
                            const float* __restrict__ avs, const float* __restrict__ avd,
                            float* __restrict__ h, int n) {
    const int M = 8192 / OUT;
    const int OC = OUT / 8;
    const int KC = 32;
    const int SXS = M + 4;
    const int SWS = OUT + 4;

    __shared__ __align__(16) float sSc[IN];
    __shared__ __align__(16) float sSh[IN];
    __shared__ __align__(16) float sX[KC * SXS];
    __shared__ __align__(16) float sW[KC * SWS];

    int tid = threadIdx.x;
    int og = tid % OC;
    int rg = tid / OC;
    int r0 = blockIdx.x * M;

    if (useAffine) {
        for (int o = tid; o < IN; o += 256) { sSc[o] = g_scale[o]; sSh[o] = g_shift[o]; }
        __syncthreads();
    }

    float acc[4][8];
#pragma unroll
    for (int i = 0; i < 4; i++)
#pragma unroll
        for (int j = 0; j < 8; j++) acc[i][j] = 0.f;

    for (int kc = 0; kc < IN; kc += KC) {
        for (int idx = tid; idx < M * (KC / 4); idx += 256) {
            int r = idx >> 3, q = idx & 7;
            int k = q * 4;
            int row = r0 + r;
            float4 v = (row < n) ? *(const float4*)&x[row * IN + kc + k]
                                 : make_float4(0.f, 0.f, 0.f, 0.f);
            if (useAffine) {
                v.x = v.x * sSc[kc + k] + sSh[kc + k];
                v.y = v.y * sSc[kc + k + 1] + sSh[kc + k + 1];
                v.z = v.z * sSc[kc + k + 2] + sSh[kc + k + 2];
                v.w = v.w * sSc[kc + k + 3] + sSh[kc + k + 3];
            }
            sX[(k + 0) * SXS + r] = v.x;
            sX[(k + 1) * SXS + r] = v.y;
            sX[(k + 2) * SXS + r] = v.z;
            sX[(k + 3) * SXS + r] = v.w;
        }
        for (int idx = tid; idx < OUT * (KC / 4); idx += 256) {
            int o = idx >> 3, q = idx & 7;
            int k = q * 4;
            float4 w = *(const float4*)&W[o * IN + kc + k];
            sW[(k + 0) * SWS + o] = w.x;
            sW[(k + 1) * SWS + o] = w.y;
            sW[(k + 2) * SWS + o] = w.z;
            sW[(k + 3) * SWS + o] = w.w;
        }
        __syncthreads();

#pragma unroll
        for (int k = 0; k < KC; k++) {
            float4 a  = *(const float4*)&sX[k * SXS + rg * 4];
            float4 b0 = *(const float4*)&sW[k * SWS + og * 8];
            float4 b1 = *(const float4*)&sW[k * SWS + og * 8 + 4];
            float av[4] = {a.x, a.y, a.z, a.w};
            float bv[8] = {b0.x, b0.y, b0.z, b0.w, b1.x, b1.y, b1.z, b1.w};
#pragma unroll
            for (int i = 0; i < 4; i++)
#pragma unroll
                for (int j = 0; j < 8; j++)
                    acc[i][j] += av[i] * bv[j];
        }
        __syncthreads();
    }

    float avsr[8], avdr[8];
#pragma unroll
    for (int j = 0; j < 8; j++) {
        avsr[j] = __ldg(&avs[og * 8 + j]);
        avdr[j] = __ldg(&avd[og * 8 + j]);
    }

    float* sP = sX;
    float* sQ = sX + M * OC;
#pragma unroll
    for (int i = 0; i < 4; i++) {
        int rl = rg * 4 + i;
        int row = r0 + rl;
        float ps = 0.f, pd = 0.f;
#pragma unroll
        for (int j = 0; j < 8; j++) {
            ps += acc[i][j] * avsr[j];
            pd += acc[i][j] * avdr[j];
        }
        sP[rl * OC + og] = ps;
        sQ[rl * OC + og] = pd;
        if (row < n) {
            float4 v0 = make_float4(acc[i][0], acc[i][1], acc[i][2], acc[i][3]);
            float4 v1 = make_float4(acc[i][4], acc[i][5], acc[i][6], acc[i][7]);
            *(float4*)&h[row * OUT + og * 8] = v0;
            *(float4*)&h[row * OUT + og * 8 + 4] = v1;
        }
    }
    __syncthreads();
    if (tid < M) {
        int row = r0 + tid;
        if (row < n) {
            float as = 0.f, ad = 0.f;
#pragma unroll
            for (int t = 0; t < OC; t++) {
                as += sP[tid * OC + t];
                ad += sQ[tid * OC + t];
            }
            g_as[row] = as;
            g_ad[row] = ad;
        }
    }
}

// ---------------- final GEMM: x_hat = relu(affine(u) @ W4^T + b4); fused output ------
__global__ void gemm_final_kernel(const float* __restrict__ u, const float* __restrict__ W,
                                  const float* __restrict__ b4, const float* __restrict__ x,
                                  float* __restrict__ out, int n, int out_size) {
    const int IN = HID, OUT = FEAT;
    const int M = 8192 / OUT;          // 64
    const int OC = OUT / 8;            // 16
    const int KC = 32;
    const int SXS = M + 4;
    const int SWS = OUT + 4;

    __shared__ __align__(16) float sSc[IN];
    __shared__ __align__(16) float sSh[IN];
    __shared__ __align__(16) float sX[KC * SXS];
    __shared__ __align__(16) float sW[KC * SWS];

    int tid = threadIdx.x;
    int og = tid % OC;
    int rg = tid / OC;
    int r0 = blockIdx.x * M;

    for (int o = tid; o < IN; o += 256) { sSc[o] = g_scale[o]; sSh[o] = g_shift[o]; }
    __syncthreads();

    float acc[4][8];
#pragma unroll
    for (int i = 0; i < 4; i++)
#pragma unroll
        for (int j = 0; j < 8; j++) acc[i][j] = 0.f;

    for (int kc = 0; kc < IN; kc += KC) {
        for (int idx = tid; idx < M * (KC / 4); idx += 256) {
            int r = idx >> 3, q = idx & 7;
            int k = q * 4;
            int row = r0 + r;
            float4 v = (row < n) ? *(const float4*)&u[row * IN + kc + k]
                                 : make_float4(0.f, 0.f, 0.f, 0.f);
            v.x = v.x * sSc[kc + k] + sSh[kc + k];
            v.y = v.y * sSc[kc + k + 1] + sSh[kc + k + 1];
            v.z = v.z * sSc[kc + k + 2] + sSh[kc + k + 2];
            v.w = v.w * sSc[kc + k + 3] + sSh[kc + k + 3];
            sX[(k + 0) * SXS + r] = v.x;
            sX[(k + 1) * SXS + r] = v.y;
            sX[(k + 2) * SXS + r] = v.z;
            sX[(k + 3) * SXS + r] = v.w;
        }
        for (int idx = tid; idx < OUT * (KC / 4); idx += 256) {
            int o = idx >> 3, q = idx & 7;
            int k = q * 4;
            float4 w = *(const float4*)&W[o * IN + kc + k];
            sW[(k + 0) * SWS + o] = w.x;
            sW[(k + 1) * SWS + o] = w.y;
            sW[(k + 2) * SWS + o] = w.z;
            sW[(k + 3) * SWS + o] = w.w;
        }
        __syncthreads();

#pragma unroll
        for (int k = 0; k < KC; k++) {
            float4 a  = *(const float4*)&sX[k * SXS + rg * 4];
            float4 b0 = *(const float4*)&sW[k * SWS + og * 8];
            float4 b1 = *(const float4*)&sW[k * SWS + og * 8 + 4];
            float av[4] = {a.x, a.y, a.z, a.w};
            float bv[8] = {b0.x, b0.y, b0.z, b0.w, b1.x, b1.y, b1.z, b1.w};
#pragma unroll
            for (int i = 0; i < 4; i++)
#pragma unroll
                for (int j = 0; j < 8; j++)
                    acc[i][j] += av[i] * bv[j];
        }
        __syncthreads();
    }

    float4 ba = *(const float4*)&b4[og * 8];
    float4 bb = *(const float4*)&b4[og * 8 + 4];
    float bias[8] = {ba.x, ba.y, ba.z, ba.w, bb.x, bb.y, bb.z, bb.w};
    int total = n * OUT;
    int full = (out_size >= 2 * total);

#pragma unroll
    for (int i = 0; i < 4; i++) {
        int row = r0 + rg * 4 + i;
        if (row < n) {
            float v[8];
#pragma unroll
            for (int j = 0; j < 8; j++) {
                v[j] = acc[i][j] + bias[j];
                v[j] = (v[j] > 0.f) ? v[j] : 0.f;
            }
            float4 x0 = *(const float4*)&x[row * OUT + og * 8];
            float4 x1 = *(const float4*)&x[row * OUT + og * 8 + 4];
            *(float4*)&out[row * OUT + og * 8] =
                make_float4(fabsf(x0.x - v[0]), fabsf(x0.y - v[1]),
                            fabsf(x0.z - v[2]), fabsf(x0.w - v[3]));
            *(float4*)&out[row * OUT + og * 8 + 4] =
                make_float4(fabsf(x1.x - v[4]), fabsf(x1.y - v[5]),
                            fabsf(x1.z - v[6]), fabsf(x1.w - v[7]));
            if (full) {
                *(float4*)&out[total + row * OUT + og * 8] =
                    make_float4(v[0], v[1], v[2], v[3]);
                *(float4*)&out[total + row * OUT + og * 8 + 4] =
                    make_float4(v[4], v[5], v[6], v[7]);
            }
        }
    }
}

// ---------------- alpha for layer 4 (warp per node) ----------------
__global__ void alpha4_kernel(const float* __restrict__ y, int n) {
    int warp = (blockIdx.x * blockDim.x + threadIdx.x) >> 5;
    int lane = threadIdx.x & 31;
    if (warp >= n) return;
    float as = 0.f, ad = 0.f;
#pragma unroll
    for (int j = 0; j < 2; j++) {
        int k = j * 32 + lane;
        float v = y[warp * HID + k] * g_scale[k] + g_shift[k];
        as += v * g_w4s[k];
        ad += v * g_w4d[k];
    }
#pragma unroll
    for (int off = 16; off; off >>= 1) {
        as += __shfl_down_sync(0xffffffffu, as, off);
        ad += __shfl_down_sync(0xffffffffu, ad, off);
    }
    if (lane == 0) { g_as[warp] = as; g_ad[warp] = ad; }
}

// ---------------- fused CSR aggregation + last-block BN finalize ----------------
// y = relu(agg + b), BN stats; the LAST block to finish computes scale/shift
// (folding the former bnfin_kernel) and resets stats + counter.
__global__ void agg_bn_kernel(const float* __restrict__ h, const float* __restrict__ b,
                              const float* __restrict__ gamma, const float* __restrict__ beta,
                              float invn, float* __restrict__ yout, int n) {
    const int OUT = HID;
    const int TPN = OUT / 4;            // 16
    const int NPB = 256 / TPN;          // 16
    int c4 = threadIdx.x % TPN;
    int nl = threadIdx.x / TPN;

    float4 bias = *(const float4*)&b[c4 * 4];

    float st_s[4] = {0.f, 0.f, 0.f, 0.f};
    float st_q[4] = {0.f, 0.f, 0.f, 0.f};

    for (int node = blockIdx.x * NPB + nl; node < n; node += gridDim.x * NPB) {
        int p   = g_rowptr[node];
        int end = g_rowptr[node + 1];
        float adn = g_ad[node];

        float a0 = 0.f, a1 = 0.f, a2 = 0.f, a3 = 0.f;
        float b0 = 0.f, b1_ = 0.f, b2 = 0.f, b3 = 0.f;
        float lsum = 0.f;

        for (; p + 2 <= end; p += 2) {
            int s0 = g_csrc[p];
            int s1 = g_csrc[p + 1];
            float e0 = g_as[s0] + adn;
            float e1 = g_as[s1] + adn;
            float4 h0 = *(const float4*)&h[s0 * OUT + c4 * 4];
            float4 h1 = *(const float4*)&h[s1 * OUT + c4 * 4];
            e0 = (e0 >= 0.f) ? e0 : 0.2f * e0;
            e1 = (e1 >= 0.f) ? e1 : 0.2f * e1;
            float t0 = __expf(e0);
            float t1 = __expf(e1);
            lsum += t0 + t1;
            a0 += t0 * h0.x; a1 += t0 * h0.y; a2 += t0 * h0.z; a3 += t0 * h0.w;
            b0 += t1 * h1.x; b1_ += t1 * h1.y; b2 += t1 * h1.z; b3 += t1 * h1.w;
        }
        if (p < end) {
            int s = g_csrc[p];
            float e = g_as[s] + adn;
            e = (e >= 0.f) ? e : 0.2f * e;
            float t = __expf(e);
            lsum += t;
            float4 hv = *(const float4*)&h[s * OUT + c4 * 4];
            a0 += t * hv.x; a1 += t * hv.y; a2 += t * hv.z; a3 += t * hv.w;
        }
        a0 += b0; a1 += b1_; a2 += b2; a3 += b3;

        float inv = __fdividef(1.f, lsum + 1e-16f);
        float v0 = a0 * inv + bias.x; v0 = (v0 > 0.f) ? v0 : 0.f;
        float v1 = a1 * inv + bias.y; v1 = (v1 > 0.f) ? v1 : 0.f;
        float v2 = a2 * inv + bias.z; v2 = (v2 > 0.f) ? v2 : 0.f;
        float v3 = a3 * inv + bias.w; v3 = (v3 > 0.f) ? v3 : 0.f;
        *(float4*)&yout[node * OUT + c4 * 4] = make_float4(v0, v1, v2, v3);
        st_s[0] += v0; st_q[0] += v0 * v0;
        st_s[1] += v1; st_q[1] += v1 * v1;
        st_s[2] += v2; st_q[2] += v2 * v2;
        st_s[3] += v3; st_q[3] += v3 * v3;
    }

    __shared__ float sS[256 * 4];
    __shared__ float sQ[256 * 4];
#pragma unroll
    for (int c = 0; c < 4; c++) {
        sS[threadIdx.x * 4 + c] = st_s[c];
        sQ[threadIdx.x * 4 + c] = st_q[c];
    }
    __syncthreads();
    if (nl == 0) {
#pragma unroll 4
        for (int t = 1; t < NPB; t++) {
#pragma unroll
            for (int c = 0; c < 4; c++) {
                st_s[c] += sS[(t * TPN + c4) * 4 + c];
                st_q[c] += sQ[(t * TPN + c4) * 4 + c];
            }
        }
#pragma unroll
        for (int c = 0; c < 4; c++) {
            atomicAdd(&g_colsum[c4 * 4 + c], st_s[c]);
            atomicAdd(&g_colsq[c4 * 4 + c], st_q[c]);
        }
    }

    // ---- last-block BN finalize (replaces bnfin_kernel) ----
    __shared__ int isLast;
    __syncthreads();
    if (threadIdx.x == 0) {
        __threadfence();
        int c = atomicAdd(&g_done, 1);
        isLast = (c == (int)gridDim.x - 1) ? 1 : 0;
    }
    __syncthreads();
    if (isLast) {
        int o = threadIdx.x;
        if (o < HID) {
            float mu = g_colsum[o] * invn;
            float var = g_colsq[o] * invn - mu * mu;
            float sc = gamma[o] * rsqrtf(var + 1e-5f);
            g_scale[o] = sc;
            g_shift[o] = beta[o] - mu * sc;
            g_colsum[o] = 0.f;
            g_colsq[o] = 0.f;
        }
        if (threadIdx.x == 0) g_done = 0;
    }
}

// ---------------- layer-4 aggregation (raw aggregate u, no stats) ----------------
__global__ void agg_f32_kernel(const float* __restrict__ h, float* __restrict__ yout, int n) {
    const int OUT = HID;
    const int TPN = OUT / 4;
    const int NPB = 256 / TPN;
    int c4 = threadIdx.x % TPN;
    int nl = threadIdx.x / TPN;

    for (int node = blockIdx.x * NPB + nl; node < n; node += gridDim.x * NPB) {
        int p   = g_rowptr[node];
        int end = g_rowptr[node + 1];
        float adn = g_ad[node];

        float a0 = 0.f, a1 = 0.f, a2 = 0.f, a3 = 0.f;
        float b0 = 0.f, b1_ = 0.f, b2 = 0.f, b3 = 0.f;
        float lsum = 0.f;

        for (; p + 2 <= end; p += 2) {
            int s0 = g_csrc[p];
            int s1 = g_csrc[p + 1];
            float e0 = g_as[s0] + adn;
            float e1 = g_as[s1] + adn;
            float4 h0 = *(const float4*)&h[s0 * OUT + c4 * 4];
            float4 h1 = *(const float4*)&h[s1 * OUT + c4 * 4];
            e0 = (e0 >= 0.f) ? e0 : 0.2f * e0;
            e1 = (e1 >= 0.f) ? e1 : 0.2f * e1;
            float t0 = __expf(e0);
            float t1 = __expf(e1);
            lsum += t0 + t1;
            a0 += t0 * h0.x; a1 += t0 * h0.y; a2 += t0 * h0.z; a3 += t0 * h0.w;
            b0 += t1 * h1.x; b1_ += t1 * h1.y; b2 += t1 * h1.z; b3 += t1 * h1.w;
        }
        if (p < end) {
            int s = g_csrc[p];
            float e = g_as[s] + adn;
            e = (e >= 0.f) ? e : 0.2f * e;
            float t = __expf(e);
            lsum += t;
            float4 hv = *(const float4*)&h[s * OUT + c4 * 4];
            a0 += t * hv.x; a1 += t * hv.y; a2 += t * hv.z; a3 += t * hv.w;
        }
        a0 += b0; a1 += b1_; a2 += b2; a3 += b3;

        float inv = __fdividef(1.f, lsum + 1e-16f);
        *(float4*)&yout[node * OUT + c4 * 4] =
            make_float4(a0 * inv, a1 * inv, a2 * inv, a3 * inv);
    }
}

extern "C" void kernel_launch(void* const* d_in, const int* in_sizes, int n_in,
                              void* d_out, int out_size) {
    const float* x   = (const float*)d_in[0];
    const void*  ei  = d_in[1];
    const float* W1  = (const float*)d_in[2];
    const float* a1s = (const float*)d_in[3];
    const float* a1d = (const float*)d_in[4];
    const float* b1  = (const float*)d_in[5];
    const float* g1  = (const float*)d_in[6];
    const float* be1 = (const float*)d_in[7];
    const float* W2  = (const float*)d_in[8];
    const float* a2s = (const float*)d_in[9];
    const float* a2d = (const float*)d_in[10];
    const float* b2  = (const float*)d_in[11];
    const float* g2  = (const float*)d_in[12];
    const float* be2 = (const float*)d_in[13];
    const float* W3  = (const float*)d_in[14];
    const float* a3s = (const float*)d_in[15];
    const float* a3d = (const float*)d_in[16];
    const float* b3  = (const float*)d_in[17];
    const float* g3  = (const float*)d_in[18];
    const float* be3 = (const float*)d_in[19];
    const float* W4  = (const float*)d_in[20];
    const float* a4s = (const float*)d_in[21];
    const float* a4d = (const float*)d_in[22];
    const float* b4  = (const float*)d_in[23];

    int n  = in_sizes[0] / FEAT;     // 50000
    int E  = in_sizes[1] / 2;        // 800000
    int ET = E + n;
    int nb = (n + SCH - 1) / SCH;

    float *hbuf, *ybuf, *ubuf;
    cudaGetSymbolAddress((void**)&hbuf, g_h);
    cudaGetSymbolAddress((void**)&ybuf, g_y);
    cudaGetSymbolAddress((void**)&ubuf, g_u);

    float invn = 1.0f / (float)n;
    const int AGG_BLOCKS = 1184;

    // ---- CSR build + w4 precompute ----
    start_kernel<<<1, HID>>>(ei, W4, a4s, a4d);
    convert_kernel<<<(ET + 255) / 256, 256>>>(ei, E, ET);
    scan1_kernel<<<nb, SCH>>>(n);
    scan2_kernel<<<1, 256>>>(nb, n);
    scan3_kernel<<<nb, SCH>>>(n);
    scatter_kernel<<<(ET + 255) / 256, 256>>>(ei, E, ET);

    // ---- Layer 1: 128 -> 64 ----
    gemm_kernel<FEAT, HID><<<(n + 127) / 128, 256>>>(x, W1, 0, a1s, a1d, hbuf, n);
    agg_bn_kernel<<<AGG_BLOCKS, 256>>>(hbuf, b1, g1, be1, invn, ybuf, n);

    // ---- Layer 2: 64 -> 64 ----
    gemm_kernel<HID, HID><<<(n + 127) / 128, 256>>>(ybuf, W2, 1, a2s, a2d, hbuf, n);
    agg_bn_kernel<<<AGG_BLOCKS, 256>>>(hbuf, b2, g2, be2, invn, ybuf, n);

    // ---- Layer 3: 64 -> 64 ----
    gemm_kernel<HID, HID><<<(n + 127) / 128, 256>>>(ybuf, W3, 1, a3s, a3d, hbuf, n);
    agg_bn_kernel<<<AGG_BLOCKS, 256>>>(hbuf, b3, g3, be3, invn, ybuf, n);

    // ---- Layer 4 (commuted): alpha, aggregate y, GEMM+final ----
    alpha4_kernel<<<(n * 32 + 255) / 256, 256>>>(ybuf, n);
    agg_f32_kernel<<<AGG_BLOCKS, 256>>>(ybuf, ubuf, n);
    gemm_final_kernel<<<(n + 63) / 64, 256>>>(ubuf, W4, b4, x, (float*)d_out, n, out_size);
}

// round 15
// speedup vs baseline: 2.0649x; 1.0396x over previous
#include <cuda_runtime.h>
#include <math.h>

#define FEAT 128
#define HID  64
#define NMAX 50048
#define EMAX 1048576
#define SCH  512                        // scan chunk (elements per block)

// ---------------- scratch (static __device__) ----------------
__device__ float g_h[NMAX * HID];       // post-GEMM features h (L1-3)
__device__ float g_u[NMAX * HID];       // layer-4 aggregated u
__device__ float g_y[NMAX * HID];       // post-aggregation features
__device__ float g_as[NMAX];            // alpha_src per node
__device__ float g_ad[NMAX];            // alpha_dst per node
__device__ int   g_csrc[EMAX];          // CSR: src indices grouped by dst
__device__ int   g_cnt[NMAX];           // in-degree histogram (invariant: zero at entry)
__device__ int   g_rowptr[NMAX + 1];    // CSR row pointers
__device__ int   g_cursor[NMAX];        // scatter cursors
__device__ int   g_bsum[256];           // scan block sums
__device__ float g_colsum[FEAT];        // BN stats (invariant: zero at entry)
__device__ float g_colsq[FEAT];
__device__ float g_scale[FEAT];         // BN affine for next GEMM
__device__ float g_shift[FEAT];
__device__ float g_w4s[HID];            // W4^T @ a4s
__device__ float g_w4d[HID];            // W4^T @ a4d
__device__ int   g_done;                // last-block counter (invariant: zero at entry)
__device__ int   g_is64;

// ---------------- startup: dtype probe (warp 0) + w4 matvec (all 64 threads) --------
__global__ void start_kernel(const void* ei, const float* __restrict__ W4,
                             const float* __restrict__ a4s, const float* __restrict__ a4d) {
    int t = threadIdx.x;
    if (t < 32) {
        const long long* p = (const long long*)ei;
        int bad = 0;
        for (int k = t; k < 64; k += 32) {
            long long v = p[k];
            if (v < 0 || v >= (1LL << 31)) bad = 1;
        }
        bad = __any_sync(0xffffffffu, bad);
        if (t == 0) g_is64 = bad ? 0 : 1;
    }
    float s = 0.f, d = 0.f;
#pragma unroll 8
    for (int o = 0; o < FEAT; o++) {
        float w = W4[o * HID + t];
        s += w * a4s[o];
        d += w * a4d[o];
    }
    g_w4s[t] = s;
    g_w4d[t] = d;
}

// ---------------- degree histogram ----------------
__global__ void convert_kernel(const void* ei, int E, int ET) {
    int i = blockIdx.x * blockDim.x + threadIdx.x;
    if (i >= ET) return;
    int d;
    if (i < E) {
        d = g_is64 ? (int)((const long long*)ei)[E + i] : ((const int*)ei)[E + i];
    } else {
        d = i - E;
    }
    atomicAdd(&g_cnt[d], 1);
}

// ---------------- 3-phase parallel scan ----------------
__global__ void scan1_kernel(int n) {
    __shared__ int s[SCH];
    int t = threadIdx.x;
    int i = blockIdx.x * SCH + t;
    s[t] = (i < n) ? g_cnt[i] : 0;
    __syncthreads();
#pragma unroll
    for (int off = SCH / 2; off; off >>= 1) {
        if (t < off) s[t] += s[t + off];
        __syncthreads();
    }
    if (t == 0) g_bsum[blockIdx.x] = s[0];
}

__global__ void scan2_kernel(int nb, int n) {
    __shared__ int s[256];
    int t = threadIdx.x;
    int v = (t < nb) ? g_bsum[t] : 0;
    s[t] = v;
    __syncthreads();
#pragma unroll
    for (int off = 1; off < 256; off <<= 1) {
        int u = (t >= off) ? s[t - off] : 0;
        __syncthreads();
        s[t] += u;
        __syncthreads();
    }
    if (t < nb) g_bsum[t] = s[t] - v;          // exclusive
    if (t == 0) g_rowptr[n] = s[255];
}

// phase 3: intra-block exclusive scan + block offset; re-zeroes g_cnt (replay invariant)
__global__ void scan3_kernel(int n) {
    __shared__ int s[SCH];
    int t = threadIdx.x;
    int i = blockIdx.x * SCH + t;
    int v = (i < n) ? g_cnt[i] : 0;
    s[t] = v;
    __syncthreads();
#pragma unroll
    for (int off = 1; off < SCH; off <<= 1) {
        int u = (t >= off) ? s[t - off] : 0;
        __syncthreads();
        s[t] += u;
        __syncthreads();
    }
    if (i < n) {
        int ex = g_bsum[blockIdx.x] + s[t] - v;
        g_rowptr[i] = ex;
        g_cursor[i] = ex;
        g_cnt[i] = 0;                          // ready for next replay
    }
}

// ---------------- scatter edges into CSR ----------------
__global__ void scatter_kernel(const void* ei, int E, int ET) {
    int i = blockIdx.x * blockDim.x + threadIdx.x;
    if (i >= ET) return;
    int s, d;
    if (i < E) {
        if (g_is64) {
            const long long* p = (const long long*)ei;
            s = (int)p[i]; d = (int)p[E + i];
        } else {
            const int* p = (const int*)ei;
            s = p[i]; d = p[E + i];
        }
    } else {
        s = i - E; d = i - E;
    }
    int pos = atomicAdd(&g_cursor[d], 1);
    g_csrc[pos] = s;
}

// ---------------- GEMM: h = affine(x) @ W^T  (layers 1-3) ----------------
template <int IN, int OUT>
__global__ void gemm_kernel(const float* __restrict__ x, const float* __restrict__ W,
                            int useAffine,
                            const float* __restrict__ avs, const float* __restrict__ avd,
                            float* __restrict__ h, int n) {
    const int M = 8192 / OUT;
    const int OC = OUT / 8;
    const int KC = 32;
    const int SXS = M + 4;
    const int SWS = OUT + 4;

    __shared__ __align__(16) float sSc[IN];
    __shared__ __align__(16) float sSh[IN];
    __shared__ __align__(16) float sX[KC * SXS];
    __shared__ __align__(16) float sW[KC * SWS];

    int tid = threadIdx.x;
    int og = tid % OC;
    int rg = tid / OC;
    int r0 = blockIdx.x * M;

    if (useAffine) {
        for (int o = tid; o < IN; o += 256) { sSc[o] = g_scale[o]; sSh[o] = g_shift[o]; }
        __syncthreads();
    }

    float acc[4][8];
#pragma unroll
    for (int i = 0; i < 4; i++)
#pragma unroll
        for (int j = 0; j < 8; j++) acc[i][j] = 0.f;

    for (int kc = 0; kc < IN; kc += KC) {
        for (int idx = tid; idx < M * (KC / 4); idx += 256) {
            int r = idx >> 3, q = idx & 7;
            int k = q * 4;
            int row = r0 + r;
            float4 v = (row < n) ? *(const float4*)&x[row * IN + kc + k]
                                 : make_float4(0.f, 0.f, 0.f, 0.f);
            if (useAffine) {
                v.x = v.x * sSc[kc + k] + sSh[kc + k];
                v.y = v.y * sSc[kc + k + 1] + sSh[kc + k + 1];
                v.z = v.z * sSc[kc + k + 2] + sSh[kc + k + 2];
                v.w = v.w * sSc[kc + k + 3] + sSh[kc + k + 3];
            }
            sX[(k + 0) * SXS + r] = v.x;
            sX[(k + 1) * SXS + r] = v.y;
            sX[(k + 2) * SXS + r] = v.z;
            sX[(k + 3) * SXS + r] = v.w;
        }
        for (int idx = tid; idx < OUT * (KC / 4); idx += 256) {
            int o = idx >> 3, q = idx & 7;
            int k = q * 4;
            float4 w = *(const float4*)&W[o * IN + kc + k];
            sW[(k + 0) * SWS + o] = w.x;
            sW[(k + 1) * SWS + o] = w.y;
            sW[(k + 2) * SWS + o] = w.z;
            sW[(k + 3) * SWS + o] = w.w;
        }
        __syncthreads();

#pragma unroll
        for (int k = 0; k < KC; k++) {
            float4 a  = *(const float4*)&sX[k * SXS + rg * 4];
            float4 b0 = *(const float4*)&sW[k * SWS + og * 8];
            float4 b1 = *(const float4*)&sW[k * SWS + og * 8 + 4];
            float av[4] = {a.x, a.y, a.z, a.w};
            float bv[8] = {b0.x, b0.y, b0.z, b0.w, b1.x, b1.y, b1.z, b1.w};
#pragma unroll
            for (int i = 0; i < 4; i++)
#pragma unroll
                for (int j = 0; j < 8; j++)
                    acc[i][j] += av[i] * bv[j];
        }
        __syncthreads();
    }

    float avsr[8], avdr[8];
#pragma unroll
    for (int j = 0; j < 8; j++) {
        avsr[j] = __ldg(&avs[og * 8 + j]);
        avdr[j] = __ldg(&avd[og * 8 + j]);
    }

    float* sP = sX;
    float* sQ = sX + M * OC;
#pragma unroll
    for (int i = 0; i < 4; i++) {
        int rl = rg * 4 + i;
        int row = r0 + rl;
        float ps = 0.f, pd = 0.f;
#pragma unroll
        for (int j = 0; j < 8; j++) {
            ps += acc[i][j] * avsr[j];
            pd += acc[i][j] * avdr[j];
        }
        sP[rl * OC + og] = ps;
        sQ[rl * OC + og] = pd;
        if (row < n) {
            float4 v0 = make_float4(acc[i][0], acc[i][1], acc[i][2], acc[i][3]);
            float4 v1 = make_float4(acc[i][4], acc[i][5], acc[i][6], acc[i][7]);
            *(float4*)&h[row * OUT + og * 8] = v0;
            *(float4*)&h[row * OUT + og * 8 + 4] = v1;
        }
    }
    __syncthreads();
    if (tid < M) {
        int row = r0 + tid;
        if (row < n) {
            float as = 0.f, ad = 0.f;
#pragma unroll
            for (int t = 0; t < OC; t++) {
                as += sP[tid * OC + t];
                ad += sQ[tid * OC + t];
            }
            g_as[row] = as;
            g_ad[row] = ad;
        }
    }
}

// ---------------- final GEMM: x_hat = relu(affine(u) @ W4^T + b4); fused output ------
__global__ void gemm_final_kernel(const float* __restrict__ u, const float* __restrict__ W,
                                  const float* __restrict__ b4, const float* __restrict__ x,
                                  float* __restrict__ out, int n, int out_size) {
    const int IN = HID, OUT = FEAT;
    const int M = 8192 / OUT;          // 64
    const int OC = OUT / 8;            // 16
    const int KC = 32;
    const int SXS = M + 4;
    const int SWS = OUT + 4;

    __shared__ __align__(16) float sSc[IN];
    __shared__ __align__(16) float sSh[IN];
    __shared__ __align__(16) float sX[KC * SXS];
    __shared__ __align__(16) float sW[KC * SWS];

    int tid = threadIdx.x;
    int og = tid % OC;
    int rg = tid / OC;
    int r0 = blockIdx.x * M;

    for (int o = tid; o < IN; o += 256) { sSc[o] = g_scale[o]; sSh[o] = g_shift[o]; }
    __syncthreads();

    float acc[4][8];
#pragma unroll
    for (int i = 0; i < 4; i++)
#pragma unroll
        for (int j = 0; j < 8; j++) acc[i][j] = 0.f;

    for (int kc = 0; kc < IN; kc += KC) {
        for (int idx = tid; idx < M * (KC / 4); idx += 256) {
            int r = idx >> 3, q = idx & 7;
            int k = q * 4;
            int row = r0 + r;
            float4 v = (row < n) ? *(const float4*)&u[row * IN + kc + k]
                                 : make_float4(0.f, 0.f, 0.f, 0.f);
            v.x = v.x * sSc[kc + k] + sSh[kc + k];
            v.y = v.y * sSc[kc + k + 1] + sSh[kc + k + 1];
            v.z = v.z * sSc[kc + k + 2] + sSh[kc + k + 2];
            v.w = v.w * sSc[kc + k + 3] + sSh[kc + k + 3];
            sX[(k + 0) * SXS + r] = v.x;
            sX[(k + 1) * SXS + r] = v.y;
            sX[(k + 2) * SXS + r] = v.z;
            sX[(k + 3) * SXS + r] = v.w;
        }
        for (int idx = tid; idx < OUT * (KC / 4); idx += 256) {
            int o = idx >> 3, q = idx & 7;
            int k = q * 4;
            float4 w = *(const float4*)&W[o * IN + kc + k];
            sW[(k + 0) * SWS + o] = w.x;
            sW[(k + 1) * SWS + o] = w.y;
            sW[(k + 2) * SWS + o] = w.z;
            sW[(k + 3) * SWS + o] = w.w;
        }
        __syncthreads();

#pragma unroll
        for (int k = 0; k < KC; k++) {
            float4 a  = *(const float4*)&sX[k * SXS + rg * 4];
            float4 b0 = *(const float4*)&sW[k * SWS + og * 8];
            float4 b1 = *(const float4*)&sW[k * SWS + og * 8 + 4];
            float av[4] = {a.x, a.y, a.z, a.w};
            float bv[8] = {b0.x, b0.y, b0.z, b0.w, b1.x, b1.y, b1.z, b1.w};
#pragma unroll
            for (int i = 0; i < 4; i++)
#pragma unroll
                for (int j = 0; j < 8; j++)
                    acc[i][j] += av[i] * bv[j];
        }
        __syncthreads();
    }

    float4 ba = *(const float4*)&b4[og * 8];
    float4 bb = *(const float4*)&b4[og * 8 + 4];
    float bias[8] = {ba.x, ba.y, ba.z, ba.w, bb.x, bb.y, bb.z, bb.w};
    int total = n * OUT;
    int full = (out_size >= 2 * total);

#pragma unroll
    for (int i = 0; i < 4; i++) {
        int row = r0 + rg * 4 + i;
        if (row < n) {
            float v[8];
#pragma unroll
            for (int j = 0; j < 8; j++) {
                v[j] = acc[i][j] + bias[j];
                v[j] = (v[j] > 0.f) ? v[j] : 0.f;
            }
            float4 x0 = *(const float4*)&x[row * OUT + og * 8];
            float4 x1 = *(const float4*)&x[row * OUT + og * 8 + 4];
            *(float4*)&out[row * OUT + og * 8] =
                make_float4(fabsf(x0.x - v[0]), fabsf(x0.y - v[1]),
                            fabsf(x0.z - v[2]), fabsf(x0.w - v[3]));
            *(float4*)&out[row * OUT + og * 8 + 4] =
                make_float4(fabsf(x1.x - v[4]), fabsf(x1.y - v[5]),
                            fabsf(x1.z - v[6]), fabsf(x1.w - v[7]));
            if (full) {
                *(float4*)&out[total + row * OUT + og * 8] =
                    make_float4(v[0], v[1], v[2], v[3]);
                *(float4*)&out[total + row * OUT + og * 8 + 4] =
                    make_float4(v[4], v[5], v[6], v[7]);
            }
        }
    }
}

// ---------------- alpha for layer 4 (warp per node) ----------------
__global__ void alpha4_kernel(const float* __restrict__ y, int n) {
    int warp = (blockIdx.x * blockDim.x + threadIdx.x) >> 5;
    int lane = threadIdx.x & 31;
    if (warp >= n) return;
    float as = 0.f, ad = 0.f;
#pragma unroll
    for (int j = 0; j < 2; j++) {
        int k = j * 32 + lane;
        float v = y[warp * HID + k] * g_scale[k] + g_shift[k];
        as += v * g_w4s[k];
        ad += v * g_w4d[k];
    }
#pragma unroll
    for (int off = 16; off; off >>= 1) {
        as += __shfl_down_sync(0xffffffffu, as, off);
        ad += __shfl_down_sync(0xffffffffu, ad, off);
    }
    if (lane == 0) { g_as[warp] = as; g_ad[warp] = ad; }
}

// ---------------- fused CSR aggregation + last-block BN finalize ----------------
__global__ void agg_bn_kernel(const float* __restrict__ h, const float* __restrict__ b,
                              const float* __restrict__ gamma, const float* __restrict__ beta,
                              float invn, float* __restrict__ yout, int n) {
    const int OUT = HID;
    const int TPN = OUT / 4;            // 16
    const int NPB = 256 / TPN;          // 16
    int c4 = threadIdx.x % TPN;
    int nl = threadIdx.x / TPN;

    float4 bias = *(const float4*)&b[c4 * 4];

    float st_s[4] = {0.f, 0.f, 0.f, 0.f};
    float st_q[4] = {0.f, 0.f, 0.f, 0.f};

    for (int node = blockIdx.x * NPB + nl; node < n; node += gridDim.x * NPB) {
        int p   = g_rowptr[node];
        int end = g_rowptr[node + 1];
        float adn = g_ad[node];

        float a0 = 0.f, a1 = 0.f, a2 = 0.f, a3 = 0.f;
        float b0 = 0.f, b1_ = 0.f, b2 = 0.f, b3 = 0.f;
        float lsum = 0.f;

        for (; p + 2 <= end; p += 2) {
            int s0 = g_csrc[p];
            int s1 = g_csrc[p + 1];
            float e0 = g_as[s0] + adn;
            float e1 = g_as[s1] + adn;
            float4 h0 = *(const float4*)&h[s0 * OUT + c4 * 4];
            float4 h1 = *(const float4*)&h[s1 * OUT + c4 * 4];
            e0 = (e0 >= 0.f) ? e0 : 0.2f * e0;
            e1 = (e1 >= 0.f) ? e1 : 0.2f * e1;
            float t0 = __expf(e0);
            float t1 = __expf(e1);
            lsum += t0 + t1;
            a0 += t0 * h0.x; a1 += t0 * h0.y; a2 += t0 * h0.z; a3 += t0 * h0.w;
            b0 += t1 * h1.x; b1_ += t1 * h1.y; b2 += t1 * h1.z; b3 += t1 * h1.w;
        }
        if (p < end) {
            int s = g_csrc[p];
            float e = g_as[s] + adn;
            e = (e >= 0.f) ? e : 0.2f * e;
            float t = __expf(e);
            lsum += t;
            float4 hv = *(const float4*)&h[s * OUT + c4 * 4];
            a0 += t * hv.x; a1 += t * hv.y; a2 += t * hv.z; a3 += t * hv.w;
        }
        a0 += b0; a1 += b1_; a2 += b2; a3 += b3;

        float inv = __fdividef(1.f, lsum + 1e-16f);
        float v0 = a0 * inv + bias.x; v0 = (v0 > 0.f) ? v0 : 0.f;
        float v1 = a1 * inv + bias.y; v1 = (v1 > 0.f) ? v1 : 0.f;
        float v2 = a2 * inv + bias.z; v2 = (v2 > 0.f) ? v2 : 0.f;
        float v3 = a3 * inv + bias.w; v3 = (v3 > 0.f) ? v3 : 0.f;
        *(float4*)&yout[node * OUT + c4 * 4] = make_float4(v0, v1, v2, v3);
        st_s[0] += v0; st_q[0] += v0 * v0;
        st_s[1] += v1; st_q[1] += v1 * v1;
        st_s[2] += v2; st_q[2] += v2 * v2;
        st_s[3] += v3; st_q[3] += v3 * v3;
    }

    __shared__ float sS[256 * 4];
    __shared__ float sQ[256 * 4];
#pragma unroll
    for (int c = 0; c < 4; c++) {
        sS[threadIdx.x * 4 + c] = st_s[c];
        sQ[threadIdx.x * 4 + c] = st_q[c];
    }
    __syncthreads();
    if (nl == 0) {
#pragma unroll 4
        for (int t = 1; t < NPB; t++) {
#pragma unroll
            for (int c = 0; c < 4; c++) {
                st_s[c] += sS[(t * TPN + c4) * 4 + c];
                st_q[c] += sQ[(t * TPN + c4) * 4 + c];
            }
        }
#pragma unroll
        for (int c = 0; c < 4; c++) {
            atomicAdd(&g_colsum[c4 * 4 + c], st_s[c]);
            atomicAdd(&g_colsq[c4 * 4 + c], st_q[c]);
        }
    }

    // last-block BN finalize
    __shared__ int isLast;
    __syncthreads();
    if (threadIdx.x == 0) {
        __threadfence();
        int c = atomicAdd(&g_done, 1);
        isLast = (c == (int)gridDim.x - 1) ? 1 : 0;
    }
    __syncthreads();
    if (isLast) {
        int o = threadIdx.x;
        if (o < HID) {
            float mu = g_colsum[o] * invn;
            float var = g_colsq[o] * invn - mu * mu;
            float sc = gamma[o] * rsqrtf(var + 1e-5f);
            g_scale[o] = sc;
            g_shift[o] = beta[o] - mu * sc;
            g_colsum[o] = 0.f;
            g_colsq[o] = 0.f;
        }
        if (threadIdx.x == 0) g_done = 0;
    }
}

// ---------------- layer-4 aggregation (raw aggregate u, no stats) ----------------
__global__ void agg_f32_kernel(const float* __restrict__ h, float* __restrict__ yout, int n) {
    const int OUT = HID;
    const int TPN = OUT / 4;
    const int NPB = 256 / TPN;
    int c4 = threadIdx.x % TPN;
    int nl = threadIdx.x / TPN;

    for (int node = blockIdx.x * NPB + nl; node < n; node += gridDim.x * NPB) {
        int p   = g_rowptr[node];
        int end = g_rowptr[node + 1];
        float adn = g_ad[node];

        float a0 = 0.f, a1 = 0.f, a2 = 0.f, a3 = 0.f;
        float b0 = 0.f, b1_ = 0.f, b2 = 0.f, b3 = 0.f;
        float lsum = 0.f;

        for (; p + 2 <= end; p += 2) {
            int s0 = g_csrc[p];
            int s1 = g_csrc[p + 1];
            float e0 = g_as[s0] + adn;
            float e1 = g_as[s1] + adn;
            float4 h0 = *(const float4*)&h[s0 * OUT + c4 * 4];
            float4 h1 = *(const float4*)&h[s1 * OUT + c4 * 4];
            e0 = (e0 >= 0.f) ? e0 : 0.2f * e0;
            e1 = (e1 >= 0.f) ? e1 : 0.2f * e1;
            float t0 = __expf(e0);
            float t1 = __expf(e1);
            lsum += t0 + t1;
            a0 += t0 * h0.x; a1 += t0 * h0.y; a2 += t0 * h0.z; a3 += t0 * h0.w;
            b0 += t1 * h1.x; b1_ += t1 * h1.y; b2 += t1 * h1.z; b3 += t1 * h1.w;
        }
        if (p < end) {
            int s = g_csrc[p];
            float e = g_as[s] + adn;
            e = (e >= 0.f) ? e : 0.2f * e;
            float t = __expf(e);
            lsum += t;
            float4 hv = *(const float4*)&h[s * OUT + c4 * 4];
            a0 += t * hv.x; a1 += t * hv.y; a2 += t * hv.z; a3 += t * hv.w;
        }
        a0 += b0; a1 += b1_; a2 += b2; a3 += b3;

        float inv = __fdividef(1.f, lsum + 1e-16f);
        *(float4*)&yout[node * OUT + c4 * 4] =
            make_float4(a0 * inv, a1 * inv, a2 * inv, a3 * inv);
    }
}

extern "C" void kernel_launch(void* const* d_in, const int* in_sizes, int n_in,
                              void* d_out, int out_size) {
    const float* x   = (const float*)d_in[0];
    const void*  ei  = d_in[1];
    const float* W1  = (const float*)d_in[2];
    const float* a1s = (const float*)d_in[3];
    const float* a1d = (const float*)d_in[4];
    const float* b1  = (const float*)d_in[5];
    const float* g1  = (const float*)d_in[6];
    const float* be1 = (const float*)d_in[7];
    const float* W2  = (const float*)d_in[8];
    const float* a2s = (const float*)d_in[9];
    const float* a2d = (const float*)d_in[10];
    const float* b2  = (const float*)d_in[11];
    const float* g2  = (const float*)d_in[12];
    const float* be2 = (const float*)d_in[13];
    const float* W3  = (const float*)d_in[14];
    const float* a3s = (const float*)d_in[15];
    const float* a3d = (const float*)d_in[16];
    const float* b3  = (const float*)d_in[17];
    const float* g3  = (const float*)d_in[18];
    const float* be3 = (const float*)d_in[19];
    const float* W4  = (const float*)d_in[20];
    const float* a4s = (const float*)d_in[21];
    const float* a4d = (const float*)d_in[22];
    const float* b4  = (const float*)d_in[23];

    int n  = in_sizes[0] / FEAT;     // 50000
    int E  = in_sizes[1] / 2;        // 800000
    int ET = E + n;
    int nb = (n + SCH - 1) / SCH;

    float *hbuf, *ybuf, *ubuf;
    cudaGetSymbolAddress((void**)&hbuf, g_h);
    cudaGetSymbolAddress((void**)&ybuf, g_y);
    cudaGetSymbolAddress((void**)&ubuf, g_u);

    float invn = 1.0f / (float)n;
    const int AGG_BLOCKS = 1184;

    // Fork a side stream so the CSR build overlaps the layer-1 GEMM.
    cudaStream_t s1;
    cudaStreamCreateWithFlags(&s1, cudaStreamNonBlocking);
    cudaEvent_t e0, e1;
    cudaEventCreateWithFlags(&e0, cudaEventDisableTiming);
    cudaEventCreateWithFlags(&e1, cudaEventDisableTiming);

    // ---- common prologue (dtype probe + w4) on the origin stream ----
    start_kernel<<<1, HID>>>(ei, W4, a4s, a4d);
    cudaEventRecord(e0, 0);

    // ---- branch B (side stream): CSR build ----
    cudaStreamWaitEvent(s1, e0, 0);
    convert_kernel<<<(ET + 255) / 256, 256, 0, s1>>>(ei, E, ET);
    scan1_kernel<<<nb, SCH, 0, s1>>>(n);
    scan2_kernel<<<1, 256, 0, s1>>>(nb, n);
    scan3_kernel<<<nb, SCH, 0, s1>>>(n);
    scatter_kernel<<<(ET + 255) / 256, 256, 0, s1>>>(ei, E, ET);
    cudaEventRecord(e1, s1);

    // ---- branch A (origin stream): layer-1 GEMM (independent of CSR) ----
    gemm_kernel<FEAT, HID><<<(n + 127) / 128, 256>>>(x, W1, 0, a1s, a1d, hbuf, n);

    // ---- join: aggregation needs both branches ----
    cudaStreamWaitEvent(0, e1, 0);
    agg_bn_kernel<<<AGG_BLOCKS, 256>>>(hbuf, b1, g1, be1, invn, ybuf, n);

    // ---- Layer 2: 64 -> 64 ----
    gemm_kernel<HID, HID><<<(n + 127) / 128, 256>>>(ybuf, W2, 1, a2s, a2d, hbuf, n);
    agg_bn_kernel<<<AGG_BLOCKS, 256>>>(hbuf, b2, g2, be2, invn, ybuf, n);

    // ---- Layer 3: 64 -> 64 ----
    gemm_kernel<HID, HID><<<(n + 127) / 128, 256>>>(ybuf, W3, 1, a3s, a3d, hbuf, n);
    agg_bn_kernel<<<AGG_BLOCKS, 256>>>(hbuf, b3, g3, be3, invn, ybuf, n);

    // ---- Layer 4 (commuted): alpha, aggregate y, GEMM+final ----
    alpha4_kernel<<<(n * 32 + 255) / 256, 256>>>(ybuf, n);
    agg_f32_kernel<<<AGG_BLOCKS, 256>>>(ybuf, ubuf, n);
    gemm_final_kernel<<<(n + 63) / 64, 256>>>(ubuf, W4, b4, x, (float*)d_out, n, out_size);

    cudaEventDestroy(e0);
    cudaEventDestroy(e1);
    cudaStreamDestroy(s1);
}

// round 16
// speedup vs baseline: 2.1483x; 1.0404x over previous
#include <cuda_runtime.h>
#include <math.h>

#define FEAT 128
#define HID  64
#define NMAX 50048
#define EMAX 1048576
#define SCH  512                        // scan chunk (elements per block)

// ---------------- scratch (static __device__) ----------------
__device__ float g_h[NMAX * HID];       // post-GEMM features h (L1-3)
__device__ float g_u[NMAX * HID];       // layer-4 aggregated u
__device__ float g_y[NMAX * HID];       // post-aggregation features
__device__ float g_as[NMAX];            // alpha_src per node
__device__ float g_ad[NMAX];            // alpha_dst per node
__device__ int   g_csrc[EMAX];          // CSR: src indices grouped by dst
__device__ int   g_cnt[NMAX];           // in-degree histogram (invariant: zero at entry)
__device__ int   g_rowptr[NMAX + 1];    // CSR row pointers
__device__ int   g_cursor[NMAX];        // scatter cursors
__device__ int   g_bsum[256];           // scan block sums
__device__ float g_colsum[FEAT];        // BN stats (invariant: zero at entry)
__device__ float g_colsq[FEAT];
__device__ float g_scale[FEAT];         // BN affine for next GEMM
__device__ float g_shift[FEAT];
__device__ float g_w4s[HID];            // W4^T @ a4s
__device__ float g_w4d[HID];            // W4^T @ a4d
__device__ int   g_done;                // last-block counter (invariant: zero at entry)
__device__ int   g_is64;

// ---------------- startup: dtype probe (warp 0) + w4 matvec (all 64 threads) --------
__global__ void start_kernel(const void* ei, const float* __restrict__ W4,
                             const float* __restrict__ a4s, const float* __restrict__ a4d) {
    int t = threadIdx.x;
    if (t < 32) {
        const long long* p = (const long long*)ei;
        int bad = 0;
        for (int k = t; k < 64; k += 32) {
            long long v = p[k];
            if (v < 0 || v >= (1LL << 31)) bad = 1;
        }
        bad = __any_sync(0xffffffffu, bad);
        if (t == 0) g_is64 = bad ? 0 : 1;
    }
    float s = 0.f, d = 0.f;
#pragma unroll 8
    for (int o = 0; o < FEAT; o++) {
        float w = W4[o * HID + t];
        s += w * a4s[o];
        d += w * a4d[o];
    }
    g_w4s[t] = s;
    g_w4d[t] = d;
}

// ---------------- degree histogram ----------------
__global__ void convert_kernel(const void* ei, int E, int ET) {
    int i = blockIdx.x * blockDim.x + threadIdx.x;
    if (i >= ET) return;
    int d;
    if (i < E) {
        d = g_is64 ? (int)((const long long*)ei)[E + i] : ((const int*)ei)[E + i];
    } else {
        d = i - E;
    }
    atomicAdd(&g_cnt[d], 1);
}

// ---------------- 3-phase parallel scan ----------------
__global__ void scan1_kernel(int n) {
    __shared__ int s[SCH];
    int t = threadIdx.x;
    int i = blockIdx.x * SCH + t;
    s[t] = (i < n) ? g_cnt[i] : 0;
    __syncthreads();
#pragma unroll
    for (int off = SCH / 2; off; off >>= 1) {
        if (t < off) s[t] += s[t + off];
        __syncthreads();
    }
    if (t == 0) g_bsum[blockIdx.x] = s[0];
}

__global__ void scan2_kernel(int nb, int n) {
    __shared__ int s[256];
    int t = threadIdx.x;
    int v = (t < nb) ? g_bsum[t] : 0;
    s[t] = v;
    __syncthreads();
#pragma unroll
    for (int off = 1; off < 256; off <<= 1) {
        int u = (t >= off) ? s[t - off] : 0;
        __syncthreads();
        s[t] += u;
        __syncthreads();
    }
    if (t < nb) g_bsum[t] = s[t] - v;          // exclusive
    if (t == 0) g_rowptr[n] = s[255];
}

// phase 3: intra-block exclusive scan + block offset; re-zeroes g_cnt (replay invariant)
__global__ void scan3_kernel(int n) {
    __shared__ int s[SCH];
    int t = threadIdx.x;
    int i = blockIdx.x * SCH + t;
    int v = (i < n) ? g_cnt[i] : 0;
    s[t] = v;
    __syncthreads();
#pragma unroll
    for (int off = 1; off < SCH; off <<= 1) {
        int u = (t >= off) ? s[t - off] : 0;
        __syncthreads();
        s[t] += u;
        __syncthreads();
    }
    if (i < n) {
        int ex = g_bsum[blockIdx.x] + s[t] - v;
        g_rowptr[i] = ex;
        g_cursor[i] = ex;
        g_cnt[i] = 0;                          // ready for next replay
    }
}

// ---------------- scatter edges into CSR ----------------
__global__ void scatter_kernel(const void* ei, int E, int ET) {
    int i = blockIdx.x * blockDim.x + threadIdx.x;
    if (i >= ET) return;
    int s, d;
    if (i < E) {
        if (g_is64) {
            const long long* p = (const long long*)ei;
            s = (int)p[i]; d = (int)p[E + i];
        } else {
            const int* p = (const int*)ei;
            s = p[i]; d = p[E + i];
        }
    } else {
        s = i - E; d = i - E;
    }
    int pos = atomicAdd(&g_cursor[d], 1);
    g_csrc[pos] = s;
}

// ---------------- GEMM: h = affine(x) @ W^T  (layers 1-3) ----------------
template <int IN, int OUT>
__global__ void gemm_kernel(const float* __restrict__ x, const float* __restrict__ W,
                            int useAffine,
                            const float* __restrict__ avs, const float* __restrict__ avd,
                            float* __restrict__ h, int n) {
    const int M = 8192 / OUT;
    const int OC = OUT / 8;
    const int KC = 32;
    const int SXS = M + 4;
    const int SWS = OUT + 4;

    __shared__ __align__(16) float sSc[IN];
    __shared__ __align__(16) float sSh[IN];
    __shared__ __align__(16) float sX[KC * SXS];
    __shared__ __align__(16) float sW[KC * SWS];

    int tid = threadIdx.x;
    int og = tid % OC;
    int rg = tid / OC;
    int r0 = blockIdx.x * M;

    if (useAffine) {
        for (int o = tid; o < IN; o += 256) { sSc[o] = g_scale[o]; sSh[o] = g_shift[o]; }
        __syncthreads();
    }

    float acc[4][8];
#pragma unroll
    for (int i = 0; i < 4; i++)
#pragma unroll
        for (int j = 0; j < 8; j++) acc[i][j] = 0.f;

    for (int kc = 0; kc < IN; kc += KC) {
        for (int idx = tid; idx < M * (KC / 4); idx += 256) {
            int r = idx >> 3, q = idx & 7;
            int k = q * 4;
            int row = r0 + r;
            float4 v = (row < n) ? *(const float4*)&x[row * IN + kc + k]
                                 : make_float4(0.f, 0.f, 0.f, 0.f);
            if (useAffine) {
                v.x = v.x * sSc[kc + k] + sSh[kc + k];
                v.y = v.y * sSc[kc + k + 1] + sSh[kc + k + 1];
                v.z = v.z * sSc[kc + k + 2] + sSh[kc + k + 2];
                v.w = v.w * sSc[kc + k + 3] + sSh[kc + k + 3];
            }
            sX[(k + 0) * SXS + r] = v.x;
            sX[(k + 1) * SXS + r] = v.y;
            sX[(k + 2) * SXS + r] = v.z;
            sX[(k + 3) * SXS + r] = v.w;
        }
        for (int idx = tid; idx < OUT * (KC / 4); idx += 256) {
            int o = idx >> 3, q = idx & 7;
            int k = q * 4;
            float4 w = *(const float4*)&W[o * IN + kc + k];
            sW[(k + 0) * SWS + o] = w.x;
            sW[(k + 1) * SWS + o] = w.y;
            sW[(k + 2) * SWS + o] = w.z;
            sW[(k + 3) * SWS + o] = w.w;
        }
        __syncthreads();

#pragma unroll
        for (int k = 0; k < KC; k++) {
            float4 a  = *(const float4*)&sX[k * SXS + rg * 4];
            float4 b0 = *(const float4*)&sW[k * SWS + og * 8];
            float4 b1 = *(const float4*)&sW[k * SWS + og * 8 + 4];
            float av[4] = {a.x, a.y, a.z, a.w};
            float bv[8] = {b0.x, b0.y, b0.z, b0.w, b1.x, b1.y, b1.z, b1.w};
#pragma unroll
            for (int i = 0; i < 4; i++)
#pragma unroll
                for (int j = 0; j < 8; j++)
                    acc[i][j] += av[i] * bv[j];
        }
        __syncthreads();
    }

    float avsr[8], avdr[8];
#pragma unroll
    for (int j = 0; j < 8; j++) {
        avsr[j] = __ldg(&avs[og * 8 + j]);
        avdr[j] = __ldg(&avd[og * 8 + j]);
    }

    float* sP = sX;
    float* sQ = sX + M * OC;
#pragma unroll
    for (int i = 0; i < 4; i++) {
        int rl = rg * 4 + i;
        int row = r0 + rl;
        float ps = 0.f, pd = 0.f;
#pragma unroll
        for (int j = 0; j < 8; j++) {
            ps += acc[i][j] * avsr[j];
            pd += acc[i][j] * avdr[j];
        }
        sP[rl * OC + og] = ps;
        sQ[rl * OC + og] = pd;
        if (row < n) {
            float4 v0 = make_float4(acc[i][0], acc[i][1], acc[i][2], acc[i][3]);
            float4 v1 = make_float4(acc[i][4], acc[i][5], acc[i][6], acc[i][7]);
            *(float4*)&h[row * OUT + og * 8] = v0;
            *(float4*)&h[row * OUT + og * 8 + 4] = v1;
        }
    }
    __syncthreads();
    if (tid < M) {
        int row = r0 + tid;
        if (row < n) {
            float as = 0.f, ad = 0.f;
#pragma unroll
            for (int t = 0; t < OC; t++) {
                as += sP[tid * OC + t];
                ad += sQ[tid * OC + t];
            }
            g_as[row] = as;
            g_ad[row] = ad;
        }
    }
}

// ---------------- final GEMM: x_hat = relu(affine(u) @ W4^T + b4); fused output ------
__global__ void gemm_final_kernel(const float* __restrict__ u, const float* __restrict__ W,
                                  const float* __restrict__ b4, const float* __restrict__ x,
                                  float* __restrict__ out, int n, int out_size) {
    const int IN = HID, OUT = FEAT;
    const int M = 8192 / OUT;          // 64
    const int OC = OUT / 8;            // 16
    const int KC = 32;
    const int SXS = M + 4;
    const int SWS = OUT + 4;

    __shared__ __align__(16) float sSc[IN];
    __shared__ __align__(16) float sSh[IN];
    __shared__ __align__(16) float sX[KC * SXS];
    __shared__ __align__(16) float sW[KC * SWS];

    int tid = threadIdx.x;
    int og = tid % OC;
    int rg = tid / OC;
    int r0 = blockIdx.x * M;

    for (int o = tid; o < IN; o += 256) { sSc[o] = g_scale[o]; sSh[o] = g_shift[o]; }
    __syncthreads();

    float acc[4][8];
#pragma unroll
    for (int i = 0; i < 4; i++)
#pragma unroll
        for (int j = 0; j < 8; j++) acc[i][j] = 0.f;

    for (int kc = 0; kc < IN; kc += KC) {
        for (int idx = tid; idx < M * (KC / 4); idx += 256) {
            int r = idx >> 3, q = idx & 7;
            int k = q * 4;
            int row = r0 + r;
            float4 v = (row < n) ? *(const float4*)&u[row * IN + kc + k]
                                 : make_float4(0.f, 0.f, 0.f, 0.f);
            v.x = v.x * sSc[kc + k] + sSh[kc + k];
            v.y = v.y * sSc[kc + k + 1] + sSh[kc + k + 1];
            v.z = v.z * sSc[kc + k + 2] + sSh[kc + k + 2];
            v.w = v.w * sSc[kc + k + 3] + sSh[kc + k + 3];
            sX[(k + 0) * SXS + r] = v.x;
            sX[(k + 1) * SXS + r] = v.y;
            sX[(k + 2) * SXS + r] = v.z;
            sX[(k + 3) * SXS + r] = v.w;
        }
        for (int idx = tid; idx < OUT * (KC / 4); idx += 256) {
            int o = idx >> 3, q = idx & 7;
            int k = q * 4;
            float4 w = *(const float4*)&W[o * IN + kc + k];
            sW[(k + 0) * SWS + o] = w.x;
            sW[(k + 1) * SWS + o] = w.y;
            sW[(k + 2) * SWS + o] = w.z;
            sW[(k + 3) * SWS + o] = w.w;
        }
        __syncthreads();

#pragma unroll
        for (int k = 0; k < KC; k++) {
            float4 a  = *(const float4*)&sX[k * SXS + rg * 4];
            float4 b0 = *(const float4*)&sW[k * SWS + og * 8];
            float4 b1 = *(const float4*)&sW[k * SWS + og * 8 + 4];
            float av[4] = {a.x, a.y, a.z, a.w};
            float bv[8] = {b0.x, b0.y, b0.z, b0.w, b1.x, b1.y, b1.z, b1.w};
#pragma unroll
            for (int i = 0; i < 4; i++)
#pragma unroll
                for (int j = 0; j < 8; j++)
                    acc[i][j] += av[i] * bv[j];
        }
        __syncthreads();
    }

    float4 ba = *(const float4*)&b4[og * 8];
    float4 bb = *(const float4*)&b4[og * 8 + 4];
    float bias[8] = {ba.x, ba.y, ba.z, ba.w, bb.x, bb.y, bb.z, bb.w};
    int total = n * OUT;
    int full = (out_size >= 2 * total);

#pragma unroll
    for (int i = 0; i < 4; i++) {
        int row = r0 + rg * 4 + i;
        if (row < n) {
            float v[8];
#pragma unroll
            for (int j = 0; j < 8; j++) {
                v[j] = acc[i][j] + bias[j];
                v[j] = (v[j] > 0.f) ? v[j] : 0.f;
            }
            float4 x0 = *(const float4*)&x[row * OUT + og * 8];
            float4 x1 = *(const float4*)&x[row * OUT + og * 8 + 4];
            *(float4*)&out[row * OUT + og * 8] =
                make_float4(fabsf(x0.x - v[0]), fabsf(x0.y - v[1]),
                            fabsf(x0.z - v[2]), fabsf(x0.w - v[3]));
            *(float4*)&out[row * OUT + og * 8 + 4] =
                make_float4(fabsf(x1.x - v[4]), fabsf(x1.y - v[5]),
                            fabsf(x1.z - v[6]), fabsf(x1.w - v[7]));
            if (full) {
                *(float4*)&out[total + row * OUT + og * 8] =
                    make_float4(v[0], v[1], v[2], v[3]);
                *(float4*)&out[total + row * OUT + og * 8 + 4] =
                    make_float4(v[4], v[5], v[6], v[7]);
            }
        }
    }
}

// ---------------- alpha for layer 4 (warp per node) ----------------
__global__ void alpha4_kernel(const float* __restrict__ y, int n) {
    int warp = (blockIdx.x * blockDim.x + threadIdx.x) >> 5;
    int lane = threadIdx.x & 31;
    if (warp >= n) return;
    float as = 0.f, ad = 0.f;
#pragma unroll
    for (int j = 0; j < 2; j++) {
        int k = j * 32 + lane;
        float v = y[warp * HID + k] * g_scale[k] + g_shift[k];
        as += v * g_w4s[k];
        ad += v * g_w4d[k];
    }
#pragma unroll
    for (int off = 16; off; off >>= 1) {
        as += __shfl_down_sync(0xffffffffu, as, off);
        ad += __shfl_down_sync(0xffffffffu, ad, off);
    }
    if (lane == 0) { g_as[warp] = as; g_ad[warp] = ad; }
}

// ---------------- edge-batch macro body: x4 pipelined gather ----------------
// (all index loads issued first -> MLP 4 on hop 1; then all as/h loads -> MLP 8 on hop 2)

// ---------------- fused CSR aggregation + last-block BN finalize ----------------
__global__ void agg_bn_kernel(const float* __restrict__ h, const float* __restrict__ b,
                              const float* __restrict__ gamma, const float* __restrict__ beta,
                              float invn, float* __restrict__ yout, int n) {
    const int OUT = HID;
    const int TPN = OUT / 4;            // 16
    const int NPB = 256 / TPN;          // 16
    int c4 = threadIdx.x % TPN;
    int nl = threadIdx.x / TPN;

    float4 bias = *(const float4*)&b[c4 * 4];

    float st_s[4] = {0.f, 0.f, 0.f, 0.f};
    float st_q[4] = {0.f, 0.f, 0.f, 0.f};

    for (int node = blockIdx.x * NPB + nl; node < n; node += gridDim.x * NPB) {
        int p   = g_rowptr[node];
        int end = g_rowptr[node + 1];
        float adn = g_ad[node];

        float a0 = 0.f, a1 = 0.f, a2 = 0.f, a3 = 0.f;   // chain A (edges 0,2 of batch)
        float b0 = 0.f, b1_ = 0.f, b2 = 0.f, b3 = 0.f;  // chain B (edges 1,3 of batch)
        float lsum = 0.f;

        // x4 batch: 4 independent index loads, then 4 as + 4 h loads, then FMAs
        for (; p + 4 <= end; p += 4) {
            int s0 = g_csrc[p];
            int s1 = g_csrc[p + 1];
            int s2 = g_csrc[p + 2];
            int s3 = g_csrc[p + 3];
            float e0 = g_as[s0];
            float e1 = g_as[s1];
            float e2 = g_as[s2];
            float e3 = g_as[s3];
            float4 h0 = *(const float4*)&h[s0 * OUT + c4 * 4];
            float4 h1 = *(const float4*)&h[s1 * OUT + c4 * 4];
            float4 h2 = *(const float4*)&h[s2 * OUT + c4 * 4];
            float4 h3 = *(const float4*)&h[s3 * OUT + c4 * 4];
            e0 += adn; e0 = (e0 >= 0.f) ? e0 : 0.2f * e0;
            e1 += adn; e1 = (e1 >= 0.f) ? e1 : 0.2f * e1;
            e2 += adn; e2 = (e2 >= 0.f) ? e2 : 0.2f * e2;
            e3 += adn; e3 = (e3 >= 0.f) ? e3 : 0.2f * e3;
            float t0 = __expf(e0);
            float t1 = __expf(e1);
            float t2 = __expf(e2);
            float t3 = __expf(e3);
            lsum += (t0 + t1) + (t2 + t3);
            a0 += t0 * h0.x; a1 += t0 * h0.y; a2 += t0 * h0.z; a3 += t0 * h0.w;
            b0 += t1 * h1.x; b1_ += t1 * h1.y; b2 += t1 * h1.z; b3 += t1 * h1.w;
            a0 += t2 * h2.x; a1 += t2 * h2.y; a2 += t2 * h2.z; a3 += t2 * h2.w;
            b0 += t3 * h3.x; b1_ += t3 * h3.y; b2 += t3 * h3.z; b3 += t3 * h3.w;
        }
        if (p + 2 <= end) {
            int s0 = g_csrc[p];
            int s1 = g_csrc[p + 1];
            float e0 = g_as[s0] + adn;
            float e1 = g_as[s1] + adn;
            float4 h0 = *(const float4*)&h[s0 * OUT + c4 * 4];
            float4 h1 = *(const float4*)&h[s1 * OUT + c4 * 4];
            e0 = (e0 >= 0.f) ? e0 : 0.2f * e0;
            e1 = (e1 >= 0.f) ? e1 : 0.2f * e1;
            float t0 = __expf(e0);
            float t1 = __expf(e1);
            lsum += t0 + t1;
            a0 += t0 * h0.x; a1 += t0 * h0.y; a2 += t0 * h0.z; a3 += t0 * h0.w;
            b0 += t1 * h1.x; b1_ += t1 * h1.y; b2 += t1 * h1.z; b3 += t1 * h1.w;
            p += 2;
        }
        if (p < end) {
            int s = g_csrc[p];
            float e = g_as[s] + adn;
            e = (e >= 0.f) ? e : 0.2f * e;
            float t = __expf(e);
            lsum += t;
            float4 hv = *(const float4*)&h[s * OUT + c4 * 4];
            a0 += t * hv.x; a1 += t * hv.y; a2 += t * hv.z; a3 += t * hv.w;
        }
        a0 += b0; a1 += b1_; a2 += b2; a3 += b3;

        float inv = __fdividef(1.f, lsum + 1e-16f);
        float v0 = a0 * inv + bias.x; v0 = (v0 > 0.f) ? v0 : 0.f;
        float v1 = a1 * inv + bias.y; v1 = (v1 > 0.f) ? v1 : 0.f;
        float v2 = a2 * inv + bias.z; v2 = (v2 > 0.f) ? v2 : 0.f;
        float v3 = a3 * inv + bias.w; v3 = (v3 > 0.f) ? v3 : 0.f;
        *(float4*)&yout[node * OUT + c4 * 4] = make_float4(v0, v1, v2, v3);
        st_s[0] += v0; st_q[0] += v0 * v0;
        st_s[1] += v1; st_q[1] += v1 * v1;
        st_s[2] += v2; st_q[2] += v2 * v2;
        st_s[3] += v3; st_q[3] += v3 * v3;
    }

    __shared__ float sS[256 * 4];
    __shared__ float sQ[256 * 4];
#pragma unroll
    for (int c = 0; c < 4; c++) {
        sS[threadIdx.x * 4 + c] = st_s[c];
        sQ[threadIdx.x * 4 + c] = st_q[c];
    }
    __syncthreads();
    if (nl == 0) {
#pragma unroll 4
        for (int t = 1; t < NPB; t++) {
#pragma unroll
            for (int c = 0; c < 4; c++) {
                st_s[c] += sS[(t * TPN + c4) * 4 + c];
                st_q[c] += sQ[(t * TPN + c4) * 4 + c];
            }
        }
#pragma unroll
        for (int c = 0; c < 4; c++) {
            atomicAdd(&g_colsum[c4 * 4 + c], st_s[c]);
            atomicAdd(&g_colsq[c4 * 4 + c], st_q[c]);
        }
    }

    // last-block BN finalize
    __shared__ int isLast;
    __syncthreads();
    if (threadIdx.x == 0) {
        __threadfence();
        int c = atomicAdd(&g_done, 1);
        isLast = (c == (int)gridDim.x - 1) ? 1 : 0;
    }
    __syncthreads();
    if (isLast) {
        int o = threadIdx.x;
        if (o < HID) {
            float mu = g_colsum[o] * invn;
            float var = g_colsq[o] * invn - mu * mu;
            float sc = gamma[o] * rsqrtf(var + 1e-5f);
            g_scale[o] = sc;
            g_shift[o] = beta[o] - mu * sc;
            g_colsum[o] = 0.f;
            g_colsq[o] = 0.f;
        }
        if (threadIdx.x == 0) g_done = 0;
    }
}

// ---------------- layer-4 aggregation (raw aggregate u, x4 pipelined) ----------------
__global__ void agg_f32_kernel(const float* __restrict__ h, float* __restrict__ yout, int n) {
    const int OUT = HID;
    const int TPN = OUT / 4;
    const int NPB = 256 / TPN;
    int c4 = threadIdx.x % TPN;
    int nl = threadIdx.x / TPN;

    for (int node = blockIdx.x * NPB + nl; node < n; node += gridDim.x * NPB) {
        int p   = g_rowptr[node];
        int end = g_rowptr[node + 1];
        float adn = g_ad[node];

        float a0 = 0.f, a1 = 0.f, a2 = 0.f, a3 = 0.f;
        float b0 = 0.f, b1_ = 0.f, b2 = 0.f, b3 = 0.f;
        float lsum = 0.f;

        for (; p + 4 <= end; p += 4) {
            int s0 = g_csrc[p];
            int s1 = g_csrc[p + 1];
            int s2 = g_csrc[p + 2];
            int s3 = g_csrc[p + 3];
            float e0 = g_as[s0];
            float e1 = g_as[s1];
            float e2 = g_as[s2];
            float e3 = g_as[s3];
            float4 h0 = *(const float4*)&h[s0 * OUT + c4 * 4];
            float4 h1 = *(const float4*)&h[s1 * OUT + c4 * 4];
            float4 h2 = *(const float4*)&h[s2 * OUT + c4 * 4];
            float4 h3 = *(const float4*)&h[s3 * OUT + c4 * 4];
            e0 += adn; e0 = (e0 >= 0.f) ? e0 : 0.2f * e0;
            e1 += adn; e1 = (e1 >= 0.f) ? e1 : 0.2f * e1;
            e2 += adn; e2 = (e2 >= 0.f) ? e2 : 0.2f * e2;
            e3 += adn; e3 = (e3 >= 0.f) ? e3 : 0.2f * e3;
            float t0 = __expf(e0);
            float t1 = __expf(e1);
            float t2 = __expf(e2);
            float t3 = __expf(e3);
            lsum += (t0 + t1) + (t2 + t3);
            a0 += t0 * h0.x; a1 += t0 * h0.y; a2 += t0 * h0.z; a3 += t0 * h0.w;
            b0 += t1 * h1.x; b1_ += t1 * h1.y; b2 += t1 * h1.z; b3 += t1 * h1.w;
            a0 += t2 * h2.x; a1 += t2 * h2.y; a2 += t2 * h2.z; a3 += t2 * h2.w;
            b0 += t3 * h3.x; b1_ += t3 * h3.y; b2 += t3 * h3.z; b3 += t3 * h3.w;
        }
        if (p + 2 <= end) {
            int s0 = g_csrc[p];
            int s1 = g_csrc[p + 1];
            float e0 = g_as[s0] + adn;
            float e1 = g_as[s1] + adn;
            float4 h0 = *(const float4*)&h[s0 * OUT + c4 * 4];
            float4 h1 = *(const float4*)&h[s1 * OUT + c4 * 4];
            e0 = (e0 >= 0.f) ? e0 : 0.2f * e0;
            e1 = (e1 >= 0.f) ? e1 : 0.2f * e1;
            float t0 = __expf(e0);
            float t1 = __expf(e1);
            lsum += t0 + t1;
            a0 += t0 * h0.x; a1 += t0 * h0.y; a2 += t0 * h0.z; a3 += t0 * h0.w;
            b0 += t1 * h1.x; b1_ += t1 * h1.y; b2 += t1 * h1.z; b3 += t1 * h1.w;
            p += 2;
        }
        if (p < end) {
            int s = g_csrc[p];
            float e = g_as[s] + adn;
            e = (e >= 0.f) ? e : 0.2f * e;
            float t = __expf(e);
            lsum += t;
            float4 hv = *(const float4*)&h[s * OUT + c4 * 4];
            a0 += t * hv.x; a1 += t * hv.y; a2 += t * hv.z; a3 += t * hv.w;
        }
        a0 += b0; a1 += b1_; a2 += b2; a3 += b3;

        float inv = __fdividef(1.f, lsum + 1e-16f);
        *(float4*)&yout[node * OUT + c4 * 4] =
            make_float4(a0 * inv, a1 * inv, a2 * inv, a3 * inv);
    }
}

extern "C" void kernel_launch(void* const* d_in, const int* in_sizes, int n_in,
                              void* d_out, int out_size) {
    const float* x   = (const float*)d_in[0];
    const void*  ei  = d_in[1];
    const float* W1  = (const float*)d_in[2];
    const float* a1s = (const float*)d_in[3];
    const float* a1d = (const float*)d_in[4];
    const float* b1  = (const float*)d_in[5];
    const float* g1  = (const float*)d_in[6];
    const float* be1 = (const float*)d_in[7];
    const float* W2  = (const float*)d_in[8];
    const float* a2s = (const float*)d_in[9];
    const float* a2d = (const float*)d_in[10];
    const float* b2  = (const float*)d_in[11];
    const float* g2  = (const float*)d_in[12];
    const float* be2 = (const float*)d_in[13];
    const float* W3  = (const float*)d_in[14];
    const float* a3s = (const float*)d_in[15];
    const float* a3d = (const float*)d_in[16];
    const float* b3  = (const float*)d_in[17];
    const float* g3  = (const float*)d_in[18];
    const float* be3 = (const float*)d_in[19];
    const float* W4  = (const float*)d_in[20];
    const float* a4s = (const float*)d_in[21];
    const float* a4d = (const float*)d_in[22];
    const float* b4  = (const float*)d_in[23];

    int n  = in_sizes[0] / FEAT;     // 50000
    int E  = in_sizes[1] / 2;        // 800000
    int ET = E + n;
    int nb = (n + SCH - 1) / SCH;

    float *hbuf, *ybuf, *ubuf;
    cudaGetSymbolAddress((void**)&hbuf, g_h);
    cudaGetSymbolAddress((void**)&ybuf, g_y);
    cudaGetSymbolAddress((void**)&ubuf, g_u);

    float invn = 1.0f / (float)n;
    const int AGG_BLOCKS = 1184;

    // Fork a side stream so the CSR build overlaps the layer-1 GEMM.
    cudaStream_t s1;
    cudaStreamCreateWithFlags(&s1, cudaStreamNonBlocking);
    cudaEvent_t e0, e1;
    cudaEventCreateWithFlags(&e0, cudaEventDisableTiming);
    cudaEventCreateWithFlags(&e1, cudaEventDisableTiming);

    // ---- common prologue (dtype probe + w4) on the origin stream ----
    start_kernel<<<1, HID>>>(ei, W4, a4s, a4d);
    cudaEventRecord(e0, 0);

    // ---- branch B (side stream): CSR build ----
    cudaStreamWaitEvent(s1, e0, 0);
    convert_kernel<<<(ET + 255) / 256, 256, 0, s1>>>(ei, E, ET);
    scan1_kernel<<<nb, SCH, 0, s1>>>(n);
    scan2_kernel<<<1, 256, 0, s1>>>(nb, n);
    scan3_kernel<<<nb, SCH, 0, s1>>>(n);
    scatter_kernel<<<(ET + 255) / 256, 256, 0, s1>>>(ei, E, ET);
    cudaEventRecord(e1, s1);

    // ---- branch A (origin stream): layer-1 GEMM (independent of CSR) ----
    gemm_kernel<FEAT, HID><<<(n + 127) / 128, 256>>>(x, W1, 0, a1s, a1d, hbuf, n);

    // ---- join: aggregation needs both branches ----
    cudaStreamWaitEvent(0, e1, 0);
    agg_bn_kernel<<<AGG_BLOCKS, 256>>>(hbuf, b1, g1, be1, invn, ybuf, n);

    // ---- Layer 2: 64 -> 64 ----
    gemm_kernel<HID, HID><<<(n + 127) / 128, 256>>>(ybuf, W2, 1, a2s, a2d, hbuf, n);
    agg_bn_kernel<<<AGG_BLOCKS, 256>>>(hbuf, b2, g2, be2, invn, ybuf, n);

    // ---- Layer 3: 64 -> 64 ----
    gemm_kernel<HID, HID><<<(n + 127) / 128, 256>>>(ybuf, W3, 1, a3s, a3d, hbuf, n);
    agg_bn_kernel<<<AGG_BLOCKS, 256>>>(hbuf, b3, g3, be3, invn, ybuf, n);

    // ---- Layer 4 (commuted): alpha, aggregate y, GEMM+final ----
    alpha4_kernel<<<(n * 32 + 255) / 256, 256>>>(ybuf, n);
    agg_f32_kernel<<<AGG_BLOCKS, 256>>>(ybuf, ubuf, n);
    gemm_final_kernel<<<(n + 63) / 64, 256>>>(ubuf, W4, b4, x, (float*)d_out, n, out_size);

    cudaEventDestroy(e0);
    cudaEventDestroy(e1);
    cudaStreamDestroy(s1);
}

// round 17
// speedup vs baseline: 2.1771x; 1.0134x over previous
#include <cuda_runtime.h>
#include <math.h>

#define FEAT 128
#define HID  64
#define NMAX 50048
#define EMAX 1048576
#define SCH  512                        // scan chunk (elements per block)

// ---------------- scratch (static __device__) ----------------
__device__ float g_h[NMAX * HID];       // post-GEMM features h (L1-3)
__device__ float g_u[NMAX * HID];       // layer-4 aggregated u
__device__ float g_y[NMAX * HID];       // post-aggregation features
__device__ float g_as[NMAX];            // alpha_src per node
__device__ float g_ad[NMAX];            // alpha_dst per node
__device__ int   g_csrc[EMAX];          // CSR: src indices grouped by dst
__device__ int   g_cnt[NMAX];           // in-degree histogram (invariant: zero at entry)
__device__ int   g_rowptr[NMAX + 1];    // CSR row pointers
__device__ int   g_cursor[NMAX];        // scatter cursors
__device__ int   g_bsum[256];           // scan block sums
__device__ float g_colsum[FEAT];        // BN stats (invariant: zero at entry)
__device__ float g_colsq[FEAT];
__device__ float g_scale[FEAT];         // BN affine for next GEMM
__device__ float g_shift[FEAT];
__device__ float g_w4s[HID];            // W4^T @ a4s
__device__ float g_w4d[HID];            // W4^T @ a4d
__device__ int   g_done;                // last-block counter (invariant: zero at entry)
__device__ int   g_is64;

// ---------------- startup: dtype probe (warp 0) + w4 matvec (all 64 threads) --------
__global__ void start_kernel(const void* ei, const float* __restrict__ W4,
                             const float* __restrict__ a4s, const float* __restrict__ a4d) {
    int t = threadIdx.x;
    if (t < 32) {
        const long long* p = (const long long*)ei;
        int bad = 0;
        for (int k = t; k < 64; k += 32) {
            long long v = p[k];
            if (v < 0 || v >= (1LL << 31)) bad = 1;
        }
        bad = __any_sync(0xffffffffu, bad);
        if (t == 0) g_is64 = bad ? 0 : 1;
    }
    float s = 0.f, d = 0.f;
#pragma unroll 8
    for (int o = 0; o < FEAT; o++) {
        float w = W4[o * HID + t];
        s += w * a4s[o];
        d += w * a4d[o];
    }
    g_w4s[t] = s;
    g_w4d[t] = d;
}

// ---------------- degree histogram ----------------
__global__ void convert_kernel(const void* ei, int E, int ET) {
    int i = blockIdx.x * blockDim.x + threadIdx.x;
    if (i >= ET) return;
    int d;
    if (i < E) {
        d = g_is64 ? (int)((const long long*)ei)[E + i] : ((const int*)ei)[E + i];
    } else {
        d = i - E;
    }
    atomicAdd(&g_cnt[d], 1);
}

// ---------------- 3-phase parallel scan ----------------
__global__ void scan1_kernel(int n) {
    __shared__ int s[SCH];
    int t = threadIdx.x;
    int i = blockIdx.x * SCH + t;
    s[t] = (i < n) ? g_cnt[i] : 0;
    __syncthreads();
#pragma unroll
    for (int off = SCH / 2; off; off >>= 1) {
        if (t < off) s[t] += s[t + off];
        __syncthreads();
    }
    if (t == 0) g_bsum[blockIdx.x] = s[0];
}

__global__ void scan2_kernel(int nb, int n) {
    __shared__ int s[256];
    int t = threadIdx.x;
    int v = (t < nb) ? g_bsum[t] : 0;
    s[t] = v;
    __syncthreads();
#pragma unroll
    for (int off = 1; off < 256; off <<= 1) {
        int u = (t >= off) ? s[t - off] : 0;
        __syncthreads();
        s[t] += u;
        __syncthreads();
    }
    if (t < nb) g_bsum[t] = s[t] - v;          // exclusive
    if (t == 0) g_rowptr[n] = s[255];
}

// phase 3: intra-block exclusive scan + block offset; re-zeroes g_cnt (replay invariant)
__global__ void scan3_kernel(int n) {
    __shared__ int s[SCH];
    int t = threadIdx.x;
    int i = blockIdx.x * SCH + t;
    int v = (i < n) ? g_cnt[i] : 0;
    s[t] = v;
    __syncthreads();
#pragma unroll
    for (int off = 1; off < SCH; off <<= 1) {
        int u = (t >= off) ? s[t - off] : 0;
        __syncthreads();
        s[t] += u;
        __syncthreads();
    }
    if (i < n) {
        int ex = g_bsum[blockIdx.x] + s[t] - v;
        g_rowptr[i] = ex;
        g_cursor[i] = ex;
        g_cnt[i] = 0;                          // ready for next replay
    }
}

// ---------------- scatter edges into CSR ----------------
__global__ void scatter_kernel(const void* ei, int E, int ET) {
    int i = blockIdx.x * blockDim.x + threadIdx.x;
    if (i >= ET) return;
    int s, d;
    if (i < E) {
        if (g_is64) {
            const long long* p = (const long long*)ei;
            s = (int)p[i]; d = (int)p[E + i];
        } else {
            const int* p = (const int*)ei;
            s = p[i]; d = p[E + i];
        }
    } else {
        s = i - E; d = i - E;
    }
    int pos = atomicAdd(&g_cursor[d], 1);
    g_csrc[pos] = s;
}

// ---------------- GEMM: h = affine(x) @ W^T  (layers 1-3) ----------------
template <int IN, int OUT>
__global__ void gemm_kernel(const float* __restrict__ x, const float* __restrict__ W,
                            int useAffine,
                            const float* __restrict__ avs, const float* __restrict__ avd,
                            float* __restrict__ h, int n) {
    const int M = 8192 / OUT;
    const int OC = OUT / 8;
    const int KC = 32;
    const int SXS = M + 4;
    const int SWS = OUT + 4;

    __shared__ __align__(16) float sSc[IN];
    __shared__ __align__(16) float sSh[IN];
    __shared__ __align__(16) float sX[KC * SXS];
    __shared__ __align__(16) float sW[KC * SWS];

    int tid = threadIdx.x;
    int og = tid % OC;
    int rg = tid / OC;
    int r0 = blockIdx.x * M;

    if (useAffine) {
        for (int o = tid; o < IN; o += 256) { sSc[o] = g_scale[o]; sSh[o] = g_shift[o]; }
        __syncthreads();
    }

    float acc[4][8];
#pragma unroll
    for (int i = 0; i < 4; i++)
#pragma unroll
        for (int j = 0; j < 8; j++) acc[i][j] = 0.f;

    for (int kc = 0; kc < IN; kc += KC) {
        for (int idx = tid; idx < M * (KC / 4); idx += 256) {
            int r = idx >> 3, q = idx & 7;
            int k = q * 4;
            int row = r0 + r;
            float4 v = (row < n) ? *(const float4*)&x[row * IN + kc + k]
                                 : make_float4(0.f, 0.f, 0.f, 0.f);
            if (useAffine) {
                v.x = v.x * sSc[kc + k] + sSh[kc + k];
                v.y = v.y * sSc[kc + k + 1] + sSh[kc + k + 1];
                v.z = v.z * sSc[kc + k + 2] + sSh[kc + k + 2];
                v.w = v.w * sSc[kc + k + 3] + sSh[kc + k + 3];
            }
            sX[(k + 0) * SXS + r] = v.x;
            sX[(k + 1) * SXS + r] = v.y;
            sX[(k + 2) * SXS + r] = v.z;
            sX[(k + 3) * SXS + r] = v.w;
        }
        for (int idx = tid; idx < OUT * (KC / 4); idx += 256) {
            int o = idx >> 3, q = idx & 7;
            int k = q * 4;
            float4 w = *(const float4*)&W[o * IN + kc + k];
            sW[(k + 0) * SWS + o] = w.x;
            sW[(k + 1) * SWS + o] = w.y;
            sW[(k + 2) * SWS + o] = w.z;
            sW[(k + 3) * SWS + o] = w.w;
        }
        __syncthreads();

#pragma unroll
        for (int k = 0; k < KC; k++) {
            float4 a  = *(const float4*)&sX[k * SXS + rg * 4];
            float4 b0 = *(const float4*)&sW[k * SWS + og * 8];
            float4 b1 = *(const float4*)&sW[k * SWS + og * 8 + 4];
            float av[4] = {a.x, a.y, a.z, a.w};
            float bv[8] = {b0.x, b0.y, b0.z, b0.w, b1.x, b1.y, b1.z, b1.w};
#pragma unroll
            for (int i = 0; i < 4; i++)
#pragma unroll
                for (int j = 0; j < 8; j++)
                    acc[i][j] += av[i] * bv[j];
        }
        __syncthreads();
    }

    float avsr[8], avdr[8];
#pragma unroll
    for (int j = 0; j < 8; j++) {
        avsr[j] = __ldg(&avs[og * 8 + j]);
        avdr[j] = __ldg(&avd[og * 8 + j]);
    }

    float* sP = sX;
    float* sQ = sX + M * OC;
#pragma unroll
    for (int i = 0; i < 4; i++) {
        int rl = rg * 4 + i;
        int row = r0 + rl;
        float ps = 0.f, pd = 0.f;
#pragma unroll
        for (int j = 0; j < 8; j++) {
            ps += acc[i][j] * avsr[j];
            pd += acc[i][j] * avdr[j];
        }
        sP[rl * OC + og] = ps;
        sQ[rl * OC + og] = pd;
        if (row < n) {
            float4 v0 = make_float4(acc[i][0], acc[i][1], acc[i][2], acc[i][3]);
            float4 v1 = make_float4(acc[i][4], acc[i][5], acc[i][6], acc[i][7]);
            *(float4*)&h[row * OUT + og * 8] = v0;
            *(float4*)&h[row * OUT + og * 8 + 4] = v1;
        }
    }
    __syncthreads();
    if (tid < M) {
        int row = r0 + tid;
        if (row < n) {
            float as = 0.f, ad = 0.f;
#pragma unroll
            for (int t = 0; t < OC; t++) {
                as += sP[tid * OC + t];
                ad += sQ[tid * OC + t];
            }
            g_as[row] = as;
            g_ad[row] = ad;
        }
    }
}

// ---------------- final GEMM: x_hat = relu(affine(u) @ W4^T + b4); fused output ------
__global__ void gemm_final_kernel(const float* __restrict__ u, const float* __restrict__ W,
                                  const float* __restrict__ b4, const float* __restrict__ x,
                                  float* __restrict__ out, int n, int out_size) {
    const int IN = HID, OUT = FEAT;
    const int M = 8192 / OUT;          // 64
    const int OC = OUT / 8;            // 16
    const int KC = 32;
    const int SXS = M + 4;
    const int SWS = OUT + 4;

    __shared__ __align__(16) float sSc[IN];
    __shared__ __align__(16) float sSh[IN];
    __shared__ __align__(16) float sX[KC * SXS];
    __shared__ __align__(16) float sW[KC * SWS];

    int tid = threadIdx.x;
    int og = tid % OC;
    int rg = tid / OC;
    int r0 = blockIdx.x * M;

    for (int o = tid; o < IN; o += 256) { sSc[o] = g_scale[o]; sSh[o] = g_shift[o]; }
    __syncthreads();

    float acc[4][8];
#pragma unroll
    for (int i = 0; i < 4; i++)
#pragma unroll
        for (int j = 0; j < 8; j++) acc[i][j] = 0.f;

    for (int kc = 0; kc < IN; kc += KC) {
        for (int idx = tid; idx < M * (KC / 4); idx += 256) {
            int r = idx >> 3, q = idx & 7;
            int k = q * 4;
            int row = r0 + r;
            float4 v = (row < n) ? *(const float4*)&u[row * IN + kc + k]
                                 : make_float4(0.f, 0.f, 0.f, 0.f);
            v.x = v.x * sSc[kc + k] + sSh[kc + k];
            v.y = v.y * sSc[kc + k + 1] + sSh[kc + k + 1];
            v.z = v.z * sSc[kc + k + 2] + sSh[kc + k + 2];
            v.w = v.w * sSc[kc + k + 3] + sSh[kc + k + 3];
            sX[(k + 0) * SXS + r] = v.x;
            sX[(k + 1) * SXS + r] = v.y;
            sX[(k + 2) * SXS + r] = v.z;
            sX[(k + 3) * SXS + r] = v.w;
        }
        for (int idx = tid; idx < OUT * (KC / 4); idx += 256) {
            int o = idx >> 3, q = idx & 7;
            int k = q * 4;
            float4 w = *(const float4*)&W[o * IN + kc + k];
            sW[(k + 0) * SWS + o] = w.x;
            sW[(k + 1) * SWS + o] = w.y;
            sW[(k + 2) * SWS + o] = w.z;
            sW[(k + 3) * SWS + o] = w.w;
        }
        __syncthreads();

#pragma unroll
        for (int k = 0; k < KC; k++) {
            float4 a  = *(const float4*)&sX[k * SXS + rg * 4];
            float4 b0 = *(const float4*)&sW[k * SWS + og * 8];
            float4 b1 = *(const float4*)&sW[k * SWS + og * 8 + 4];
            float av[4] = {a.x, a.y, a.z, a.w};
            float bv[8] = {b0.x, b0.y, b0.z, b0.w, b1.x, b1.y, b1.z, b1.w};
#pragma unroll
            for (int i = 0; i < 4; i++)
#pragma unroll
                for (int j = 0; j < 8; j++)
                    acc[i][j] += av[i] * bv[j];
        }
        __syncthreads();
    }

    float4 ba = *(const float4*)&b4[og * 8];
    float4 bb = *(const float4*)&b4[og * 8 + 4];
    float bias[8] = {ba.x, ba.y, ba.z, ba.w, bb.x, bb.y, bb.z, bb.w};
    int total = n * OUT;
    int full = (out_size >= 2 * total);

#pragma unroll
    for (int i = 0; i < 4; i++) {
        int row = r0 + rg * 4 + i;
        if (row < n) {
            float v[8];
#pragma unroll
            for (int j = 0; j < 8; j++) {
                v[j] = acc[i][j] + bias[j];
                v[j] = (v[j] > 0.f) ? v[j] : 0.f;
            }
            float4 x0 = *(const float4*)&x[row * OUT + og * 8];
            float4 x1 = *(const float4*)&x[row * OUT + og * 8 + 4];
            *(float4*)&out[row * OUT + og * 8] =
                make_float4(fabsf(x0.x - v[0]), fabsf(x0.y - v[1]),
                            fabsf(x0.z - v[2]), fabsf(x0.w - v[3]));
            *(float4*)&out[row * OUT + og * 8 + 4] =
                make_float4(fabsf(x1.x - v[4]), fabsf(x1.y - v[5]),
                            fabsf(x1.z - v[6]), fabsf(x1.w - v[7]));
            if (full) {
                *(float4*)&out[total + row * OUT + og * 8] =
                    make_float4(v[0], v[1], v[2], v[3]);
                *(float4*)&out[total + row * OUT + og * 8 + 4] =
                    make_float4(v[4], v[5], v[6], v[7]);
            }
        }
    }
}

// ---------------- alpha for layer 4 (warp per node) ----------------
__global__ void alpha4_kernel(const float* __restrict__ y, int n) {
    int warp = (blockIdx.x * blockDim.x + threadIdx.x) >> 5;
    int lane = threadIdx.x & 31;
    if (warp >= n) return;
    float as = 0.f, ad = 0.f;
#pragma unroll
    for (int j = 0; j < 2; j++) {
        int k = j * 32 + lane;
        float v = y[warp * HID + k] * g_scale[k] + g_shift[k];
        as += v * g_w4s[k];
        ad += v * g_w4d[k];
    }
#pragma unroll
    for (int off = 16; off; off >>= 1) {
        as += __shfl_down_sync(0xffffffffu, as, off);
        ad += __shfl_down_sync(0xffffffffu, ad, off);
    }
    if (lane == 0) { g_as[warp] = as; g_ad[warp] = ad; }
}

// ---------------- fused CSR aggregation + last-block BN finalize ----------------
// Edge loop: x4 batch with NEXT-batch index prefetch (hop-1 latency hidden).
__global__ void agg_bn_kernel(const float* __restrict__ h, const float* __restrict__ b,
                              const float* __restrict__ gamma, const float* __restrict__ beta,
                              float invn, float* __restrict__ yout, int n) {
    const int OUT = HID;
    const int TPN = OUT / 4;            // 16
    const int NPB = 256 / TPN;          // 16
    int c4 = threadIdx.x % TPN;
    int nl = threadIdx.x / TPN;

    float4 bias = *(const float4*)&b[c4 * 4];

    float st_s[4] = {0.f, 0.f, 0.f, 0.f};
    float st_q[4] = {0.f, 0.f, 0.f, 0.f};

    for (int node = blockIdx.x * NPB + nl; node < n; node += gridDim.x * NPB) {
        int p   = g_rowptr[node];
        int end = g_rowptr[node + 1];
        float adn = g_ad[node];

        float a0 = 0.f, a1 = 0.f, a2 = 0.f, a3 = 0.f;
        float b0 = 0.f, b1_ = 0.f, b2 = 0.f, b3 = 0.f;
        float lsum = 0.f;

        int s0, s1, s2, s3;
        bool have = (p + 4 <= end);
        if (have) {
            s0 = g_csrc[p]; s1 = g_csrc[p + 1];
            s2 = g_csrc[p + 2]; s3 = g_csrc[p + 3];
        }
        while (have) {
            int np = p + 4;
            bool nhave = (np + 4 <= end);
            // speculative prefetch of next batch's indices (bounds-safe within g_csrc)
            int t0i = g_csrc[np];
            int t1i = g_csrc[np + 1];
            int t2i = g_csrc[np + 2];
            int t3i = g_csrc[np + 3];

            float e0 = g_as[s0];
            float e1 = g_as[s1];
            float e2 = g_as[s2];
            float e3 = g_as[s3];
            float4 h0 = *(const float4*)&h[s0 * OUT + c4 * 4];
            float4 h1 = *(const float4*)&h[s1 * OUT + c4 * 4];
            float4 h2 = *(const float4*)&h[s2 * OUT + c4 * 4];
            float4 h3 = *(const float4*)&h[s3 * OUT + c4 * 4];
            e0 += adn; e0 = (e0 >= 0.f) ? e0 : 0.2f * e0;
            e1 += adn; e1 = (e1 >= 0.f) ? e1 : 0.2f * e1;
            e2 += adn; e2 = (e2 >= 0.f) ? e2 : 0.2f * e2;
            e3 += adn; e3 = (e3 >= 0.f) ? e3 : 0.2f * e3;
            float t0 = __expf(e0);
            float t1 = __expf(e1);
            float t2 = __expf(e2);
            float t3 = __expf(e3);
            lsum += (t0 + t1) + (t2 + t3);
            a0 += t0 * h0.x; a1 += t0 * h0.y; a2 += t0 * h0.z; a3 += t0 * h0.w;
            b0 += t1 * h1.x; b1_ += t1 * h1.y; b2 += t1 * h1.z; b3 += t1 * h1.w;
            a0 += t2 * h2.x; a1 += t2 * h2.y; a2 += t2 * h2.z; a3 += t2 * h2.w;
            b0 += t3 * h3.x; b1_ += t3 * h3.y; b2 += t3 * h3.z; b3 += t3 * h3.w;

            p = np;
            s0 = t0i; s1 = t1i; s2 = t2i; s3 = t3i;
            have = nhave;
        }
        for (; p < end; p++) {                   // remainder 0..3 edges
            int s = g_csrc[p];
            float e = g_as[s] + adn;
            e = (e >= 0.f) ? e : 0.2f * e;
            float t = __expf(e);
            lsum += t;
            float4 hv = *(const float4*)&h[s * OUT + c4 * 4];
            a0 += t * hv.x; a1 += t * hv.y; a2 += t * hv.z; a3 += t * hv.w;
        }
        a0 += b0; a1 += b1_; a2 += b2; a3 += b3;

        float inv = __fdividef(1.f, lsum + 1e-16f);
        float v0 = a0 * inv + bias.x; v0 = (v0 > 0.f) ? v0 : 0.f;
        float v1 = a1 * inv + bias.y; v1 = (v1 > 0.f) ? v1 : 0.f;
        float v2 = a2 * inv + bias.z; v2 = (v2 > 0.f) ? v2 : 0.f;
        float v3 = a3 * inv + bias.w; v3 = (v3 > 0.f) ? v3 : 0.f;
        *(float4*)&yout[node * OUT + c4 * 4] = make_float4(v0, v1, v2, v3);
        st_s[0] += v0; st_q[0] += v0 * v0;
        st_s[1] += v1; st_q[1] += v1 * v1;
        st_s[2] += v2; st_q[2] += v2 * v2;
        st_s[3] += v3; st_q[3] += v3 * v3;
    }

    __shared__ float sS[256 * 4];
    __shared__ float sQ[256 * 4];
#pragma unroll
    for (int c = 0; c < 4; c++) {
        sS[threadIdx.x * 4 + c] = st_s[c];
        sQ[threadIdx.x * 4 + c] = st_q[c];
    }
    __syncthreads();
    if (nl == 0) {
#pragma unroll 4
        for (int t = 1; t < NPB; t++) {
#pragma unroll
            for (int c = 0; c < 4; c++) {
                st_s[c] += sS[(t * TPN + c4) * 4 + c];
                st_q[c] += sQ[(t * TPN + c4) * 4 + c];
            }
        }
#pragma unroll
        for (int c = 0; c < 4; c++) {
            atomicAdd(&g_colsum[c4 * 4 + c], st_s[c]);
            atomicAdd(&g_colsq[c4 * 4 + c], st_q[c]);
        }
    }

    // last-block BN finalize
    __shared__ int isLast;
    __syncthreads();
    if (threadIdx.x == 0) {
        __threadfence();
        int c = atomicAdd(&g_done, 1);
        isLast = (c == (int)gridDim.x - 1) ? 1 : 0;
    }
    __syncthreads();
    if (isLast) {
        int o = threadIdx.x;
        if (o < HID) {
            float mu = g_colsum[o] * invn;
            float var = g_colsq[o] * invn - mu * mu;
            float sc = gamma[o] * rsqrtf(var + 1e-5f);
            g_scale[o] = sc;
            g_shift[o] = beta[o] - mu * sc;
            g_colsum[o] = 0.f;
            g_colsq[o] = 0.f;
        }
        if (threadIdx.x == 0) g_done = 0;
    }
}

// ---------------- layer-4 aggregation (raw aggregate u, pipelined x4) ----------------
__global__ void agg_f32_kernel(const float* __restrict__ h, float* __restrict__ yout, int n) {
    const int OUT = HID;
    const int TPN = OUT / 4;
    const int NPB = 256 / TPN;
    int c4 = threadIdx.x % TPN;
    int nl = threadIdx.x / TPN;

    for (int node = blockIdx.x * NPB + nl; node < n; node += gridDim.x * NPB) {
        int p   = g_rowptr[node];
        int end = g_rowptr[node + 1];
        float adn = g_ad[node];

        float a0 = 0.f, a1 = 0.f, a2 = 0.f, a3 = 0.f;
        float b0 = 0.f, b1_ = 0.f, b2 = 0.f, b3 = 0.f;
        float lsum = 0.f;

        int s0, s1, s2, s3;
        bool have = (p + 4 <= end);
        if (have) {
            s0 = g_csrc[p]; s1 = g_csrc[p + 1];
            s2 = g_csrc[p + 2]; s3 = g_csrc[p + 3];
        }
        while (have) {
            int np = p + 4;
            bool nhave = (np + 4 <= end);
            int t0i = g_csrc[np];
            int t1i = g_csrc[np + 1];
            int t2i = g_csrc[np + 2];
            int t3i = g_csrc[np + 3];

            float e0 = g_as[s0];
            float e1 = g_as[s1];
            float e2 = g_as[s2];
            float e3 = g_as[s3];
            float4 h0 = *(const float4*)&h[s0 * OUT + c4 * 4];
            float4 h1 = *(const float4*)&h[s1 * OUT + c4 * 4];
            float4 h2 = *(const float4*)&h[s2 * OUT + c4 * 4];
            float4 h3 = *(const float4*)&h[s3 * OUT + c4 * 4];
            e0 += adn; e0 = (e0 >= 0.f) ? e0 : 0.2f * e0;
            e1 += adn; e1 = (e1 >= 0.f) ? e1 : 0.2f * e1;
            e2 += adn; e2 = (e2 >= 0.f) ? e2 : 0.2f * e2;
            e3 += adn; e3 = (e3 >= 0.f) ? e3 : 0.2f * e3;
            float t0 = __expf(e0);
            float t1 = __expf(e1);
            float t2 = __expf(e2);
            float t3 = __expf(e3);
            lsum += (t0 + t1) + (t2 + t3);
            a0 += t0 * h0.x; a1 += t0 * h0.y; a2 += t0 * h0.z; a3 += t0 * h0.w;
            b0 += t1 * h1.x; b1_ += t1 * h1.y; b2 += t1 * h1.z; b3 += t1 * h1.w;
            a0 += t2 * h2.x; a1 += t2 * h2.y; a2 += t2 * h2.z; a3 += t2 * h2.w;
            b0 += t3 * h3.x; b1_ += t3 * h3.y; b2 += t3 * h3.z; b3 += t3 * h3.w;

            p = np;
            s0 = t0i; s1 = t1i; s2 = t2i; s3 = t3i;
            have = nhave;
        }
        for (; p < end; p++) {
            int s = g_csrc[p];
            float e = g_as[s] + adn;
            e = (e >= 0.f) ? e : 0.2f * e;
            float t = __expf(e);
            lsum += t;
            float4 hv = *(const float4*)&h[s * OUT + c4 * 4];
            a0 += t * hv.x; a1 += t * hv.y; a2 += t * hv.z; a3 += t * hv.w;
        }
        a0 += b0; a1 += b1_; a2 += b2; a3 += b3;

        float inv = __fdividef(1.f, lsum + 1e-16f);
        *(float4*)&yout[node * OUT + c4 * 4] =
            make_float4(a0 * inv, a1 * inv, a2 * inv, a3 * inv);
    }
}

extern "C" void kernel_launch(void* const* d_in, const int* in_sizes, int n_in,
                              void* d_out, int out_size) {
    const float* x   = (const float*)d_in[0];
    const void*  ei  = d_in[1];
    const float* W1  = (const float*)d_in[2];
    const float* a1s = (const float*)d_in[3];
    const float* a1d = (const float*)d_in[4];
    const float* b1  = (const float*)d_in[5];
    const float* g1  = (const float*)d_in[6];
    const float* be1 = (const float*)d_in[7];
    const float* W2  = (const float*)d_in[8];
    const float* a2s = (const float*)d_in[9];
    const float* a2d = (const float*)d_in[10];
    const float* b2  = (const float*)d_in[11];
    const float* g2  = (const float*)d_in[12];
    const float* be2 = (const float*)d_in[13];
    const float* W3  = (const float*)d_in[14];
    const float* a3s = (const float*)d_in[15];
    const float* a3d = (const float*)d_in[16];
    const float* b3  = (const float*)d_in[17];
    const float* g3  = (const float*)d_in[18];
    const float* be3 = (const float*)d_in[19];
    const float* W4  = (const float*)d_in[20];
    const float* a4s = (const float*)d_in[21];
    const float* a4d = (const float*)d_in[22];
    const float* b4  = (const float*)d_in[23];

    int n  = in_sizes[0] / FEAT;     // 50000
    int E  = in_sizes[1] / 2;        // 800000
    int ET = E + n;
    int nb = (n + SCH - 1) / SCH;

    float *hbuf, *ybuf, *ubuf;
    cudaGetSymbolAddress((void**)&hbuf, g_h);
    cudaGetSymbolAddress((void**)&ybuf, g_y);
    cudaGetSymbolAddress((void**)&ubuf, g_u);

    float invn = 1.0f / (float)n;
    const int AGG_BLOCKS = 1184;

    // Fork a side stream so the CSR build overlaps the layer-1 GEMM.
    cudaStream_t s1;
    cudaStreamCreateWithFlags(&s1, cudaStreamNonBlocking);
    cudaEvent_t e0, e1;
    cudaEventCreateWithFlags(&e0, cudaEventDisableTiming);
    cudaEventCreateWithFlags(&e1, cudaEventDisableTiming);

    // ---- common prologue (dtype probe + w4) on the origin stream ----
    start_kernel<<<1, HID>>>(ei, W4, a4s, a4d);
    cudaEventRecord(e0, 0);

    // ---- branch B (side stream): CSR build ----
    cudaStreamWaitEvent(s1, e0, 0);
    convert_kernel<<<(ET + 255) / 256, 256, 0, s1>>>(ei, E, ET);
    scan1_kernel<<<nb, SCH, 0, s1>>>(n);
    scan2_kernel<<<1, 256, 0, s1>>>(nb, n);
    scan3_kernel<<<nb, SCH, 0, s1>>>(n);
    scatter_kernel<<<(ET + 255) / 256, 256, 0, s1>>>(ei, E, ET);
    cudaEventRecord(e1, s1);

    // ---- branch A (origin stream): layer-1 GEMM (independent of CSR) ----
    gemm_kernel<FEAT, HID><<<(n + 127) / 128, 256>>>(x, W1, 0, a1s, a1d, hbuf, n);

    // ---- join: aggregation needs both branches ----
    cudaStreamWaitEvent(0, e1, 0);
    agg_bn_kernel<<<AGG_BLOCKS, 256>>>(hbuf, b1, g1, be1, invn, ybuf, n);

    // ---- Layer 2: 64 -> 64 ----
    gemm_kernel<HID, HID><<<(n + 127) / 128, 256>>>(ybuf, W2, 1, a2s, a2d, hbuf, n);
    agg_bn_kernel<<<AGG_BLOCKS, 256>>>(hbuf, b2, g2, be2, invn, ybuf, n);

    // ---- Layer 3: 64 -> 64 ----
    gemm_kernel<HID, HID><<<(n + 127) / 128, 256>>>(ybuf, W3, 1, a3s, a3d, hbuf, n);
    agg_bn_kernel<<<AGG_BLOCKS, 256>>>(hbuf, b3, g3, be3, invn, ybuf, n);

    // ---- Layer 4 (commuted): alpha, aggregate y, GEMM+final ----
    alpha4_kernel<<<(n * 32 + 255) / 256, 256>>>(ybuf, n);
    agg_f32_kernel<<<AGG_BLOCKS, 256>>>(ybuf, ubuf, n);
    gemm_final_kernel<<<(n + 63) / 64, 256>>>(ubuf, W4, b4, x, (float*)d_out, n, out_size);

    cudaEventDestroy(e0);
    cudaEventDestroy(e1);
    cudaStreamDestroy(s1);
}